// round 3
// baseline (speedup 1.0000x reference)
#include <cuda_runtime.h>
#include <math.h>

#define Bv 4
#define Tv 4096
#define Cv 512
#define Rv (Bv*Tv)            // 16384 rows
#define Fv (4*Cv)             // 2048
#define GUARDE (2048*Cv)      // guard rows (zero-init) for shifted scan operand

// ---------------- static device scratch (zero-initialized) ----------------
__device__ float g_h[Rv*Cv];
__device__ float g_qA[GUARDE + Rv*Cv];
__device__ float g_qB[GUARDE + Rv*Cv];
__device__ float g_v[Rv*Cv];
__device__ float g_z[Rv*Cv];
__device__ float g_fc[Rv*Fv];
__device__ float g_X [2*Cv*Cv];
__device__ float g_X2[2*Cv*Cv];
__device__ float g_Y [2*Cv*Cv];
__device__ float g_Mm[2*Cv*Cv];
__device__ float g_part[2*Cv];
__device__ float g_rn[2];

// ---------------- GEMM ----------------
// C[M,N] = f(alpha * A?B + beta*add + diag*I)
// AM=0: A is K-major, A[m*K+k]      AM=1: A is M-major, A[k*M+m] (i.e. uses A^T)
// BMO=0: B is K-major, B[n*K+k] (C=A.B^T)   BMO=1: B is N-major, B[k*N+n] (C=A.B)
struct Epi {
    float alpha;
    const float* add;
    float beta;
    float diag;
    int gelu;
    long strideAdd;
};

template<int BM,int BN,int BK,int TM,int TN,int AM,int BMO>
__global__ __launch_bounds__((BM/TM)*(BN/TN))
void gemm_k(const float* __restrict__ A, const float* __restrict__ Bp,
            float* __restrict__ C, int M, int N, int K,
            long sA, long sB, long sC, Epi e)
{
    constexpr int NT = (BM/TM)*(BN/TN);
    __shared__ __align__(16) float Sa[BK][BM+4];
    __shared__ __align__(16) float Sb[BK][BN+4];
    const int tid = threadIdx.x;
    const int bz  = blockIdx.z;
    A  += (long)bz * sA;
    Bp += (long)bz * sB;
    C  += (long)bz * sC;
    const float* Ad = e.add ? (e.add + (long)bz * e.strideAdd) : (const float*)0;
    const int m0 = blockIdx.y * BM;
    const int n0 = blockIdx.x * BN;
    const int tx = tid % (BN/TN);
    const int ty = tid / (BN/TN);

    float acc[TM][TN];
#pragma unroll
    for (int i=0;i<TM;i++)
#pragma unroll
        for (int j=0;j<TN;j++) acc[i][j]=0.f;

    for (int k0=0; k0<K; k0+=BK) {
        // load A tile -> Sa[k][m]
        {
            constexpr int NV = BM*BK/4;
#pragma unroll
            for (int t=0; t<NV/NT; t++) {
                int vv = tid + t*NT;
                if (AM==0) {
                    int m  = vv/(BK/4);
                    int kk = (vv%(BK/4))*4;
                    float4 f = *(const float4*)(A + (long)(m0+m)*K + (k0+kk));
                    Sa[kk+0][m]=f.x; Sa[kk+1][m]=f.y; Sa[kk+2][m]=f.z; Sa[kk+3][m]=f.w;
                } else {
                    int kk = vv/(BM/4);
                    int mm = (vv%(BM/4))*4;
                    *(float4*)&Sa[kk][mm] = *(const float4*)(A + (long)(k0+kk)*M + (m0+mm));
                }
            }
        }
        // load B tile -> Sb[k][n]
        {
            constexpr int NV = BN*BK/4;
#pragma unroll
            for (int t=0; t<NV/NT; t++) {
                int vv = tid + t*NT;
                if (BMO==0) {
                    int n  = vv/(BK/4);
                    int kk = (vv%(BK/4))*4;
                    float4 f = *(const float4*)(Bp + (long)(n0+n)*K + (k0+kk));
                    Sb[kk+0][n]=f.x; Sb[kk+1][n]=f.y; Sb[kk+2][n]=f.z; Sb[kk+3][n]=f.w;
                } else {
                    int kk = vv/(BN/4);
                    int nn = (vv%(BN/4))*4;
                    *(float4*)&Sb[kk][nn] = *(const float4*)(Bp + (long)(k0+kk)*N + (n0+nn));
                }
            }
        }
        __syncthreads();
#pragma unroll
        for (int k=0;k<BK;k++) {
            float ra[TM], rb[TN];
#pragma unroll
            for (int i=0;i<TM;i+=4) {
                float4 t4 = *(const float4*)&Sa[k][ty*TM+i];
                ra[i]=t4.x; ra[i+1]=t4.y; ra[i+2]=t4.z; ra[i+3]=t4.w;
            }
#pragma unroll
            for (int j=0;j<TN;j+=4) {
                float4 t4 = *(const float4*)&Sb[k][tx*TN+j];
                rb[j]=t4.x; rb[j+1]=t4.y; rb[j+2]=t4.z; rb[j+3]=t4.w;
            }
#pragma unroll
            for (int i=0;i<TM;i++)
#pragma unroll
                for (int j=0;j<TN;j++)
                    acc[i][j] = fmaf(ra[i], rb[j], acc[i][j]);
        }
        __syncthreads();
    }

#pragma unroll
    for (int i=0;i<TM;i++) {
        int gm = m0 + ty*TM + i;
#pragma unroll
        for (int j=0;j<TN;j++) {
            int gn = n0 + tx*TN + j;
            float v = e.alpha * acc[i][j];
            if (Ad) v += e.beta * Ad[(long)gm*N + gn];
            if (e.diag != 0.f && gm==gn) v += e.diag;
            if (e.gelu) v = 0.5f*v*(1.f + erff(v*0.70710678118654752f));
            C[(long)gm*N + gn] = v;
        }
    }
}

// ---------------- elementwise / reduction kernels ----------------
__global__ void ln_kernel(const float* __restrict__ x, const float* __restrict__ w,
                          float* __restrict__ o)
{
    const int r = blockIdx.x, tid = threadIdx.x; // 128 threads, C=512 => 1 float4/thr
    float4 f = ((const float4*)(x + (long)r*Cv))[tid];
    float s = f.x+f.y+f.z+f.w;
    float q = f.x*f.x+f.y*f.y+f.z*f.z+f.w*f.w;
    __shared__ float shs[4], shq[4];
#pragma unroll
    for (int off=16; off>0; off>>=1) {
        s += __shfl_down_sync(0xffffffffu, s, off);
        q += __shfl_down_sync(0xffffffffu, q, off);
    }
    if ((tid&31)==0) { shs[tid>>5]=s; shq[tid>>5]=q; }
    __syncthreads();
    float S = shs[0]+shs[1]+shs[2]+shs[3];
    float Q = shq[0]+shq[1]+shq[2]+shq[3];
    float mean = S*(1.f/Cv);
    float var  = Q*(1.f/Cv) - mean*mean;
    float inv  = rsqrtf(var + 1e-5f);
    float4 wf = ((const float4*)w)[tid];
    float4 r4;
    r4.x = (f.x-mean)*inv*wf.x;
    r4.y = (f.y-mean)*inv*wf.y;
    r4.z = (f.z-mean)*inv*wf.z;
    r4.w = (f.w-mean)*inv*wf.w;
    ((float4*)(o + (long)r*Cv))[tid] = r4;
}

__global__ void pscan_combine(const float* __restrict__ z, const float* __restrict__ qold,
                              float* __restrict__ qnew, int d)
{
    const int r = blockIdx.x, tid = threadIdx.x;
    const int t = r & (Tv-1);
    if (t < d) {
        ((float4*)(qnew + (long)r*Cv))[tid] = ((const float4*)(qold + (long)r*Cv))[tid];
        return;
    }
    float4 f = ((const float4*)(z + (long)r*Cv))[tid];
    float q = f.x*f.x+f.y*f.y+f.z*f.z+f.w*f.w;
    __shared__ float shq[4];
#pragma unroll
    for (int off=16; off>0; off>>=1) q += __shfl_down_sync(0xffffffffu, q, off);
    if ((tid&31)==0) shq[tid>>5]=q;
    __syncthreads();
    float Q = shq[0]+shq[1]+shq[2]+shq[3];
    float sc = rsqrtf(Q*(1.f/Cv) + 1e-6f);
    float4 r4; r4.x=f.x*sc; r4.y=f.y*sc; r4.z=f.z*sc; r4.w=f.w*sc;
    ((float4*)(qnew + (long)r*Cv))[tid] = r4;
}

__global__ void mul_k(const float* __restrict__ a, const float* __restrict__ b,
                      float* __restrict__ o)
{
    long i = (long)blockIdx.x*blockDim.x + threadIdx.x;  // R*C/4 float4s exactly
    float4 fa = ((const float4*)a)[i];
    float4 fb = ((const float4*)b)[i];
    float4 r4; r4.x=fa.x*fb.x; r4.y=fa.y*fb.y; r4.z=fa.z*fb.z; r4.w=fa.w*fb.w;
    ((float4*)o)[i] = r4;
}

__global__ void frob1(const float* __restrict__ W1, const float* __restrict__ W2,
                      float* __restrict__ part)
{
    const int row = blockIdx.x, mat = blockIdx.y, tid = threadIdx.x;
    const float* W = mat ? W2 : W1;
    float4 f = ((const float4*)(W + (long)row*Cv))[tid];
    float q = f.x*f.x+f.y*f.y+f.z*f.z+f.w*f.w;
    __shared__ float shq[4];
#pragma unroll
    for (int off=16; off>0; off>>=1) q += __shfl_down_sync(0xffffffffu, q, off);
    if ((tid&31)==0) shq[tid>>5]=q;
    __syncthreads();
    if (tid==0) part[mat*Cv + row] = shq[0]+shq[1]+shq[2]+shq[3];
}

__global__ void frob2(const float* __restrict__ part, float* __restrict__ rn)
{
    const int mat = blockIdx.x, tid = threadIdx.x;  // 256 threads
    __shared__ float sh[256];
    sh[tid] = part[mat*Cv + tid] + part[mat*Cv + tid + 256];
    __syncthreads();
    for (int off=128; off>0; off>>=1) {
        if (tid<off) sh[tid] += sh[tid+off];
        __syncthreads();
    }
    if (tid==0) rn[mat] = rsqrtf(sh[0]);
}

__global__ void polar_scale(const float* __restrict__ W1, const float* __restrict__ W2,
                            const float* __restrict__ rn, float* __restrict__ X)
{
    int idx = blockIdx.x*blockDim.x + threadIdx.x;   // 2*512*512 total
    int mat = idx >> 18;
    float w = mat ? W2[idx - Cv*Cv] : W1[idx];
    X[idx] = w * rn[mat];
}

// ---------------- host ----------------
static inline Epi epi_none() { Epi e; e.alpha=1.f; e.add=0; e.beta=0.f; e.diag=0.f; e.gelu=0; e.strideAdd=0; return e; }

extern "C" void kernel_launch(void* const* d_in, const int* in_sizes, int n_in,
                              void* d_out, int out_size)
{
    const float* x   = (const float*)d_in[0];
    const float* ln1 = (const float*)d_in[1];
    const float* Wq  = (const float*)d_in[2];
    const float* Wv  = (const float*)d_in[3];
    const float* Wo  = (const float*)d_in[4];
    // d_in[5] = identity : mathematically unused (its rows are discarded by the where-mask)
    const float* Wp1 = (const float*)d_in[6];
    const float* Wp2 = (const float*)d_in[7];
    const float* ln2 = (const float*)d_in[8];
    const float* Wfc = (const float*)d_in[9];
    const float* Wpr = (const float*)d_in[10];
    float* out = (float*)d_out;

    float *h,*qA,*qB,*v,*z,*fc,*X,*X2,*Y,*Mm,*part,*rn;
    cudaGetSymbolAddress((void**)&h,  g_h);
    cudaGetSymbolAddress((void**)&qA, g_qA);
    cudaGetSymbolAddress((void**)&qB, g_qB);
    cudaGetSymbolAddress((void**)&v,  g_v);
    cudaGetSymbolAddress((void**)&z,  g_z);
    cudaGetSymbolAddress((void**)&fc, g_fc);
    cudaGetSymbolAddress((void**)&X,  g_X);
    cudaGetSymbolAddress((void**)&X2, g_X2);
    cudaGetSymbolAddress((void**)&Y,  g_Y);
    cudaGetSymbolAddress((void**)&Mm, g_Mm);
    cudaGetSymbolAddress((void**)&part, g_part);
    cudaGetSymbolAddress((void**)&rn,   g_rn);

    float* qAb = qA + GUARDE;
    float* qBb = qB + GUARDE;
    const long S = (long)Cv*Cv;
    Epi e0 = epi_none();

    // ---- polar factors of Wp1, Wp2 via Muon-quintic + Newton-Schulz ----
    frob1<<<dim3(Cv,2),128>>>(Wp1, Wp2, part);
    frob2<<<2,256>>>(part, rn);
    polar_scale<<<(2*Cv*Cv)/256,256>>>(Wp1, Wp2, rn, X);

    float* Xc = X;  float* Xn = X2;
    for (int it=0; it<10; ++it) {   // quintic: X <- X(aI + bY + cY^2), Y = X^T X
        gemm_k<64,64,16,4,4,1,1><<<dim3(8,8,2),256>>>(Xc, Xc, Y, Cv,Cv,Cv, S,S,S, e0);
        Epi em = e0; em.alpha=2.0315f; em.add=Y; em.beta=-4.7750f; em.diag=3.4445f; em.strideAdd=S;
        gemm_k<64,64,16,4,4,0,1><<<dim3(8,8,2),256>>>(Y, Y, Mm, Cv,Cv,Cv, S,S,S, em);
        gemm_k<64,64,16,4,4,0,1><<<dim3(8,8,2),256>>>(Xc, Mm, Xn, Cv,Cv,Cv, S,S,S, e0);
        float* tmp=Xc; Xc=Xn; Xn=tmp;
    }
    for (int it=0; it<8; ++it) {    // Newton-Schulz: X <- 1.5X - 0.5 X (X^T X)
        gemm_k<64,64,16,4,4,1,1><<<dim3(8,8,2),256>>>(Xc, Xc, Y, Cv,Cv,Cv, S,S,S, e0);
        Epi en = e0; en.alpha=-0.5f; en.add=Xc; en.beta=1.5f; en.strideAdd=S;
        gemm_k<64,64,16,4,4,0,1><<<dim3(8,8,2),256>>>(Xc, Y, Xn, Cv,Cv,Cv, S,S,S, en);
        float* tmp=Xc; Xc=Xn; Xn=tmp;
    }
    const float* P1 = Xc;
    const float* P2 = Xc + S;

    // ---- SSM branch ----
    ln_kernel<<<Rv,128>>>(x, ln1, h);
    gemm_k<128,128,16,8,8,0,0><<<dim3(Cv/128, Rv/128, 1),256>>>(h, Wq, qAb, Rv,Cv,Cv, 0,0,0, e0);
    gemm_k<128,128,16,8,8,0,0><<<dim3(Cv/128, Rv/128, 1),256>>>(h, Wv, v,   Rv,Cv,Cv, 0,0,0, e0);

    float* qc = qAb;  float* qn = qBb;
    for (int d=1; d<Tv; d<<=1) {
        // z = qshift @ P1^T  (guard rows are zeros; invalid rows discarded below)
        gemm_k<128,128,16,8,8,0,0><<<dim3(Cv/128, Rv/128, 1),256>>>(qc - (long)d*Cv, P1, z, Rv,Cv,Cv, 0,0,0, e0);
        // z += q @ P2^T
        Epi ea = e0; ea.add=z; ea.beta=1.f;
        gemm_k<128,128,16,8,8,0,0><<<dim3(Cv/128, Rv/128, 1),256>>>(qc, P2, z, Rv,Cv,Cv, 0,0,0, ea);
        pscan_combine<<<Rv,128>>>(z, qc, qn, d);
        float* tmp=qc; qc=qn; qn=tmp;
    }

    // x1 = x + (q*v) @ Wo^T   (into d_out)
    mul_k<<<(Rv*Cv/4)/256,256>>>(qc, v, h);
    Epi er = e0; er.add=x; er.beta=1.f;
    gemm_k<128,128,16,8,8,0,0><<<dim3(Cv/128, Rv/128, 1),256>>>(h, Wo, out, Rv,Cv,Cv, 0,0,0, er);

    // ---- MLP branch ----
    ln_kernel<<<Rv,128>>>(out, ln2, h);
    Epi eg = e0; eg.gelu=1;
    gemm_k<128,128,16,8,8,0,0><<<dim3(Fv/128, Rv/128, 1),256>>>(h, Wfc, fc, Rv,Fv,Cv, 0,0,0, eg);
    Epi er2 = e0; er2.add=out; er2.beta=1.f;
    gemm_k<128,128,16,8,8,0,0><<<dim3(Cv/128, Rv/128, 1),256>>>(fc, Wpr, out, Rv,Cv,Fv, 0,0,0, er2);
}

// round 5
// speedup vs baseline: 1.9364x; 1.9364x over previous
#include <cuda_runtime.h>
#include <cuda_bf16.h>
#include <math.h>
#include <stdint.h>

#define Bv 4
#define Tv 4096
#define Cv 512
#define Rv (Bv*Tv)            // 16384 rows
#define Fv (4*Cv)             // 2048
#define GUARDE (2048*Cv)      // guard rows (zero-init) for shifted scan operand

// ---------------- static device scratch (zero-initialized) ----------------
__device__ float g_qAF[Rv*Cv];
__device__ float g_qBF[Rv*Cv];
__device__ __nv_bfloat16 g_qAH[GUARDE + Rv*Cv];
__device__ __nv_bfloat16 g_qAL[GUARDE + Rv*Cv];
__device__ __nv_bfloat16 g_qBH[GUARDE + Rv*Cv];
__device__ __nv_bfloat16 g_qBL[GUARDE + Rv*Cv];
__device__ float g_vF[Rv*Cv];
__device__ float g_z[Rv*Cv];
__device__ __nv_bfloat16 g_hH[Rv*Cv];
__device__ __nv_bfloat16 g_hL[Rv*Cv];
__device__ __nv_bfloat16 g_fcH[Rv*Fv];
__device__ __nv_bfloat16 g_fcL[Rv*Fv];
// weight splits
__device__ __nv_bfloat16 g_WqH[Cv*Cv], g_WqL[Cv*Cv];
__device__ __nv_bfloat16 g_WvH[Cv*Cv], g_WvL[Cv*Cv];
__device__ __nv_bfloat16 g_WoH[Cv*Cv], g_WoL[Cv*Cv];
__device__ __nv_bfloat16 g_WfcH[Fv*Cv], g_WfcL[Fv*Cv];
__device__ __nv_bfloat16 g_WprH[Cv*Fv], g_WprL[Cv*Fv];
__device__ __nv_bfloat16 g_PH[2*Cv*Cv], g_PL[2*Cv*Cv];
// polar scratch
__device__ float g_X [2*Cv*Cv];
__device__ float g_X2[2*Cv*Cv];
__device__ float g_Y [2*Cv*Cv];
__device__ float g_Mm[2*Cv*Cv];
__device__ float g_part[2*Cv];
__device__ float g_rn[2];

// ================= helpers =================
__device__ __forceinline__ uint32_t smem_to_u32(const void* p) {
    uint32_t a;
    asm("{ .reg .u64 t; cvta.to.shared.u64 t, %1; cvt.u32.u64 %0, t; }" : "=r"(a) : "l"(p));
    return a;
}
__device__ __forceinline__ void split2(float x, __nv_bfloat16& h, __nv_bfloat16& l) {
    h = __float2bfloat16(x);
    l = __float2bfloat16(x - __bfloat162float(h));
}
__device__ __forceinline__ uint32_t pk2(__nv_bfloat16 a, __nv_bfloat16 b) {
    __nv_bfloat162 t; t.x = a; t.y = b;
    return *(uint32_t*)&t;
}
__device__ __forceinline__ void ldsm4(uint32_t (&r)[4], uint32_t addr) {
    asm volatile("ldmatrix.sync.aligned.m8n8.x4.shared.b16 {%0,%1,%2,%3}, [%4];"
        : "=r"(r[0]), "=r"(r[1]), "=r"(r[2]), "=r"(r[3]) : "r"(addr));
}
__device__ __forceinline__ void mma16816(float (&d)[4], const uint32_t (&a)[4],
                                         uint32_t b0, uint32_t b1) {
    asm volatile("mma.sync.aligned.m16n8k16.row.col.f32.bf16.bf16.f32 "
        "{%0,%1,%2,%3}, {%4,%5,%6,%7}, {%8,%9}, {%0,%1,%2,%3};"
        : "+f"(d[0]), "+f"(d[1]), "+f"(d[2]), "+f"(d[3])
        : "r"(a[0]), "r"(a[1]), "r"(a[2]), "r"(a[3]), "r"(b0), "r"(b1));
}
__device__ __forceinline__ void cp_async16(uint32_t so, const void* gp) {
    asm volatile("cp.async.cg.shared.global [%0], [%1], 16;" :: "r"(so), "l"(gp) : "memory");
}
#define CP_COMMIT() asm volatile("cp.async.commit_group;" ::: "memory")
#define CP_WAIT0()  asm volatile("cp.async.wait_group 0;" ::: "memory")
#define CP_WAIT1()  asm volatile("cp.async.wait_group 1;" ::: "memory")

// ================= mma.sync split-bf16 GEMM: C = A@B^T (+epi) =================
// A: [M,K] bf16 hi/lo, B: [N,K] bf16 hi/lo. 3 passes: Ah*Bh + Ah*Bl + Al*Bh.
// CTA tile 128x128, 8 warps of 64x32, K-chunk 64, cp.async double buffer.
struct TEpi {
    const float* add;          // fp32 residual [M,N] or null
    int gelu;
    float* outF;               // fp32 out or null
    __nv_bfloat16* outH;       // bf16 hi out or null
    __nv_bfloat16* outL;       // bf16 lo out or null
};

#define MM_SMEM (2*65536)      // 2 buffers x 4 tiles x 16KB

__global__ __launch_bounds__(256, 1)
void mma_gemm(const __nv_bfloat16* __restrict__ Ah, const __nv_bfloat16* __restrict__ Al,
              const __nv_bfloat16* __restrict__ Bh, const __nv_bfloat16* __restrict__ Bl,
              int M, int N, int K, TEpi e)
{
    extern __shared__ char smem[];
    const uint32_t sb = smem_to_u32(smem);
    const int tid  = threadIdx.x;
    const int lane = tid & 31;
    const int wm   = (tid >> 5) & 1;   // warp row 0..1 (64 rows each)
    const int wn   = (tid >> 5) >> 1;  // warp col 0..3 (32 cols each)
    const int m0 = blockIdx.y * 128;
    const int n0 = blockIdx.x * 128;
    const int NC = K / 64;

    // per-lane ldmatrix address components (swizzled rows of 128B)
    int aRow[4], aXm[4];
#pragma unroll
    for (int mf = 0; mf < 4; mf++) {
        int r = wm * 64 + mf * 16 + (lane & 15);
        aRow[mf] = r * 128;
        aXm[mf]  = (r & 7) << 4;
    }
    const int aKb = (lane >> 4) * 16;      // k-byte offset within frag
    int bRow[2], bXm[2];
#pragma unroll
    for (int nb = 0; nb < 2; nb++) {
        int r = wn * 32 + nb * 16 + ((lane >> 4) << 3) + (lane & 7);
        bRow[nb] = r * 128;
        bXm[nb]  = (r & 7) << 4;
    }
    const int bKb = ((lane >> 3) & 1) * 16;

    float acc[4][4][4];
#pragma unroll
    for (int i = 0; i < 4; i++)
#pragma unroll
        for (int j = 0; j < 4; j++)
#pragma unroll
            for (int t = 0; t < 4; t++) acc[i][j][t] = 0.f;

    auto loadChunk = [&](int c, int b) {
        const long cofs = (long)c * 64;
#pragma unroll
        for (int t = 0; t < 16; t++) {
            int u = tid + t * 256;
            int tile = u >> 10;
            int w = u & 1023;
            int row = w >> 3;
            int seg = w & 7;
            const __nv_bfloat16* gp;
            if      (tile == 0) gp = Ah + (long)(m0 + row) * K + cofs;
            else if (tile == 1) gp = Al + (long)(m0 + row) * K + cofs;
            else if (tile == 2) gp = Bh + (long)(n0 + row) * K + cofs;
            else                gp = Bl + (long)(n0 + row) * K + cofs;
            gp += seg * 8;
            uint32_t so = sb + b * 65536 + tile * 16384 + row * 128
                        + ((seg * 16) ^ ((row & 7) << 4));
            cp_async16(so, gp);
        }
        CP_COMMIT();
    };

    loadChunk(0, 0);

    for (int c = 0; c < NC; c++) {
        if (c + 1 < NC) {
            loadChunk(c + 1, (c + 1) & 1);
            CP_WAIT1();
        } else {
            CP_WAIT0();
        }
        __syncthreads();

        const uint32_t bufBase = sb + (c & 1) * 65536;
#pragma unroll
        for (int pass = 0; pass < 3; pass++) {
            const uint32_t aB = bufBase + (pass == 2 ? 16384 : 0);
            const uint32_t bB = bufBase + 32768 + (pass == 1 ? 16384 : 0);
#pragma unroll
            for (int ks = 0; ks < 4; ks++) {
                uint32_t afr[4][4];
#pragma unroll
                for (int mf = 0; mf < 4; mf++)
                    ldsm4(afr[mf], aB + aRow[mf] + ((ks * 32 + aKb) ^ aXm[mf]));
                uint32_t bfr[4][4];  // [nb][4]; frag nf=2*nb uses r0,r1; nf=2*nb+1 uses r2,r3
#pragma unroll
                for (int nb = 0; nb < 2; nb++)
                    ldsm4(bfr[nb], bB + bRow[nb] + ((ks * 32 + bKb) ^ bXm[nb]));
#pragma unroll
                for (int mf = 0; mf < 4; mf++) {
#pragma unroll
                    for (int nf = 0; nf < 4; nf++)
                        mma16816(acc[mf][nf], afr[mf], bfr[nf >> 1][(nf & 1) * 2],
                                 bfr[nf >> 1][(nf & 1) * 2 + 1]);
                }
            }
        }
        __syncthreads();
    }

    // ---- epilogue: direct register -> gmem ----
    const int rl = lane >> 2;
    const int cl = (lane & 3) * 2;
#pragma unroll
    for (int mf = 0; mf < 4; mf++) {
#pragma unroll
        for (int nf = 0; nf < 4; nf++) {
            int c0 = n0 + wn * 32 + nf * 8 + cl;
#pragma unroll
            for (int half = 0; half < 2; half++) {
                int row = m0 + wm * 64 + mf * 16 + rl + half * 8;
                long ofs = (long)row * N + c0;
                float f0 = acc[mf][nf][half * 2];
                float f1 = acc[mf][nf][half * 2 + 1];
                if (e.add) {
                    float2 ra = *(const float2*)(e.add + ofs);
                    f0 += ra.x; f1 += ra.y;
                }
                if (e.gelu) {
                    f0 = 0.5f * f0 * (1.f + erff(f0 * 0.70710678118654752f));
                    f1 = 0.5f * f1 * (1.f + erff(f1 * 0.70710678118654752f));
                }
                if (e.outF)
                    *(float2*)(e.outF + ofs) = make_float2(f0, f1);
                if (e.outH) {
                    __nv_bfloat16 h0, h1, l0, l1;
                    split2(f0, h0, l0);
                    split2(f1, h1, l1);
                    *(uint32_t*)(e.outH + ofs) = pk2(h0, h1);
                    *(uint32_t*)(e.outL + ofs) = pk2(l0, l1);
                }
            }
        }
    }
}

// ================= fp32 SIMT GEMM (polar iterations only) =================
struct Epi {
    float alpha;
    const float* add;
    float beta;
    float diag;
    long strideAdd;
};

template<int BM,int BN,int BK,int TM,int TN,int AM,int BMO>
__global__ __launch_bounds__((BM/TM)*(BN/TN))
void gemm_k(const float* __restrict__ A, const float* __restrict__ Bp,
            float* __restrict__ C, int M, int N, int K,
            long sA, long sB, long sC, Epi e)
{
    constexpr int NT = (BM/TM)*(BN/TN);
    __shared__ float Sa[BK][BM+4];
    __shared__ float Sb[BK][BN+4];
    const int tid = threadIdx.x;
    const int bz  = blockIdx.z;
    A  += (long)bz * sA;
    Bp += (long)bz * sB;
    C  += (long)bz * sC;
    const float* Ad = e.add ? (e.add + (long)bz * e.strideAdd) : (const float*)0;
    const int m0 = blockIdx.y * BM;
    const int n0 = blockIdx.x * BN;
    const int tx = tid % (BN/TN);
    const int ty = tid / (BN/TN);

    float acc[TM][TN];
#pragma unroll
    for (int i=0;i<TM;i++)
#pragma unroll
        for (int j=0;j<TN;j++) acc[i][j]=0.f;

    for (int k0=0; k0<K; k0+=BK) {
        for (int vv=tid; vv<BM*BK/4; vv+=NT) {
            if (AM==0) {
                int m  = vv/(BK/4);
                int kk = (vv%(BK/4))*4;
                float4 f = *(const float4*)(A + (long)(m0+m)*K + (k0+kk));
                Sa[kk+0][m]=f.x; Sa[kk+1][m]=f.y; Sa[kk+2][m]=f.z; Sa[kk+3][m]=f.w;
            } else {
                int kk = vv/(BM/4);
                int mm = (vv%(BM/4))*4;
                *(float4*)&Sa[kk][mm] = *(const float4*)(A + (long)(k0+kk)*M + (m0+mm));
            }
        }
        for (int vv=tid; vv<BN*BK/4; vv+=NT) {
            if (BMO==0) {
                int n  = vv/(BK/4);
                int kk = (vv%(BK/4))*4;
                float4 f = *(const float4*)(Bp + (long)(n0+n)*K + (k0+kk));
                Sb[kk+0][n]=f.x; Sb[kk+1][n]=f.y; Sb[kk+2][n]=f.z; Sb[kk+3][n]=f.w;
            } else {
                int kk = vv/(BN/4);
                int nn = (vv%(BN/4))*4;
                *(float4*)&Sb[kk][nn] = *(const float4*)(Bp + (long)(k0+kk)*N + (n0+nn));
            }
        }
        __syncthreads();
#pragma unroll
        for (int k=0;k<BK;k++) {
            float ra[TM], rb[TN];
#pragma unroll
            for (int i=0;i<TM;i++) ra[i]=Sa[k][ty*TM+i];
#pragma unroll
            for (int j=0;j<TN;j++) rb[j]=Sb[k][tx*TN+j];
#pragma unroll
            for (int i=0;i<TM;i++)
#pragma unroll
                for (int j=0;j<TN;j++)
                    acc[i][j] = fmaf(ra[i], rb[j], acc[i][j]);
        }
        __syncthreads();
    }

#pragma unroll
    for (int i=0;i<TM;i++) {
        int gm = m0 + ty*TM + i;
#pragma unroll
        for (int j=0;j<TN;j++) {
            int gn = n0 + tx*TN + j;
            float v = e.alpha * acc[i][j];
            if (Ad) v += e.beta * Ad[(long)gm*N + gn];
            if (e.diag != 0.f && gm==gn) v += e.diag;
            C[(long)gm*N + gn] = v;
        }
    }
}

// ---------------- elementwise / reduction kernels ----------------
__global__ void ln_kernel(const float* __restrict__ x, const float* __restrict__ w,
                          __nv_bfloat16* __restrict__ oh, __nv_bfloat16* __restrict__ ol)
{
    const int r = blockIdx.x, tid = threadIdx.x;
    float4 f = ((const float4*)(x + (long)r*Cv))[tid];
    float s = f.x+f.y+f.z+f.w;
    float q = f.x*f.x+f.y*f.y+f.z*f.z+f.w*f.w;
    __shared__ float shs[4], shq[4];
#pragma unroll
    for (int off=16; off>0; off>>=1) {
        s += __shfl_down_sync(0xffffffffu, s, off);
        q += __shfl_down_sync(0xffffffffu, q, off);
    }
    if ((tid&31)==0) { shs[tid>>5]=s; shq[tid>>5]=q; }
    __syncthreads();
    float S = shs[0]+shs[1]+shs[2]+shs[3];
    float Q = shq[0]+shq[1]+shq[2]+shq[3];
    float mean = S*(1.f/Cv);
    float var  = Q*(1.f/Cv) - mean*mean;
    float inv  = rsqrtf(var + 1e-5f);
    float4 wf = ((const float4*)w)[tid];
    float o0=(f.x-mean)*inv*wf.x, o1=(f.y-mean)*inv*wf.y;
    float o2=(f.z-mean)*inv*wf.z, o3=(f.w-mean)*inv*wf.w;
    __nv_bfloat16 h0,h1,h2,h3,l0,l1,l2,l3;
    split2(o0,h0,l0); split2(o1,h1,l1); split2(o2,h2,l2); split2(o3,h3,l3);
    long ofs = (long)r*Cv + tid*4;
    uint2 uh; uh.x=pk2(h0,h1); uh.y=pk2(h2,h3);
    uint2 ul; ul.x=pk2(l0,l1); ul.y=pk2(l2,l3);
    *(uint2*)(oh+ofs)=uh; *(uint2*)(ol+ofs)=ul;
}

__global__ void pscan_combine(const float* __restrict__ z,
                              const float* __restrict__ qoF,
                              const __nv_bfloat16* __restrict__ qoH,
                              const __nv_bfloat16* __restrict__ qoL,
                              float* __restrict__ qnF,
                              __nv_bfloat16* __restrict__ qnH,
                              __nv_bfloat16* __restrict__ qnL, int d)
{
    const int r = blockIdx.x, tid = threadIdx.x;
    const int t = r & (Tv-1);
    long ofs = (long)r*Cv + tid*4;
    if (t < d) {
        *(float4*)(qnF+ofs) = *(const float4*)(qoF+ofs);
        *(uint2*)(qnH+ofs)  = *(const uint2*)(qoH+ofs);
        *(uint2*)(qnL+ofs)  = *(const uint2*)(qoL+ofs);
        return;
    }
    float4 f = *(const float4*)(z+ofs);
    float q = f.x*f.x+f.y*f.y+f.z*f.z+f.w*f.w;
    __shared__ float shq[4];
#pragma unroll
    for (int off=16; off>0; off>>=1) q += __shfl_down_sync(0xffffffffu, q, off);
    if ((tid&31)==0) shq[tid>>5]=q;
    __syncthreads();
    float Q = shq[0]+shq[1]+shq[2]+shq[3];
    float sc = rsqrtf(Q*(1.f/Cv) + 1e-6f);
    float o0=f.x*sc, o1=f.y*sc, o2=f.z*sc, o3=f.w*sc;
    *(float4*)(qnF+ofs) = make_float4(o0,o1,o2,o3);
    __nv_bfloat16 h0,h1,h2,h3,l0,l1,l2,l3;
    split2(o0,h0,l0); split2(o1,h1,l1); split2(o2,h2,l2); split2(o3,h3,l3);
    uint2 uh; uh.x=pk2(h0,h1); uh.y=pk2(h2,h3);
    uint2 ul; ul.x=pk2(l0,l1); ul.y=pk2(l2,l3);
    *(uint2*)(qnH+ofs)=uh; *(uint2*)(qnL+ofs)=ul;
}

__global__ void mul_split(const float* __restrict__ a, const float* __restrict__ b,
                          __nv_bfloat16* __restrict__ H, __nv_bfloat16* __restrict__ L)
{
    long i = ((long)blockIdx.x*blockDim.x + threadIdx.x)*4;
    float4 fa = *(const float4*)(a+i);
    float4 fb = *(const float4*)(b+i);
    float o0=fa.x*fb.x, o1=fa.y*fb.y, o2=fa.z*fb.z, o3=fa.w*fb.w;
    __nv_bfloat16 h0,h1,h2,h3,l0,l1,l2,l3;
    split2(o0,h0,l0); split2(o1,h1,l1); split2(o2,h2,l2); split2(o3,h3,l3);
    uint2 uh; uh.x=pk2(h0,h1); uh.y=pk2(h2,h3);
    uint2 ul; ul.x=pk2(l0,l1); ul.y=pk2(l2,l3);
    *(uint2*)(H+i)=uh; *(uint2*)(L+i)=ul;
}

__global__ void wsplit(const float* __restrict__ W, __nv_bfloat16* __restrict__ H,
                       __nv_bfloat16* __restrict__ L, int n)
{
    int i = blockIdx.x*256 + threadIdx.x;
    if (i < n) {
        float x = W[i];
        __nv_bfloat16 h, l; split2(x, h, l);
        H[i] = h; L[i] = l;
    }
}

__global__ void frob1(const float* __restrict__ W1, const float* __restrict__ W2,
                      float* __restrict__ part)
{
    const int row = blockIdx.x, mat = blockIdx.y, tid = threadIdx.x;
    const float* W = mat ? W2 : W1;
    float4 f = ((const float4*)(W + (long)row*Cv))[tid];
    float q = f.x*f.x+f.y*f.y+f.z*f.z+f.w*f.w;
    __shared__ float shq[4];
#pragma unroll
    for (int off=16; off>0; off>>=1) q += __shfl_down_sync(0xffffffffu, q, off);
    if ((tid&31)==0) shq[tid>>5]=q;
    __syncthreads();
    if (tid==0) part[mat*Cv + row] = shq[0]+shq[1]+shq[2]+shq[3];
}

__global__ void frob2(const float* __restrict__ part, float* __restrict__ rn)
{
    const int mat = blockIdx.x, tid = threadIdx.x;
    __shared__ float sh[256];
    sh[tid] = part[mat*Cv + tid] + part[mat*Cv + tid + 256];
    __syncthreads();
    for (int off=128; off>0; off>>=1) {
        if (tid<off) sh[tid] += sh[tid+off];
        __syncthreads();
    }
    if (tid==0) rn[mat] = rsqrtf(sh[0]);
}

__global__ void polar_scale(const float* __restrict__ W1, const float* __restrict__ W2,
                            const float* __restrict__ rn, float* __restrict__ X)
{
    int idx = blockIdx.x*blockDim.x + threadIdx.x;
    int mat = idx >> 18;
    float w = mat ? W2[idx - Cv*Cv] : W1[idx];
    X[idx] = w * rn[mat];
}

// ---------------- host ----------------
static inline Epi epi_none() { Epi e; e.alpha=1.f; e.add=0; e.beta=0.f; e.diag=0.f; e.strideAdd=0; return e; }
static inline TEpi tepi_none() { TEpi e; e.add=0; e.gelu=0; e.outF=0; e.outH=0; e.outL=0; return e; }

extern "C" void kernel_launch(void* const* d_in, const int* in_sizes, int n_in,
                              void* d_out, int out_size)
{
    const float* x   = (const float*)d_in[0];
    const float* ln1 = (const float*)d_in[1];
    const float* Wq  = (const float*)d_in[2];
    const float* Wv  = (const float*)d_in[3];
    const float* Wo  = (const float*)d_in[4];
    // d_in[5] = identity : mathematically unused (rows computed from it are discarded)
    const float* Wp1 = (const float*)d_in[6];
    const float* Wp2 = (const float*)d_in[7];
    const float* ln2 = (const float*)d_in[8];
    const float* Wfc = (const float*)d_in[9];
    const float* Wpr = (const float*)d_in[10];
    float* out = (float*)d_out;

    cudaFuncSetAttribute(mma_gemm, cudaFuncAttributeMaxDynamicSharedMemorySize, MM_SMEM);

    float *qAF,*qBF,*vF,*z,*X,*X2,*Y,*Mm,*part,*rn;
    __nv_bfloat16 *qAH,*qAL,*qBH,*qBL,*hH,*hL,*fcH,*fcL;
    __nv_bfloat16 *WqH,*WqL,*WvH,*WvL,*WoH,*WoL,*WfcH,*WfcL,*WprH,*WprL,*PH,*PL;
    cudaGetSymbolAddress((void**)&qAF, g_qAF);
    cudaGetSymbolAddress((void**)&qBF, g_qBF);
    cudaGetSymbolAddress((void**)&qAH, g_qAH);
    cudaGetSymbolAddress((void**)&qAL, g_qAL);
    cudaGetSymbolAddress((void**)&qBH, g_qBH);
    cudaGetSymbolAddress((void**)&qBL, g_qBL);
    cudaGetSymbolAddress((void**)&vF,  g_vF);
    cudaGetSymbolAddress((void**)&z,   g_z);
    cudaGetSymbolAddress((void**)&hH,  g_hH);
    cudaGetSymbolAddress((void**)&hL,  g_hL);
    cudaGetSymbolAddress((void**)&fcH, g_fcH);
    cudaGetSymbolAddress((void**)&fcL, g_fcL);
    cudaGetSymbolAddress((void**)&WqH, g_WqH); cudaGetSymbolAddress((void**)&WqL, g_WqL);
    cudaGetSymbolAddress((void**)&WvH, g_WvH); cudaGetSymbolAddress((void**)&WvL, g_WvL);
    cudaGetSymbolAddress((void**)&WoH, g_WoH); cudaGetSymbolAddress((void**)&WoL, g_WoL);
    cudaGetSymbolAddress((void**)&WfcH,g_WfcH); cudaGetSymbolAddress((void**)&WfcL,g_WfcL);
    cudaGetSymbolAddress((void**)&WprH,g_WprH); cudaGetSymbolAddress((void**)&WprL,g_WprL);
    cudaGetSymbolAddress((void**)&PH,  g_PH);  cudaGetSymbolAddress((void**)&PL,  g_PL);
    cudaGetSymbolAddress((void**)&X,  g_X);
    cudaGetSymbolAddress((void**)&X2, g_X2);
    cudaGetSymbolAddress((void**)&Y,  g_Y);
    cudaGetSymbolAddress((void**)&Mm, g_Mm);
    cudaGetSymbolAddress((void**)&part, g_part);
    cudaGetSymbolAddress((void**)&rn,   g_rn);

    const long S = (long)Cv*Cv;
    Epi e0 = epi_none();

    // ---- weight splits ----
    wsplit<<<(Cv*Cv+255)/256,256>>>(Wq, WqH, WqL, Cv*Cv);
    wsplit<<<(Cv*Cv+255)/256,256>>>(Wv, WvH, WvL, Cv*Cv);
    wsplit<<<(Cv*Cv+255)/256,256>>>(Wo, WoH, WoL, Cv*Cv);
    wsplit<<<(Fv*Cv+255)/256,256>>>(Wfc, WfcH, WfcL, Fv*Cv);
    wsplit<<<(Cv*Fv+255)/256,256>>>(Wpr, WprH, WprL, Cv*Fv);

    // ---- polar factors of Wp1, Wp2: Muon-quintic + Newton-Schulz (fp32 SIMT) ----
    frob1<<<dim3(Cv,2),128>>>(Wp1, Wp2, part);
    frob2<<<2,256>>>(part, rn);
    polar_scale<<<(2*Cv*Cv)/256,256>>>(Wp1, Wp2, rn, X);

    float* Xc = X;  float* Xn = X2;
    for (int it=0; it<9; ++it) {    // quintic: X <- X(aI + bY + cY^2), Y = X^T X
        gemm_k<32,32,16,2,2,1,1><<<dim3(16,16,2),256>>>(Xc, Xc, Y, Cv,Cv,Cv, S,S,S, e0);
        Epi em = e0; em.alpha=2.0315f; em.add=Y; em.beta=-4.7750f; em.diag=3.4445f; em.strideAdd=S;
        gemm_k<32,32,16,2,2,0,1><<<dim3(16,16,2),256>>>(Y, Y, Mm, Cv,Cv,Cv, S,S,S, em);
        gemm_k<32,32,16,2,2,0,1><<<dim3(16,16,2),256>>>(Xc, Mm, Xn, Cv,Cv,Cv, S,S,S, e0);
        float* tmp=Xc; Xc=Xn; Xn=tmp;
    }
    for (int it=0; it<7; ++it) {    // Newton-Schulz: X <- 1.5X - 0.5 X (X^T X)
        gemm_k<32,32,16,2,2,1,1><<<dim3(16,16,2),256>>>(Xc, Xc, Y, Cv,Cv,Cv, S,S,S, e0);
        Epi en = e0; en.alpha=-0.5f; en.add=Xc; en.beta=1.5f; en.strideAdd=S;
        gemm_k<32,32,16,2,2,0,1><<<dim3(16,16,2),256>>>(Xc, Y, Xn, Cv,Cv,Cv, S,S,S, en);
        float* tmp=Xc; Xc=Xn; Xn=tmp;
    }
    wsplit<<<(2*Cv*Cv+255)/256,256>>>(Xc, PH, PL, 2*Cv*Cv);
    __nv_bfloat16* P1H = PH;        __nv_bfloat16* P1L = PL;
    __nv_bfloat16* P2H = PH + S;    __nv_bfloat16* P2L = PL + S;

    // ---- SSM branch ----
    ln_kernel<<<Rv,128>>>(x, ln1, hH, hL);
    {
        TEpi eq = tepi_none(); eq.outF = qAF; eq.outH = qAH + GUARDE; eq.outL = qAL + GUARDE;
        mma_gemm<<<dim3(Cv/128, Rv/128), 256, MM_SMEM>>>(hH, hL, WqH, WqL, Rv, Cv, Cv, eq);
        TEpi ev = tepi_none(); ev.outF = vF;
        mma_gemm<<<dim3(Cv/128, Rv/128), 256, MM_SMEM>>>(hH, hL, WvH, WvL, Rv, Cv, Cv, ev);
    }

    float* qcF = qAF; float* qnF = qBF;
    __nv_bfloat16 *qcH = qAH, *qcL = qAL, *qnH = qBH, *qnL = qBL;
    for (int d=1; d<Tv; d<<=1) {
        // z = qshift @ P1^T  (guard rows are zeros; invalid rows discarded by combine)
        TEpi e1 = tepi_none(); e1.outF = z;
        mma_gemm<<<dim3(Cv/128, Rv/128), 256, MM_SMEM>>>(
            qcH + GUARDE - (long)d*Cv, qcL + GUARDE - (long)d*Cv, P1H, P1L, Rv, Cv, Cv, e1);
        // z += q @ P2^T
        TEpi e2 = tepi_none(); e2.add = z; e2.outF = z;
        mma_gemm<<<dim3(Cv/128, Rv/128), 256, MM_SMEM>>>(
            qcH + GUARDE, qcL + GUARDE, P2H, P2L, Rv, Cv, Cv, e2);
        pscan_combine<<<Rv,128>>>(z, qcF, qcH + GUARDE, qcL + GUARDE,
                                  qnF, qnH + GUARDE, qnL + GUARDE, d);
        { float* t=qcF; qcF=qnF; qnF=t; }
        { __nv_bfloat16* t=qcH; qcH=qnH; qnH=t; }
        { __nv_bfloat16* t=qcL; qcL=qnL; qnL=t; }
    }

    // x1 = x + (q*v) @ Wo^T   (into d_out)
    mul_split<<<(Rv*Cv/4)/256,256>>>(qcF, vF, hH, hL);
    {
        TEpi er = tepi_none(); er.add = x; er.outF = out;
        mma_gemm<<<dim3(Cv/128, Rv/128), 256, MM_SMEM>>>(hH, hL, WoH, WoL, Rv, Cv, Cv, er);
    }

    // ---- MLP branch ----
    ln_kernel<<<Rv,128>>>(out, ln2, hH, hL);
    {
        TEpi eg = tepi_none(); eg.gelu = 1; eg.outH = fcH; eg.outL = fcL;
        mma_gemm<<<dim3(Fv/128, Rv/128), 256, MM_SMEM>>>(hH, hL, WfcH, WfcL, Rv, Fv, Cv, eg);
        TEpi er2 = tepi_none(); er2.add = out; er2.outF = out;
        mma_gemm<<<dim3(Cv/128, Rv/128), 256, MM_SMEM>>>(fcH, fcL, WprH, WprL, Rv, Cv, Fv, er2);
    }
}

// round 6
// speedup vs baseline: 2.8338x; 1.4634x over previous
#include <cuda_runtime.h>
#include <cuda_bf16.h>
#include <math.h>
#include <stdint.h>

#define Bv 4
#define Tv 4096
#define Cv 512
#define Rv (Bv*Tv)            // 16384 rows
#define Fv (4*Cv)             // 2048
#define GUARDE (2048*Cv)      // guard rows (zero-init) for shifted scan operand
#define Sm ((long)Cv*Cv)

typedef __nv_bfloat16 bf16;

// ---------------- static device scratch (zero-initialized) ----------------
__device__ bf16 g_qH[GUARDE + Rv*Cv];
__device__ bf16 g_qL[GUARDE + Rv*Cv];
__device__ bf16 g_vH[Rv*Cv], g_vL[Rv*Cv];
__device__ float g_z[Rv*Cv];
__device__ bf16 g_hH[Rv*Cv], g_hL[Rv*Cv];
__device__ bf16 g_fcH[Rv*Fv], g_fcL[Rv*Fv];
// weight splits
__device__ bf16 g_WqH[Cv*Cv], g_WqL[Cv*Cv];
__device__ bf16 g_WvH[Cv*Cv], g_WvL[Cv*Cv];
__device__ bf16 g_WoH[Cv*Cv], g_WoL[Cv*Cv];
__device__ bf16 g_WfcH[Fv*Cv], g_WfcL[Fv*Cv];
__device__ bf16 g_WprH[Cv*Fv], g_WprL[Cv*Fv];
// polar scratch (x2 matrices, batched)
__device__ bf16 g_XaH[2*Cv*Cv], g_XaL[2*Cv*Cv];
__device__ bf16 g_XbH[2*Cv*Cv], g_XbL[2*Cv*Cv];
__device__ bf16 g_XtH[2*Cv*Cv], g_XtL[2*Cv*Cv];
__device__ bf16 g_YH [2*Cv*Cv], g_YL [2*Cv*Cv];
__device__ bf16 g_MH [2*Cv*Cv], g_ML [2*Cv*Cv];
__device__ float g_YF[2*Cv*Cv];
__device__ bf16 g_PcH[Cv*2*Cv], g_PcL[Cv*2*Cv];   // [P1||P2] along K (512 x 1024)
__device__ float g_part[2*Cv];
__device__ float g_rn[2];

// ================= helpers =================
__device__ __forceinline__ uint32_t smem_to_u32(const void* p) {
    uint32_t a;
    asm("{ .reg .u64 t; cvta.to.shared.u64 t, %1; cvt.u32.u64 %0, t; }" : "=r"(a) : "l"(p));
    return a;
}
__device__ __forceinline__ void split2(float x, bf16& h, bf16& l) {
    h = __float2bfloat16(x);
    l = __float2bfloat16(x - __bfloat162float(h));
}
__device__ __forceinline__ uint32_t pk2(bf16 a, bf16 b) {
    __nv_bfloat162 t; t.x = a; t.y = b;
    return *(uint32_t*)&t;
}
__device__ __forceinline__ void up2(uint32_t u, float& a, float& b) {
    __nv_bfloat162 t = *(__nv_bfloat162*)&u;
    a = __bfloat162float(t.x); b = __bfloat162float(t.y);
}
__device__ __forceinline__ void ldsm4(uint32_t (&r)[4], uint32_t addr) {
    asm volatile("ldmatrix.sync.aligned.m8n8.x4.shared.b16 {%0,%1,%2,%3}, [%4];"
        : "=r"(r[0]), "=r"(r[1]), "=r"(r[2]), "=r"(r[3]) : "r"(addr));
}
__device__ __forceinline__ void mma16816(float (&d)[4], const uint32_t (&a)[4],
                                         uint32_t b0, uint32_t b1) {
    asm volatile("mma.sync.aligned.m16n8k16.row.col.f32.bf16.bf16.f32 "
        "{%0,%1,%2,%3}, {%4,%5,%6,%7}, {%8,%9}, {%0,%1,%2,%3};"
        : "+f"(d[0]), "+f"(d[1]), "+f"(d[2]), "+f"(d[3])
        : "r"(a[0]), "r"(a[1]), "r"(a[2]), "r"(a[3]), "r"(b0), "r"(b1));
}
__device__ __forceinline__ void cp_async16(uint32_t so, const void* gp) {
    asm volatile("cp.async.cg.shared.global [%0], [%1], 16;" :: "r"(so), "l"(gp) : "memory");
}
#define CP_COMMIT() asm volatile("cp.async.commit_group;" ::: "memory")
#define CP_WAIT0()  asm volatile("cp.async.wait_group 0;" ::: "memory")
#define CP_WAIT1()  asm volatile("cp.async.wait_group 1;" ::: "memory")

// ================= mma.sync split-bf16 GEMM: C = alpha*A@B^T (+beta*add +diag*I) =====
// A: [M,K] bf16 hi/lo (rows split across Ah(.k<K1)/Ah2(k>=K1), pitch lda).
// B: [N,K] bf16 hi/lo, pitch ldb. 3 passes hh+hl+lh, fp32 reg accum.
// CTA tile BMxBM, 8 warps (2x4), K-chunk 64, cp.async double buffer. z-batched.
struct GA {
    const bf16 *Ah, *Al, *Ah2, *Al2, *Bh, *Bl;
    int M, N, K, K1, lda, ldb;
    long zA, zB;
};
struct TEpi {
    float alpha, beta, diag;
    const float* add; long zAdd;
    int gelu;
    float* outF; bf16 *outH, *outL; long zOut;
};

template<int BM, int BN>
__global__ __launch_bounds__(256)
void mma_gemm(GA g, TEpi e)
{
    static_assert(BM == BN, "square tiles only");
    constexpr int MF = BM/32, NF = BN/32, NB = NF/2;
    constexpr int ASZ = BM*128;        // one operand tile in bytes
    constexpr int BUF = 4*ASZ;         // hi/lo A + hi/lo B
    extern __shared__ char smem[];
    const uint32_t sb = smem_to_u32(smem);
    const int tid  = threadIdx.x;
    const int lane = tid & 31;
    const int wm   = (tid >> 5) & 1;
    const int wn   = (tid >> 5) >> 1;
    const int m0 = blockIdx.y * BM;
    const int n0 = blockIdx.x * BN;
    const int bz = blockIdx.z;
    const int NC = g.K / 64;

    const bf16 *Ah = g.Ah + bz*g.zA,  *Al = g.Al + bz*g.zA;
    const bf16 *Ah2 = g.Ah2 + bz*g.zA, *Al2 = g.Al2 + bz*g.zA;
    const bf16 *Bh = g.Bh + bz*g.zB,  *Bl = g.Bl + bz*g.zB;

    int aRow[MF], aXm[MF];
#pragma unroll
    for (int mf = 0; mf < MF; mf++) {
        int r = wm * (BM/2) + mf * 16 + (lane & 15);
        aRow[mf] = r * 128;
        aXm[mf]  = (r & 7) << 4;
    }
    const int aKb = (lane >> 4) * 16;
    int bRow[NB], bXm[NB];
#pragma unroll
    for (int nb = 0; nb < NB; nb++) {
        int r = wn * (BN/4) + nb * 16 + ((lane >> 4) << 3) + (lane & 7);
        bRow[nb] = r * 128;
        bXm[nb]  = (r & 7) << 4;
    }
    const int bKb = ((lane >> 3) & 1) * 16;

    float acc[MF][NF][4];
#pragma unroll
    for (int i = 0; i < MF; i++)
#pragma unroll
        for (int j = 0; j < NF; j++)
#pragma unroll
            for (int t = 0; t < 4; t++) acc[i][j][t] = 0.f;

    auto loadChunk = [&](int c, int b) {
        const long cofs = (long)c * 64;
        const bf16* AHc = Ah; const bf16* ALc = Al;
        long acol = cofs;
        if (cofs >= g.K1) { AHc = Ah2; ALc = Al2; acol = cofs - g.K1; }
        constexpr int TV = BM * 8;      // 16B vectors per tile
#pragma unroll
        for (int t = 0; t < (4*TV)/256; t++) {
            int u = tid + t * 256;
            int tile = u / TV;
            int w = u % TV;
            int row = w >> 3;
            int seg = w & 7;
            const bf16* gp;
            if      (tile == 0) gp = AHc + (long)(m0 + row) * g.lda + acol;
            else if (tile == 1) gp = ALc + (long)(m0 + row) * g.lda + acol;
            else if (tile == 2) gp = Bh + (long)(n0 + row) * g.ldb + cofs;
            else                gp = Bl + (long)(n0 + row) * g.ldb + cofs;
            gp += seg * 8;
            uint32_t so = sb + b * BUF + tile * ASZ + row * 128
                        + ((seg * 16) ^ ((row & 7) << 4));
            cp_async16(so, gp);
        }
        CP_COMMIT();
    };

    loadChunk(0, 0);

    for (int c = 0; c < NC; c++) {
        if (c + 1 < NC) {
            loadChunk(c + 1, (c + 1) & 1);
            CP_WAIT1();
        } else {
            CP_WAIT0();
        }
        __syncthreads();

        const uint32_t bufB = sb + (c & 1) * BUF;
#pragma unroll
        for (int ks = 0; ks < 4; ks++) {
            uint32_t afH[MF][4], afL[MF][4], bfH[NB][4], bfL[NB][4];
#pragma unroll
            for (int mf = 0; mf < MF; mf++) {
                uint32_t off = aRow[mf] + ((ks * 32 + aKb) ^ aXm[mf]);
                ldsm4(afH[mf], bufB + off);
                ldsm4(afL[mf], bufB + ASZ + off);
            }
#pragma unroll
            for (int nb = 0; nb < NB; nb++) {
                uint32_t off = bRow[nb] + ((ks * 32 + bKb) ^ bXm[nb]);
                ldsm4(bfH[nb], bufB + 2*ASZ + off);
                ldsm4(bfL[nb], bufB + 3*ASZ + off);
            }
#pragma unroll
            for (int mf = 0; mf < MF; mf++)
#pragma unroll
                for (int nf = 0; nf < NF; nf++)
                    mma16816(acc[mf][nf], afH[mf], bfH[nf>>1][(nf&1)*2], bfH[nf>>1][(nf&1)*2+1]);
#pragma unroll
            for (int mf = 0; mf < MF; mf++)
#pragma unroll
                for (int nf = 0; nf < NF; nf++)
                    mma16816(acc[mf][nf], afH[mf], bfL[nf>>1][(nf&1)*2], bfL[nf>>1][(nf&1)*2+1]);
#pragma unroll
            for (int mf = 0; mf < MF; mf++)
#pragma unroll
                for (int nf = 0; nf < NF; nf++)
                    mma16816(acc[mf][nf], afL[mf], bfH[nf>>1][(nf&1)*2], bfH[nf>>1][(nf&1)*2+1]);
        }
        __syncthreads();
    }

    // ---- epilogue ----
    float* outF = e.outF ? e.outF + bz*e.zOut : (float*)0;
    bf16*  outH = e.outH ? e.outH + bz*e.zOut : (bf16*)0;
    bf16*  outL = e.outL ? e.outL + bz*e.zOut : (bf16*)0;
    const float* add = e.add ? e.add + bz*e.zAdd : (const float*)0;
    const int rl = lane >> 2;
    const int cl = (lane & 3) * 2;
#pragma unroll
    for (int mf = 0; mf < MF; mf++) {
#pragma unroll
        for (int nf = 0; nf < NF; nf++) {
            int c0 = n0 + wn * (BN/4) + nf * 8 + cl;
#pragma unroll
            for (int half = 0; half < 2; half++) {
                int row = m0 + wm * (BM/2) + mf * 16 + rl + half * 8;
                long ofs = (long)row * g.N + c0;
                float f0 = e.alpha * acc[mf][nf][half*2];
                float f1 = e.alpha * acc[mf][nf][half*2 + 1];
                if (add) {
                    float2 ra = *(const float2*)(add + ofs);
                    f0 += e.beta * ra.x; f1 += e.beta * ra.y;
                }
                if (e.diag != 0.f) {
                    if (row == c0)     f0 += e.diag;
                    if (row == c0 + 1) f1 += e.diag;
                }
                if (e.gelu) {
                    f0 = 0.5f * f0 * (1.f + erff(f0 * 0.70710678118654752f));
                    f1 = 0.5f * f1 * (1.f + erff(f1 * 0.70710678118654752f));
                }
                if (outF)
                    *(float2*)(outF + ofs) = make_float2(f0, f1);
                if (outH) {
                    bf16 h0, h1, l0, l1;
                    split2(f0, h0, l0);
                    split2(f1, h1, l1);
                    *(uint32_t*)(outH + ofs) = pk2(h0, h1);
                    *(uint32_t*)(outL + ofs) = pk2(l0, l1);
                }
            }
        }
    }
}

// ---------------- elementwise / reduction kernels ----------------
__global__ void ln_kernel(const float* __restrict__ x, const float* __restrict__ w,
                          bf16* __restrict__ oh, bf16* __restrict__ ol)
{
    const int r = blockIdx.x, tid = threadIdx.x;
    float4 f = ((const float4*)(x + (long)r*Cv))[tid];
    float s = f.x+f.y+f.z+f.w;
    float q = f.x*f.x+f.y*f.y+f.z*f.z+f.w*f.w;
    __shared__ float shs[4], shq[4];
#pragma unroll
    for (int off=16; off>0; off>>=1) {
        s += __shfl_down_sync(0xffffffffu, s, off);
        q += __shfl_down_sync(0xffffffffu, q, off);
    }
    if ((tid&31)==0) { shs[tid>>5]=s; shq[tid>>5]=q; }
    __syncthreads();
    float S = shs[0]+shs[1]+shs[2]+shs[3];
    float Q = shq[0]+shq[1]+shq[2]+shq[3];
    float mean = S*(1.f/Cv);
    float var  = Q*(1.f/Cv) - mean*mean;
    float inv  = rsqrtf(var + 1e-5f);
    float4 wf = ((const float4*)w)[tid];
    float o0=(f.x-mean)*inv*wf.x, o1=(f.y-mean)*inv*wf.y;
    float o2=(f.z-mean)*inv*wf.z, o3=(f.w-mean)*inv*wf.w;
    bf16 h0,h1,h2,h3,l0,l1,l2,l3;
    split2(o0,h0,l0); split2(o1,h1,l1); split2(o2,h2,l2); split2(o3,h3,l3);
    long ofs = (long)r*Cv + tid*4;
    uint2 uh; uh.x=pk2(h0,h1); uh.y=pk2(h2,h3);
    uint2 ul; ul.x=pk2(l0,l1); ul.y=pk2(l2,l3);
    *(uint2*)(oh+ofs)=uh; *(uint2*)(ol+ofs)=ul;
}

// in-place scan combine: q[t] <- rms(z[t]) for t >= d; rows t < d untouched
__global__ void pscan_combine(const float* __restrict__ z,
                              bf16* __restrict__ qH, bf16* __restrict__ qL, int d)
{
    const int r = blockIdx.x, tid = threadIdx.x;
    if ((r & (Tv-1)) < d) return;
    long ofs = (long)r*Cv + tid*4;
    float4 f = *(const float4*)(z+ofs);
    float q = f.x*f.x+f.y*f.y+f.z*f.z+f.w*f.w;
    __shared__ float shq[4];
#pragma unroll
    for (int off=16; off>0; off>>=1) q += __shfl_down_sync(0xffffffffu, q, off);
    if ((tid&31)==0) shq[tid>>5]=q;
    __syncthreads();
    float Q = shq[0]+shq[1]+shq[2]+shq[3];
    float sc = rsqrtf(Q*(1.f/Cv) + 1e-6f);
    float o0=f.x*sc, o1=f.y*sc, o2=f.z*sc, o3=f.w*sc;
    bf16 h0,h1,h2,h3,l0,l1,l2,l3;
    split2(o0,h0,l0); split2(o1,h1,l1); split2(o2,h2,l2); split2(o3,h3,l3);
    uint2 uh; uh.x=pk2(h0,h1); uh.y=pk2(h2,h3);
    uint2 ul; ul.x=pk2(l0,l1); ul.y=pk2(l2,l3);
    *(uint2*)(qH+ofs)=uh; *(uint2*)(qL+ofs)=ul;
}

// h = split(q * v) with q,v reconstructed from bf16 pairs
__global__ void mul_split(const bf16* __restrict__ qH, const bf16* __restrict__ qL,
                          const bf16* __restrict__ vH, const bf16* __restrict__ vL,
                          bf16* __restrict__ H, bf16* __restrict__ L)
{
    long i = ((long)blockIdx.x*256 + threadIdx.x)*4;
    uint2 a = *(const uint2*)(qH+i), b = *(const uint2*)(qL+i);
    uint2 c = *(const uint2*)(vH+i), d = *(const uint2*)(vL+i);
    float q0,q1,q2,q3,ql0,ql1,ql2,ql3,v0,v1,v2,v3,vl0,vl1,vl2,vl3;
    up2(a.x,q0,q1); up2(a.y,q2,q3); up2(b.x,ql0,ql1); up2(b.y,ql2,ql3);
    up2(c.x,v0,v1); up2(c.y,v2,v3); up2(d.x,vl0,vl1); up2(d.y,vl2,vl3);
    float o0=(q0+ql0)*(v0+vl0), o1=(q1+ql1)*(v1+vl1);
    float o2=(q2+ql2)*(v2+vl2), o3=(q3+ql3)*(v3+vl3);
    bf16 h0,h1,h2,h3,l0,l1,l2,l3;
    split2(o0,h0,l0); split2(o1,h1,l1); split2(o2,h2,l2); split2(o3,h3,l3);
    uint2 uh; uh.x=pk2(h0,h1); uh.y=pk2(h2,h3);
    uint2 ul; ul.x=pk2(l0,l1); ul.y=pk2(l2,l3);
    *(uint2*)(H+i)=uh; *(uint2*)(L+i)=ul;
}

__global__ void wsplit(const float* __restrict__ W, bf16* __restrict__ H,
                       bf16* __restrict__ L, int n)
{
    int i = blockIdx.x*256 + threadIdx.x;
    if (i < n) {
        float x = W[i];
        bf16 h, l; split2(x, h, l);
        H[i] = h; L[i] = l;
    }
}

__global__ void frob1(const float* __restrict__ W1, const float* __restrict__ W2,
                      float* __restrict__ part)
{
    const int row = blockIdx.x, mat = blockIdx.y, tid = threadIdx.x;
    const float* W = mat ? W2 : W1;
    float4 f = ((const float4*)(W + (long)row*Cv))[tid];
    float q = f.x*f.x+f.y*f.y+f.z*f.z+f.w*f.w;
    __shared__ float shq[4];
#pragma unroll
    for (int off=16; off>0; off>>=1) q += __shfl_down_sync(0xffffffffu, q, off);
    if ((tid&31)==0) shq[tid>>5]=q;
    __syncthreads();
    if (tid==0) part[mat*Cv + row] = shq[0]+shq[1]+shq[2]+shq[3];
}

__global__ void frob2(const float* __restrict__ part, float* __restrict__ rn)
{
    const int mat = blockIdx.x, tid = threadIdx.x;
    __shared__ float sh[256];
    sh[tid] = part[mat*Cv + tid] + part[mat*Cv + tid + 256];
    __syncthreads();
    for (int off=128; off>0; off>>=1) {
        if (tid<off) sh[tid] += sh[tid+off];
        __syncthreads();
    }
    if (tid==0) rn[mat] = rsqrtf(sh[0]);
}

// X = W * rn, split to H/L, plus transposed copies. grid (16,16,2), block (32,8).
__global__ void split_tr_init(const float* __restrict__ W1, const float* __restrict__ W2,
                              const float* __restrict__ rn,
                              bf16* XH, bf16* XL, bf16* XtH, bf16* XtL)
{
    __shared__ float t[32][33];
    const int mat = blockIdx.z;
    const float* W = mat ? W2 : W1;
    const float s = rn[mat];
    const int r0 = blockIdx.y*32, c0 = blockIdx.x*32;
    const int tx = threadIdx.x, ty = threadIdx.y;
    const long mo = (long)mat*Sm;
#pragma unroll
    for (int i = 0; i < 4; i++) {
        int rr = ty + i*8;
        t[rr][tx] = W[(long)(r0+rr)*Cv + c0+tx] * s;
    }
    __syncthreads();
#pragma unroll
    for (int i = 0; i < 4; i++) {
        int rr = ty + i*8;
        bf16 h, l;
        split2(t[rr][tx], h, l);
        XH[mo + (long)(r0+rr)*Cv + c0+tx] = h;
        XL[mo + (long)(r0+rr)*Cv + c0+tx] = l;
        split2(t[tx][rr], h, l);
        XtH[mo + (long)(c0+rr)*Cv + r0+tx] = h;
        XtL[mo + (long)(c0+rr)*Cv + r0+tx] = l;
    }
}

// bf16 pair transpose: Xt = X^T. grid (16,16,2), block (32,8).
__global__ void tr_pair(const bf16* __restrict__ XH, const bf16* __restrict__ XL,
                        bf16* __restrict__ XtH, bf16* __restrict__ XtL)
{
    __shared__ bf16 th[32][34], tl[32][34];
    const int mat = blockIdx.z;
    const int r0 = blockIdx.y*32, c0 = blockIdx.x*32;
    const int tx = threadIdx.x, ty = threadIdx.y;
    const long mo = (long)mat*Sm;
#pragma unroll
    for (int i = 0; i < 4; i++) {
        int rr = ty + i*8;
        th[rr][tx] = XH[mo + (long)(r0+rr)*Cv + c0+tx];
        tl[rr][tx] = XL[mo + (long)(r0+rr)*Cv + c0+tx];
    }
    __syncthreads();
#pragma unroll
    for (int i = 0; i < 4; i++) {
        int rr = ty + i*8;
        XtH[mo + (long)(c0+rr)*Cv + r0+tx] = th[tx][rr];
        XtL[mo + (long)(c0+rr)*Cv + r0+tx] = tl[tx][rr];
    }
}

// Pc[n, 0:512] = P1[n,:], Pc[n, 512:1024] = P2[n,:]
__global__ void packP(const bf16* __restrict__ XH, const bf16* __restrict__ XL,
                      bf16* __restrict__ PcH, bf16* __restrict__ PcL)
{
    int idx = blockIdx.x*256 + threadIdx.x;     // over 512*1024
    int n = idx >> 10, k = idx & 1023;
    long src = (k < 512) ? ((long)n*Cv + k) : (Sm + (long)n*Cv + (k-512));
    PcH[idx] = XH[src];
    PcL[idx] = XL[src];
}

// ---------------- host ----------------
static inline GA mkga(const bf16* Ah, const bf16* Al, const bf16* Bh, const bf16* Bl,
                      int M, int N, int K, int lda, int ldb, long zA = 0, long zB = 0)
{
    GA g; g.Ah=Ah; g.Al=Al; g.Ah2=Ah; g.Al2=Al; g.Bh=Bh; g.Bl=Bl;
    g.M=M; g.N=N; g.K=K; g.K1=K; g.lda=lda; g.ldb=ldb; g.zA=zA; g.zB=zB;
    return g;
}
static inline TEpi te()
{
    TEpi e; e.alpha=1.f; e.beta=1.f; e.diag=0.f; e.add=0; e.zAdd=0;
    e.gelu=0; e.outF=0; e.outH=0; e.outL=0; e.zOut=0;
    return e;
}

#define SM128 (2*4*128*128)
#define SM64  (2*4*64*128)

extern "C" void kernel_launch(void* const* d_in, const int* in_sizes, int n_in,
                              void* d_out, int out_size)
{
    const float* x   = (const float*)d_in[0];
    const float* ln1 = (const float*)d_in[1];
    const float* Wq  = (const float*)d_in[2];
    const float* Wv  = (const float*)d_in[3];
    const float* Wo  = (const float*)d_in[4];
    // d_in[5] = identity : mathematically unused (rows computed from it are discarded)
    const float* Wp1 = (const float*)d_in[6];
    const float* Wp2 = (const float*)d_in[7];
    const float* ln2 = (const float*)d_in[8];
    const float* Wfc = (const float*)d_in[9];
    const float* Wpr = (const float*)d_in[10];
    float* out = (float*)d_out;

    cudaFuncSetAttribute(mma_gemm<128,128>, cudaFuncAttributeMaxDynamicSharedMemorySize, SM128);
    cudaFuncSetAttribute(mma_gemm<64,64>,   cudaFuncAttributeMaxDynamicSharedMemorySize, SM64);

    bf16 *qH,*qL,*vH,*vL,*hH,*hL,*fcH,*fcL;
    bf16 *WqH,*WqL,*WvH,*WvL,*WoH,*WoL,*WfcH,*WfcL,*WprH,*WprL;
    bf16 *XaH,*XaL,*XbH,*XbL,*XtH,*XtL,*YH,*YL,*MH,*ML,*PcH,*PcL;
    float *z,*YF,*part,*rn;
    cudaGetSymbolAddress((void**)&qH, g_qH);   cudaGetSymbolAddress((void**)&qL, g_qL);
    cudaGetSymbolAddress((void**)&vH, g_vH);   cudaGetSymbolAddress((void**)&vL, g_vL);
    cudaGetSymbolAddress((void**)&hH, g_hH);   cudaGetSymbolAddress((void**)&hL, g_hL);
    cudaGetSymbolAddress((void**)&fcH, g_fcH); cudaGetSymbolAddress((void**)&fcL, g_fcL);
    cudaGetSymbolAddress((void**)&WqH, g_WqH); cudaGetSymbolAddress((void**)&WqL, g_WqL);
    cudaGetSymbolAddress((void**)&WvH, g_WvH); cudaGetSymbolAddress((void**)&WvL, g_WvL);
    cudaGetSymbolAddress((void**)&WoH, g_WoH); cudaGetSymbolAddress((void**)&WoL, g_WoL);
    cudaGetSymbolAddress((void**)&WfcH,g_WfcH); cudaGetSymbolAddress((void**)&WfcL,g_WfcL);
    cudaGetSymbolAddress((void**)&WprH,g_WprH); cudaGetSymbolAddress((void**)&WprL,g_WprL);
    cudaGetSymbolAddress((void**)&XaH, g_XaH); cudaGetSymbolAddress((void**)&XaL, g_XaL);
    cudaGetSymbolAddress((void**)&XbH, g_XbH); cudaGetSymbolAddress((void**)&XbL, g_XbL);
    cudaGetSymbolAddress((void**)&XtH, g_XtH); cudaGetSymbolAddress((void**)&XtL, g_XtL);
    cudaGetSymbolAddress((void**)&YH,  g_YH);  cudaGetSymbolAddress((void**)&YL,  g_YL);
    cudaGetSymbolAddress((void**)&MH,  g_MH);  cudaGetSymbolAddress((void**)&ML,  g_ML);
    cudaGetSymbolAddress((void**)&PcH, g_PcH); cudaGetSymbolAddress((void**)&PcL, g_PcL);
    cudaGetSymbolAddress((void**)&z,   g_z);
    cudaGetSymbolAddress((void**)&YF,  g_YF);
    cudaGetSymbolAddress((void**)&part,g_part);
    cudaGetSymbolAddress((void**)&rn,  g_rn);

    // ---- weight splits ----
    wsplit<<<(Cv*Cv+255)/256,256>>>(Wq, WqH, WqL, Cv*Cv);
    wsplit<<<(Cv*Cv+255)/256,256>>>(Wv, WvH, WvL, Cv*Cv);
    wsplit<<<(Cv*Cv+255)/256,256>>>(Wo, WoH, WoL, Cv*Cv);
    wsplit<<<(Fv*Cv+255)/256,256>>>(Wfc, WfcH, WfcL, Fv*Cv);
    wsplit<<<(Cv*Fv+255)/256,256>>>(Wpr, WprH, WprL, Cv*Fv);

    // ---- polar factors via Muon-quintic + Newton-Schulz on tensor cores ----
    frob1<<<dim3(Cv,2),128>>>(Wp1, Wp2, part);
    frob2<<<2,256>>>(part, rn);
    split_tr_init<<<dim3(16,16,2),dim3(32,8)>>>(Wp1, Wp2, rn, XaH, XaL, XtH, XtL);

    const dim3 gp(8, 8, 2);
    const dim3 gt(16, 16, 2);
    const dim3 bt(32, 8);
    for (int it = 0; it < 9; ++it) {
        // Y = Xt @ Xt^T  (= X^T X, symmetric)
        GA g1 = mkga(XtH, XtL, XtH, XtL, Cv, Cv, Cv, Cv, Cv, Sm, Sm);
        TEpi e1 = te(); e1.outF = YF; e1.outH = YH; e1.outL = YL; e1.zOut = Sm;
        mma_gemm<64,64><<<gp,256,SM64>>>(g1, e1);
        // M = 2.0315*Y@Y^T - 4.7750*Y + 3.4445*I  (symmetric)
        GA g2 = mkga(YH, YL, YH, YL, Cv, Cv, Cv, Cv, Cv, Sm, Sm);
        TEpi e2 = te(); e2.alpha = 2.0315f; e2.add = YF; e2.zAdd = Sm;
        e2.beta = -4.7750f; e2.diag = 3.4445f; e2.outH = MH; e2.outL = ML; e2.zOut = Sm;
        mma_gemm<64,64><<<gp,256,SM64>>>(g2, e2);
        // X' = X @ M^T (= X M, M symmetric)
        GA g3 = mkga(XaH, XaL, MH, ML, Cv, Cv, Cv, Cv, Cv, Sm, Sm);
        TEpi e3 = te(); e3.outH = XbH; e3.outL = XbL; e3.zOut = Sm;
        mma_gemm<64,64><<<gp,256,SM64>>>(g3, e3);
        tr_pair<<<gt,bt>>>(XbH, XbL, XtH, XtL);
        bf16* t;
        t = XaH; XaH = XbH; XbH = t;
        t = XaL; XaL = XbL; XbL = t;
    }
    for (int it = 0; it < 5; ++it) {
        // G = -0.5*Xt@Xt^T + 1.5I  (symmetric)
        GA g1 = mkga(XtH, XtL, XtH, XtL, Cv, Cv, Cv, Cv, Cv, Sm, Sm);
        TEpi e1 = te(); e1.alpha = -0.5f; e1.diag = 1.5f;
        e1.outH = MH; e1.outL = ML; e1.zOut = Sm;
        mma_gemm<64,64><<<gp,256,SM64>>>(g1, e1);
        // X' = X @ G^T
        GA g2 = mkga(XaH, XaL, MH, ML, Cv, Cv, Cv, Cv, Cv, Sm, Sm);
        TEpi e2 = te(); e2.outH = XbH; e2.outL = XbL; e2.zOut = Sm;
        mma_gemm<64,64><<<gp,256,SM64>>>(g2, e2);
        if (it + 1 < 5) tr_pair<<<gt,bt>>>(XbH, XbL, XtH, XtL);
        bf16* t;
        t = XaH; XaH = XbH; XbH = t;
        t = XaL; XaL = XbL; XbL = t;
    }
    packP<<<(Cv*2*Cv)/256,256>>>(XaH, XaL, PcH, PcL);

    // ---- SSM branch ----
    ln_kernel<<<Rv,128>>>(x, ln1, hH, hL);
    {
        GA gq = mkga(hH, hL, WqH, WqL, Rv, Cv, Cv, Cv, Cv);
        TEpi eq = te(); eq.outH = qH + GUARDE; eq.outL = qL + GUARDE;
        mma_gemm<128,128><<<dim3(Cv/128, Rv/128), 256, SM128>>>(gq, eq);
        GA gv = mkga(hH, hL, WvH, WvL, Rv, Cv, Cv, Cv, Cv);
        TEpi ev = te(); ev.outH = vH; ev.outL = vL;
        mma_gemm<128,128><<<dim3(Cv/128, Rv/128), 256, SM128>>>(gv, ev);
    }

    for (int d = 1; d < Tv; d <<= 1) {
        // z = qshift @ P1^T + q @ P2^T : single GEMM, K=1024
        // chunks k<512 read q[t-d] (guard zeros), k>=512 read q[t]; B = [P1||P2]
        GA gs = mkga(qH + GUARDE, qL + GUARDE, PcH, PcL, Rv, Cv, 2*Cv, Cv, 2*Cv);
        gs.Ah = qH + GUARDE - (long)d*Cv;
        gs.Al = qL + GUARDE - (long)d*Cv;
        gs.K1 = Cv;
        TEpi es = te(); es.outF = z;
        mma_gemm<128,128><<<dim3(Cv/128, Rv/128), 256, SM128>>>(gs, es);
        pscan_combine<<<Rv,128>>>(z, qH + GUARDE, qL + GUARDE, d);
    }

    // x1 = x + (q*v) @ Wo^T   (into d_out)
    mul_split<<<(Rv*Cv/4)/256,256>>>(qH + GUARDE, qL + GUARDE, vH, vL, hH, hL);
    {
        GA go = mkga(hH, hL, WoH, WoL, Rv, Cv, Cv, Cv, Cv);
        TEpi er = te(); er.add = x; er.outF = out;
        mma_gemm<128,128><<<dim3(Cv/128, Rv/128), 256, SM128>>>(go, er);
    }

    // ---- MLP branch ----
    ln_kernel<<<Rv,128>>>(out, ln2, hH, hL);
    {
        GA gf = mkga(hH, hL, WfcH, WfcL, Rv, Fv, Cv, Cv, Cv);
        TEpi eg = te(); eg.gelu = 1; eg.outH = fcH; eg.outL = fcL;
        mma_gemm<128,128><<<dim3(Fv/128, Rv/128), 256, SM128>>>(gf, eg);
        GA gr = mkga(fcH, fcL, WprH, WprL, Rv, Cv, Fv, Fv, Fv);
        TEpi er2 = te(); er2.add = out; er2.outF = out;
        mma_gemm<128,128><<<dim3(Cv/128, Rv/128), 256, SM128>>>(gr, er2);
    }
}

// round 7
// speedup vs baseline: 3.1484x; 1.1110x over previous
#include <cuda_runtime.h>
#include <cuda_bf16.h>
#include <math.h>
#include <stdint.h>

#define Bv 4
#define Tv 4096
#define Cv 512
#define Rv (Bv*Tv)            // 16384 rows
#define Fv (4*Cv)             // 2048
#define GUARDE (2048*Cv)      // guard rows (zero-init) for shifted scan operand
#define Sm ((long)Cv*Cv)

typedef __nv_bfloat16 bf16;

// ---------------- static device scratch (zero-initialized) ----------------
__device__ bf16 g_qH[GUARDE + Rv*Cv];
__device__ bf16 g_qL[GUARDE + Rv*Cv];
__device__ bf16 g_vH[Rv*Cv], g_vL[Rv*Cv];
__device__ float g_z[Rv*Cv];
__device__ bf16 g_hH[Rv*Cv], g_hL[Rv*Cv];
__device__ bf16 g_fcH[Rv*Fv], g_fcL[Rv*Fv];
// weight splits
__device__ bf16 g_WqH[Cv*Cv], g_WqL[Cv*Cv];
__device__ bf16 g_WvH[Cv*Cv], g_WvL[Cv*Cv];
__device__ bf16 g_WoH[Cv*Cv], g_WoL[Cv*Cv];
__device__ bf16 g_WfcH[Fv*Cv], g_WfcL[Fv*Cv];
__device__ bf16 g_WprH[Cv*Fv], g_WprL[Cv*Fv];
// polar scratch (x2 matrices, batched)
__device__ bf16 g_XaH[2*Cv*Cv], g_XaL[2*Cv*Cv];
__device__ bf16 g_XbH[2*Cv*Cv], g_XbL[2*Cv*Cv];
__device__ bf16 g_XtH[2*Cv*Cv], g_XtL[2*Cv*Cv];
__device__ bf16 g_YH [2*Cv*Cv], g_YL [2*Cv*Cv];
__device__ bf16 g_MH [2*Cv*Cv], g_ML [2*Cv*Cv];
__device__ float g_YF[2*Cv*Cv];
__device__ bf16 g_PcH[Cv*2*Cv], g_PcL[Cv*2*Cv];   // [P1||P2] along K (512 x 1024)
__device__ float g_part[2*Cv];
__device__ float g_rn[2];

// ================= helpers =================
__device__ __forceinline__ uint32_t smem_to_u32(const void* p) {
    uint32_t a;
    asm("{ .reg .u64 t; cvta.to.shared.u64 t, %1; cvt.u32.u64 %0, t; }" : "=r"(a) : "l"(p));
    return a;
}
__device__ __forceinline__ void split2(float x, bf16& h, bf16& l) {
    h = __float2bfloat16(x);
    l = __float2bfloat16(x - __bfloat162float(h));
}
__device__ __forceinline__ uint32_t pk2(bf16 a, bf16 b) {
    __nv_bfloat162 t; t.x = a; t.y = b;
    return *(uint32_t*)&t;
}
__device__ __forceinline__ void up2(uint32_t u, float& a, float& b) {
    __nv_bfloat162 t = *(__nv_bfloat162*)&u;
    a = __bfloat162float(t.x); b = __bfloat162float(t.y);
}
__device__ __forceinline__ void ldsm4(uint32_t (&r)[4], uint32_t addr) {
    asm volatile("ldmatrix.sync.aligned.m8n8.x4.shared.b16 {%0,%1,%2,%3}, [%4];"
        : "=r"(r[0]), "=r"(r[1]), "=r"(r[2]), "=r"(r[3]) : "r"(addr));
}
__device__ __forceinline__ void mma16816(float (&d)[4], const uint32_t (&a)[4],
                                         uint32_t b0, uint32_t b1) {
    asm volatile("mma.sync.aligned.m16n8k16.row.col.f32.bf16.bf16.f32 "
        "{%0,%1,%2,%3}, {%4,%5,%6,%7}, {%8,%9}, {%0,%1,%2,%3};"
        : "+f"(d[0]), "+f"(d[1]), "+f"(d[2]), "+f"(d[3])
        : "r"(a[0]), "r"(a[1]), "r"(a[2]), "r"(a[3]), "r"(b0), "r"(b1));
}
__device__ __forceinline__ void cp_async16(uint32_t so, const void* gp) {
    asm volatile("cp.async.cg.shared.global [%0], [%1], 16;" :: "r"(so), "l"(gp) : "memory");
}
#define CP_COMMIT() asm volatile("cp.async.commit_group;" ::: "memory")
#define CP_WAIT(n)  asm volatile("cp.async.wait_group %0;" :: "n"(n) : "memory")

// ================= mma.sync split-bf16 GEMM: C = alpha*A@B^T (+beta*add +diag*I) =====
// A: [M,K] bf16 hi/lo (K ranges split across Ah(k<K1)/Ah2(k>=K1), pitch lda).
// B: [N,K] bf16 hi/lo, pitch ldb. 3 passes hh+hl+lh, fp32 reg accum.
// CTA tile BMxBM, 8 warps (2x4). K-chunk 32, 3-stage cp.async pipeline,
// paired-row smem layout (two 64B k-rows per 128B line, XOR-16 swizzle).
// grid.z batches: A/B/out/add advance by zA/zB/zOut/zAdd; rows offset by mskip.
struct GA {
    const bf16 *Ah, *Al, *Ah2, *Al2, *Bh, *Bl;
    int M, N, K, K1, lda, ldb, mskip;
    long zA, zB;
};
struct TEpi {
    float alpha, beta, diag;
    const float* add; long zAdd;
    int gelu;
    float* outF; bf16 *outH, *outL; long zOut;
};

template<int BM, int BN>
__global__ __launch_bounds__(256, 2)
void mma_gemm(GA g, TEpi e)
{
    static_assert(BM == BN, "square tiles only");
    constexpr int MF = BM/32, NF = BN/32, NB = NF/2;
    constexpr int ASZ = BM*64;         // one operand tile (BM rows x 32 k x 2B)
    constexpr int BUF = 4*ASZ;         // hi/lo A + hi/lo B per stage
    extern __shared__ char smem[];
    const uint32_t sb = smem_to_u32(smem);
    const int tid  = threadIdx.x;
    const int lane = tid & 31;
    const int wm   = (tid >> 5) & 1;
    const int wn   = (tid >> 5) >> 1;
    const int m0 = g.mskip + blockIdx.y * BM;
    const int n0 = blockIdx.x * BN;
    const int bz = blockIdx.z;
    const int NC = g.K / 32;

    const bf16 *Ah = g.Ah + bz*g.zA,  *Al = g.Al + bz*g.zA;
    const bf16 *Ah2 = g.Ah2 + bz*g.zA, *Al2 = g.Al2 + bz*g.zA;
    const bf16 *Bh = g.Bh + bz*g.zB,  *Bl = g.Bl + bz*g.zB;

    // A frag addressing (paired-row layout)
    int aBase[MF], aPo[MF], aXm[MF];
#pragma unroll
    for (int mf = 0; mf < MF; mf++) {
        int r = wm * (BM/2) + mf * 16 + (lane & 15);
        aBase[mf] = (r >> 1) * 128;
        aPo[mf]   = (r & 1) * 64;
        aXm[mf]   = ((r >> 1) & 7) << 4;
    }
    const int aKb = (lane >> 4) * 16;
    int bBase[NB], bPo[NB], bXm[NB];
#pragma unroll
    for (int nb = 0; nb < NB; nb++) {
        int r = wn * (BN/4) + nb * 16 + ((lane >> 4) << 3) + (lane & 7);
        bBase[nb] = (r >> 1) * 128;
        bPo[nb]   = (r & 1) * 64;
        bXm[nb]   = ((r >> 1) & 7) << 4;
    }
    const int bKb = ((lane >> 3) & 1) * 16;

    float acc[MF][NF][4];
#pragma unroll
    for (int i = 0; i < MF; i++)
#pragma unroll
        for (int j = 0; j < NF; j++)
#pragma unroll
            for (int t = 0; t < 4; t++) acc[i][j][t] = 0.f;

    auto loadChunk = [&](int c) {
        const long cofs = (long)c * 32;
        const int st = c % 3;
        const bf16* AHc = Ah; const bf16* ALc = Al;
        long acol = cofs;
        if (cofs >= g.K1) { AHc = Ah2; ALc = Al2; acol = cofs - g.K1; }
        constexpr int TV = BM * 4;      // 16B vectors per tile
#pragma unroll
        for (int t = 0; t < (4*TV)/256; t++) {
            int u = tid + t * 256;
            int tile = u / TV;
            int w = u % TV;
            int row = w >> 2;
            int seg = w & 3;
            const bf16* gp;
            if      (tile == 0) gp = AHc + (long)(m0 + row) * g.lda + acol;
            else if (tile == 1) gp = ALc + (long)(m0 + row) * g.lda + acol;
            else if (tile == 2) gp = Bh + (long)(n0 + row) * g.ldb + cofs;
            else                gp = Bl + (long)(n0 + row) * g.ldb + cofs;
            gp += seg * 8;
            int j = row >> 1, p = row & 1;
            uint32_t so = sb + st * BUF + tile * ASZ + j * 128
                        + ((p * 64 + seg * 16) ^ ((j & 7) << 4));
            cp_async16(so, gp);
        }
        CP_COMMIT();
    };

    loadChunk(0);
    if (NC > 1) loadChunk(1);

    for (int c = 0; c < NC; c++) {
        if (c + 2 < NC) { loadChunk(c + 2); CP_WAIT(2); }
        else if (c + 1 < NC) CP_WAIT(1);
        else CP_WAIT(0);
        __syncthreads();

        const uint32_t bufB = sb + (c % 3) * BUF;
#pragma unroll
        for (int ks = 0; ks < 2; ks++) {
            uint32_t afH[MF][4], afL[MF][4], bfH[NB][4], bfL[NB][4];
#pragma unroll
            for (int mf = 0; mf < MF; mf++) {
                uint32_t off = aBase[mf] + ((aPo[mf] + ks * 32 + aKb) ^ aXm[mf]);
                ldsm4(afH[mf], bufB + off);
                ldsm4(afL[mf], bufB + ASZ + off);
            }
#pragma unroll
            for (int nb = 0; nb < NB; nb++) {
                uint32_t off = bBase[nb] + ((bPo[nb] + ks * 32 + bKb) ^ bXm[nb]);
                ldsm4(bfH[nb], bufB + 2*ASZ + off);
                ldsm4(bfL[nb], bufB + 3*ASZ + off);
            }
#pragma unroll
            for (int mf = 0; mf < MF; mf++)
#pragma unroll
                for (int nf = 0; nf < NF; nf++)
                    mma16816(acc[mf][nf], afH[mf], bfH[nf>>1][(nf&1)*2], bfH[nf>>1][(nf&1)*2+1]);
#pragma unroll
            for (int mf = 0; mf < MF; mf++)
#pragma unroll
                for (int nf = 0; nf < NF; nf++)
                    mma16816(acc[mf][nf], afH[mf], bfL[nf>>1][(nf&1)*2], bfL[nf>>1][(nf&1)*2+1]);
#pragma unroll
            for (int mf = 0; mf < MF; mf++)
#pragma unroll
                for (int nf = 0; nf < NF; nf++)
                    mma16816(acc[mf][nf], afL[mf], bfH[nf>>1][(nf&1)*2], bfH[nf>>1][(nf&1)*2+1]);
        }
        __syncthreads();
    }

    // ---- epilogue ----
    float* outF = e.outF ? e.outF + bz*e.zOut : (float*)0;
    bf16*  outH = e.outH ? e.outH + bz*e.zOut : (bf16*)0;
    bf16*  outL = e.outL ? e.outL + bz*e.zOut : (bf16*)0;
    const float* add = e.add ? e.add + bz*e.zAdd : (const float*)0;
    const int rl = lane >> 2;
    const int cl = (lane & 3) * 2;
#pragma unroll
    for (int mf = 0; mf < MF; mf++) {
#pragma unroll
        for (int nf = 0; nf < NF; nf++) {
            int c0 = n0 + wn * (BN/4) + nf * 8 + cl;
#pragma unroll
            for (int half = 0; half < 2; half++) {
                int row = m0 + wm * (BM/2) + mf * 16 + rl + half * 8;
                long ofs = (long)row * g.N + c0;
                float f0 = e.alpha * acc[mf][nf][half*2];
                float f1 = e.alpha * acc[mf][nf][half*2 + 1];
                if (add) {
                    float2 ra = *(const float2*)(add + ofs);
                    f0 += e.beta * ra.x; f1 += e.beta * ra.y;
                }
                if (e.diag != 0.f) {
                    if (row == c0)     f0 += e.diag;
                    if (row == c0 + 1) f1 += e.diag;
                }
                if (e.gelu) {
                    f0 = 0.5f * f0 * (1.f + erff(f0 * 0.70710678118654752f));
                    f1 = 0.5f * f1 * (1.f + erff(f1 * 0.70710678118654752f));
                }
                if (outF)
                    *(float2*)(outF + ofs) = make_float2(f0, f1);
                if (outH) {
                    bf16 h0, h1, l0, l1;
                    split2(f0, h0, l0);
                    split2(f1, h1, l1);
                    *(uint32_t*)(outH + ofs) = pk2(h0, h1);
                    *(uint32_t*)(outL + ofs) = pk2(l0, l1);
                }
            }
        }
    }
}

// ---------------- elementwise / reduction kernels ----------------
__global__ void ln_kernel(const float* __restrict__ x, const float* __restrict__ w,
                          bf16* __restrict__ oh, bf16* __restrict__ ol)
{
    const int r = blockIdx.x, tid = threadIdx.x;
    float4 f = ((const float4*)(x + (long)r*Cv))[tid];
    float s = f.x+f.y+f.z+f.w;
    float q = f.x*f.x+f.y*f.y+f.z*f.z+f.w*f.w;
    __shared__ float shs[4], shq[4];
#pragma unroll
    for (int off=16; off>0; off>>=1) {
        s += __shfl_down_sync(0xffffffffu, s, off);
        q += __shfl_down_sync(0xffffffffu, q, off);
    }
    if ((tid&31)==0) { shs[tid>>5]=s; shq[tid>>5]=q; }
    __syncthreads();
    float S = shs[0]+shs[1]+shs[2]+shs[3];
    float Q = shq[0]+shq[1]+shq[2]+shq[3];
    float mean = S*(1.f/Cv);
    float var  = Q*(1.f/Cv) - mean*mean;
    float inv  = rsqrtf(var + 1e-5f);
    float4 wf = ((const float4*)w)[tid];
    float o0=(f.x-mean)*inv*wf.x, o1=(f.y-mean)*inv*wf.y;
    float o2=(f.z-mean)*inv*wf.z, o3=(f.w-mean)*inv*wf.w;
    bf16 h0,h1,h2,h3,l0,l1,l2,l3;
    split2(o0,h0,l0); split2(o1,h1,l1); split2(o2,h2,l2); split2(o3,h3,l3);
    long ofs = (long)r*Cv + tid*4;
    uint2 uh; uh.x=pk2(h0,h1); uh.y=pk2(h2,h3);
    uint2 ul; ul.x=pk2(l0,l1); ul.y=pk2(l2,l3);
    *(uint2*)(oh+ofs)=uh; *(uint2*)(ol+ofs)=ul;
}

// in-place scan combine: q[t] <- rms(z[t]) for t >= d. grid (Tv - mskip, Bv).
__global__ void pscan_combine(const float* __restrict__ z,
                              bf16* __restrict__ qH, bf16* __restrict__ qL,
                              int d, int mskip)
{
    const int t = mskip + blockIdx.x;
    if (t < d) return;
    const int r = blockIdx.y * Tv + t;
    const int tid = threadIdx.x;
    long ofs = (long)r*Cv + tid*4;
    float4 f = *(const float4*)(z+ofs);
    float q = f.x*f.x+f.y*f.y+f.z*f.z+f.w*f.w;
    __shared__ float shq[4];
#pragma unroll
    for (int off=16; off>0; off>>=1) q += __shfl_down_sync(0xffffffffu, q, off);
    if ((tid&31)==0) shq[tid>>5]=q;
    __syncthreads();
    float Q = shq[0]+shq[1]+shq[2]+shq[3];
    float sc = rsqrtf(Q*(1.f/Cv) + 1e-6f);
    float o0=f.x*sc, o1=f.y*sc, o2=f.z*sc, o3=f.w*sc;
    bf16 h0,h1,h2,h3,l0,l1,l2,l3;
    split2(o0,h0,l0); split2(o1,h1,l1); split2(o2,h2,l2); split2(o3,h3,l3);
    uint2 uh; uh.x=pk2(h0,h1); uh.y=pk2(h2,h3);
    uint2 ul; ul.x=pk2(l0,l1); ul.y=pk2(l2,l3);
    *(uint2*)(qH+ofs)=uh; *(uint2*)(qL+ofs)=ul;
}

// h = split(q * v) with q,v reconstructed from bf16 pairs
__global__ void mul_split(const bf16* __restrict__ qH, const bf16* __restrict__ qL,
                          const bf16* __restrict__ vH, const bf16* __restrict__ vL,
                          bf16* __restrict__ H, bf16* __restrict__ L)
{
    long i = ((long)blockIdx.x*256 + threadIdx.x)*4;
    uint2 a = *(const uint2*)(qH+i), b = *(const uint2*)(qL+i);
    uint2 c = *(const uint2*)(vH+i), d = *(const uint2*)(vL+i);
    float q0,q1,q2,q3,ql0,ql1,ql2,ql3,v0,v1,v2,v3,vl0,vl1,vl2,vl3;
    up2(a.x,q0,q1); up2(a.y,q2,q3); up2(b.x,ql0,ql1); up2(b.y,ql2,ql3);
    up2(c.x,v0,v1); up2(c.y,v2,v3); up2(d.x,vl0,vl1); up2(d.y,vl2,vl3);
    float o0=(q0+ql0)*(v0+vl0), o1=(q1+ql1)*(v1+vl1);
    float o2=(q2+ql2)*(v2+vl2), o3=(q3+ql3)*(v3+vl3);
    bf16 h0,h1,h2,h3,l0,l1,l2,l3;
    split2(o0,h0,l0); split2(o1,h1,l1); split2(o2,h2,l2); split2(o3,h3,l3);
    uint2 uh; uh.x=pk2(h0,h1); uh.y=pk2(h2,h3);
    uint2 ul; ul.x=pk2(l0,l1); ul.y=pk2(l2,l3);
    *(uint2*)(H+i)=uh; *(uint2*)(L+i)=ul;
}

// all five weight splits in one launch
__global__ void wsplit5(const float* __restrict__ Wq, const float* __restrict__ Wv,
                        const float* __restrict__ Wo, const float* __restrict__ Wfc,
                        const float* __restrict__ Wpr,
                        bf16* WqH, bf16* WqL, bf16* WvH, bf16* WvL,
                        bf16* WoH, bf16* WoL, bf16* WfcH, bf16* WfcL,
                        bf16* WprH, bf16* WprL)
{
    const int S = Cv*Cv;
    long i = (long)blockIdx.x*256 + threadIdx.x;   // over 11*S
    const float* W; bf16 *H, *L; long j;
    if      (i < S)       { W=Wq;  H=WqH;  L=WqL;  j=i; }
    else if (i < 2L*S)    { W=Wv;  H=WvH;  L=WvL;  j=i-S; }
    else if (i < 3L*S)    { W=Wo;  H=WoH;  L=WoL;  j=i-2L*S; }
    else if (i < 7L*S)    { W=Wfc; H=WfcH; L=WfcL; j=i-3L*S; }
    else                  { W=Wpr; H=WprH; L=WprL; j=i-7L*S; }
    float x = W[j];
    bf16 h, l; split2(x, h, l);
    H[j] = h; L[j] = l;
}

__global__ void frob1(const float* __restrict__ W1, const float* __restrict__ W2,
                      float* __restrict__ part)
{
    const int row = blockIdx.x, mat = blockIdx.y, tid = threadIdx.x;
    const float* W = mat ? W2 : W1;
    float4 f = ((const float4*)(W + (long)row*Cv))[tid];
    float q = f.x*f.x+f.y*f.y+f.z*f.z+f.w*f.w;
    __shared__ float shq[4];
#pragma unroll
    for (int off=16; off>0; off>>=1) q += __shfl_down_sync(0xffffffffu, q, off);
    if ((tid&31)==0) shq[tid>>5]=q;
    __syncthreads();
    if (tid==0) part[mat*Cv + row] = shq[0]+shq[1]+shq[2]+shq[3];
}

__global__ void frob2(const float* __restrict__ part, float* __restrict__ rn)
{
    const int mat = blockIdx.x, tid = threadIdx.x;
    __shared__ float sh[256];
    sh[tid] = part[mat*Cv + tid] + part[mat*Cv + tid + 256];
    __syncthreads();
    for (int off=128; off>0; off>>=1) {
        if (tid<off) sh[tid] += sh[tid+off];
        __syncthreads();
    }
    if (tid==0) rn[mat] = rsqrtf(sh[0]);
}

// X = W * rn, split to H/L, plus transposed copies. grid (16,16,2), block (32,8).
__global__ void split_tr_init(const float* __restrict__ W1, const float* __restrict__ W2,
                              const float* __restrict__ rn,
                              bf16* XH, bf16* XL, bf16* XtH, bf16* XtL)
{
    __shared__ float t[32][33];
    const int mat = blockIdx.z;
    const float* W = mat ? W2 : W1;
    const float s = rn[mat];
    const int r0 = blockIdx.y*32, c0 = blockIdx.x*32;
    const int tx = threadIdx.x, ty = threadIdx.y;
    const long mo = (long)mat*Sm;
#pragma unroll
    for (int i = 0; i < 4; i++) {
        int rr = ty + i*8;
        t[rr][tx] = W[(long)(r0+rr)*Cv + c0+tx] * s;
    }
    __syncthreads();
#pragma unroll
    for (int i = 0; i < 4; i++) {
        int rr = ty + i*8;
        bf16 h, l;
        split2(t[rr][tx], h, l);
        XH[mo + (long)(r0+rr)*Cv + c0+tx] = h;
        XL[mo + (long)(r0+rr)*Cv + c0+tx] = l;
        split2(t[tx][rr], h, l);
        XtH[mo + (long)(c0+rr)*Cv + r0+tx] = h;
        XtL[mo + (long)(c0+rr)*Cv + r0+tx] = l;
    }
}

// bf16 pair transpose: Xt = X^T. grid (16,16,2), block (32,8).
__global__ void tr_pair(const bf16* __restrict__ XH, const bf16* __restrict__ XL,
                        bf16* __restrict__ XtH, bf16* __restrict__ XtL)
{
    __shared__ bf16 th[32][34], tl[32][34];
    const int mat = blockIdx.z;
    const int r0 = blockIdx.y*32, c0 = blockIdx.x*32;
    const int tx = threadIdx.x, ty = threadIdx.y;
    const long mo = (long)mat*Sm;
#pragma unroll
    for (int i = 0; i < 4; i++) {
        int rr = ty + i*8;
        th[rr][tx] = XH[mo + (long)(r0+rr)*Cv + c0+tx];
        tl[rr][tx] = XL[mo + (long)(r0+rr)*Cv + c0+tx];
    }
    __syncthreads();
#pragma unroll
    for (int i = 0; i < 4; i++) {
        int rr = ty + i*8;
        XtH[mo + (long)(c0+rr)*Cv + r0+tx] = th[tx][rr];
        XtL[mo + (long)(c0+rr)*Cv + r0+tx] = tl[tx][rr];
    }
}

// Pc[n, 0:512] = P1[n,:], Pc[n, 512:1024] = P2[n,:]
__global__ void packP(const bf16* __restrict__ XH, const bf16* __restrict__ XL,
                      bf16* __restrict__ PcH, bf16* __restrict__ PcL)
{
    int idx = blockIdx.x*256 + threadIdx.x;     // over 512*1024
    int n = idx >> 10, k = idx & 1023;
    long src = (k < 512) ? ((long)n*Cv + k) : (Sm + (long)n*Cv + (k-512));
    PcH[idx] = XH[src];
    PcL[idx] = XL[src];
}

// ---------------- host ----------------
static inline GA mkga(const bf16* Ah, const bf16* Al, const bf16* Bh, const bf16* Bl,
                      int M, int N, int K, int lda, int ldb, long zA = 0, long zB = 0)
{
    GA g; g.Ah=Ah; g.Al=Al; g.Ah2=Ah; g.Al2=Al; g.Bh=Bh; g.Bl=Bl;
    g.M=M; g.N=N; g.K=K; g.K1=K; g.lda=lda; g.ldb=ldb; g.mskip=0; g.zA=zA; g.zB=zB;
    return g;
}
static inline TEpi te()
{
    TEpi e; e.alpha=1.f; e.beta=1.f; e.diag=0.f; e.add=0; e.zAdd=0;
    e.gelu=0; e.outF=0; e.outH=0; e.outL=0; e.zOut=0;
    return e;
}

#define SM128 (3*4*128*64)
#define SM64  (3*4*64*64)

extern "C" void kernel_launch(void* const* d_in, const int* in_sizes, int n_in,
                              void* d_out, int out_size)
{
    const float* x   = (const float*)d_in[0];
    const float* ln1 = (const float*)d_in[1];
    const float* Wq  = (const float*)d_in[2];
    const float* Wv  = (const float*)d_in[3];
    const float* Wo  = (const float*)d_in[4];
    // d_in[5] = identity : mathematically unused (rows computed from it are discarded)
    const float* Wp1 = (const float*)d_in[6];
    const float* Wp2 = (const float*)d_in[7];
    const float* ln2 = (const float*)d_in[8];
    const float* Wfc = (const float*)d_in[9];
    const float* Wpr = (const float*)d_in[10];
    float* out = (float*)d_out;

    cudaFuncSetAttribute(mma_gemm<128,128>, cudaFuncAttributeMaxDynamicSharedMemorySize, SM128);
    cudaFuncSetAttribute(mma_gemm<64,64>,   cudaFuncAttributeMaxDynamicSharedMemorySize, SM64);

    bf16 *qH,*qL,*vH,*vL,*hH,*hL,*fcH,*fcL;
    bf16 *WqH,*WqL,*WvH,*WvL,*WoH,*WoL,*WfcH,*WfcL,*WprH,*WprL;
    bf16 *XaH,*XaL,*XbH,*XbL,*XtH,*XtL,*YH,*YL,*MH,*ML,*PcH,*PcL;
    float *z,*YF,*part,*rn;
    cudaGetSymbolAddress((void**)&qH, g_qH);   cudaGetSymbolAddress((void**)&qL, g_qL);
    cudaGetSymbolAddress((void**)&vH, g_vH);   cudaGetSymbolAddress((void**)&vL, g_vL);
    cudaGetSymbolAddress((void**)&hH, g_hH);   cudaGetSymbolAddress((void**)&hL, g_hL);
    cudaGetSymbolAddress((void**)&fcH, g_fcH); cudaGetSymbolAddress((void**)&fcL, g_fcL);
    cudaGetSymbolAddress((void**)&WqH, g_WqH); cudaGetSymbolAddress((void**)&WqL, g_WqL);
    cudaGetSymbolAddress((void**)&WvH, g_WvH); cudaGetSymbolAddress((void**)&WvL, g_WvL);
    cudaGetSymbolAddress((void**)&WoH, g_WoH); cudaGetSymbolAddress((void**)&WoL, g_WoL);
    cudaGetSymbolAddress((void**)&WfcH,g_WfcH); cudaGetSymbolAddress((void**)&WfcL,g_WfcL);
    cudaGetSymbolAddress((void**)&WprH,g_WprH); cudaGetSymbolAddress((void**)&WprL,g_WprL);
    cudaGetSymbolAddress((void**)&XaH, g_XaH); cudaGetSymbolAddress((void**)&XaL, g_XaL);
    cudaGetSymbolAddress((void**)&XbH, g_XbH); cudaGetSymbolAddress((void**)&XbL, g_XbL);
    cudaGetSymbolAddress((void**)&XtH, g_XtH); cudaGetSymbolAddress((void**)&XtL, g_XtL);
    cudaGetSymbolAddress((void**)&YH,  g_YH);  cudaGetSymbolAddress((void**)&YL,  g_YL);
    cudaGetSymbolAddress((void**)&MH,  g_MH);  cudaGetSymbolAddress((void**)&ML,  g_ML);
    cudaGetSymbolAddress((void**)&PcH, g_PcH); cudaGetSymbolAddress((void**)&PcL, g_PcL);
    cudaGetSymbolAddress((void**)&z,   g_z);
    cudaGetSymbolAddress((void**)&YF,  g_YF);
    cudaGetSymbolAddress((void**)&part,g_part);
    cudaGetSymbolAddress((void**)&rn,  g_rn);

    // ---- weight splits (single launch) ----
    wsplit5<<<(11*Cv*Cv)/256,256>>>(Wq, Wv, Wo, Wfc, Wpr,
        WqH, WqL, WvH, WvL, WoH, WoL, WfcH, WfcL, WprH, WprL);

    // ---- polar factors via Muon-quintic + Newton-Schulz on tensor cores ----
    frob1<<<dim3(Cv,2),128>>>(Wp1, Wp2, part);
    frob2<<<2,256>>>(part, rn);
    split_tr_init<<<dim3(16,16,2),dim3(32,8)>>>(Wp1, Wp2, rn, XaH, XaL, XtH, XtL);

    const dim3 gp(8, 8, 2);
    const dim3 gt(16, 16, 2);
    const dim3 bt(32, 8);
    for (int it = 0; it < 9; ++it) {
        // Y = Xt @ Xt^T  (= X^T X, symmetric)
        GA g1 = mkga(XtH, XtL, XtH, XtL, Cv, Cv, Cv, Cv, Cv, Sm, Sm);
        TEpi e1 = te(); e1.outF = YF; e1.outH = YH; e1.outL = YL; e1.zOut = Sm;
        mma_gemm<64,64><<<gp,256,SM64>>>(g1, e1);
        // M = 2.0315*Y@Y^T - 4.7750*Y + 3.4445*I  (symmetric)
        GA g2 = mkga(YH, YL, YH, YL, Cv, Cv, Cv, Cv, Cv, Sm, Sm);
        TEpi e2 = te(); e2.alpha = 2.0315f; e2.add = YF; e2.zAdd = Sm;
        e2.beta = -4.7750f; e2.diag = 3.4445f; e2.outH = MH; e2.outL = ML; e2.zOut = Sm;
        mma_gemm<64,64><<<gp,256,SM64>>>(g2, e2);
        // X' = X @ M^T (= X M, M symmetric)
        GA g3 = mkga(XaH, XaL, MH, ML, Cv, Cv, Cv, Cv, Cv, Sm, Sm);
        TEpi e3 = te(); e3.outH = XbH; e3.outL = XbL; e3.zOut = Sm;
        mma_gemm<64,64><<<gp,256,SM64>>>(g3, e3);
        tr_pair<<<gt,bt>>>(XbH, XbL, XtH, XtL);
        bf16* t;
        t = XaH; XaH = XbH; XbH = t;
        t = XaL; XaL = XbL; XbL = t;
    }
    for (int it = 0; it < 5; ++it) {
        // G = -0.5*Xt@Xt^T + 1.5I  (symmetric)
        GA g1 = mkga(XtH, XtL, XtH, XtL, Cv, Cv, Cv, Cv, Cv, Sm, Sm);
        TEpi e1 = te(); e1.alpha = -0.5f; e1.diag = 1.5f;
        e1.outH = MH; e1.outL = ML; e1.zOut = Sm;
        mma_gemm<64,64><<<gp,256,SM64>>>(g1, e1);
        // X' = X @ G^T
        GA g2 = mkga(XaH, XaL, MH, ML, Cv, Cv, Cv, Cv, Cv, Sm, Sm);
        TEpi e2 = te(); e2.outH = XbH; e2.outL = XbL; e2.zOut = Sm;
        mma_gemm<64,64><<<gp,256,SM64>>>(g2, e2);
        if (it + 1 < 5) tr_pair<<<gt,bt>>>(XbH, XbL, XtH, XtL);
        bf16* t;
        t = XaH; XaH = XbH; XbH = t;
        t = XaL; XaL = XbL; XbL = t;
    }
    packP<<<(Cv*2*Cv)/256,256>>>(XaH, XaL, PcH, PcL);

    // ---- SSM branch ----
    ln_kernel<<<Rv,128>>>(x, ln1, hH, hL);
    {
        GA gq = mkga(hH, hL, WqH, WqL, Rv, Cv, Cv, Cv, Cv);
        TEpi eq = te(); eq.outH = qH + GUARDE; eq.outL = qL + GUARDE;
        mma_gemm<128,128><<<dim3(Cv/128, Rv/128), 256, SM128>>>(gq, eq);
        GA gv = mkga(hH, hL, WvH, WvL, Rv, Cv, Cv, Cv, Cv);
        TEpi ev = te(); ev.outH = vH; ev.outL = vL;
        mma_gemm<128,128><<<dim3(Cv/128, Rv/128), 256, SM128>>>(gv, ev);
    }

    for (int d = 1; d < Tv; d <<= 1) {
        const int mskip = d & ~127;          // whole 128-row tiles with t<d skipped
        // z = qshift @ P1^T + q @ P2^T : single GEMM, K=1024
        // chunks k<512 read q[t-d] (guard zeros / stale rows, discarded), k>=512 read q[t]
        GA gs = mkga(qH + GUARDE, qL + GUARDE, PcH, PcL, Rv, Cv, 2*Cv, Cv, 2*Cv);
        gs.Ah = qH + GUARDE - (long)d*Cv;
        gs.Al = qL + GUARDE - (long)d*Cv;
        gs.K1 = Cv;
        gs.mskip = mskip;
        gs.zA = (long)Tv*Cv;                  // batch stride (rows)
        TEpi es = te(); es.outF = z; es.zOut = (long)Tv*Cv;
        mma_gemm<128,128><<<dim3(Cv/128, (Tv-mskip)/128, Bv), 256, SM128>>>(gs, es);
        pscan_combine<<<dim3(Tv-mskip, Bv),128>>>(z, qH + GUARDE, qL + GUARDE, d, mskip);
    }

    // x1 = x + (q*v) @ Wo^T   (into d_out)
    mul_split<<<(Rv*Cv/4)/256,256>>>(qH + GUARDE, qL + GUARDE, vH, vL, hH, hL);
    {
        GA go = mkga(hH, hL, WoH, WoL, Rv, Cv, Cv, Cv, Cv);
        TEpi er = te(); er.add = x; er.outF = out;
        mma_gemm<128,128><<<dim3(Cv/128, Rv/128), 256, SM128>>>(go, er);
    }

    // ---- MLP branch ----
    ln_kernel<<<Rv,128>>>(out, ln2, hH, hL);
    {
        GA gf = mkga(hH, hL, WfcH, WfcL, Rv, Fv, Cv, Cv, Cv);
        TEpi eg = te(); eg.gelu = 1; eg.outH = fcH; eg.outL = fcL;
        mma_gemm<128,128><<<dim3(Fv/128, Rv/128), 256, SM128>>>(gf, eg);
        GA gr = mkga(fcH, fcL, WprH, WprL, Rv, Cv, Fv, Fv, Fv);
        TEpi er2 = te(); er2.add = out; er2.outF = out;
        mma_gemm<128,128><<<dim3(Cv/128, Rv/128), 256, SM128>>>(gr, er2);
    }
}

// round 8
// speedup vs baseline: 3.1958x; 1.0150x over previous
#include <cuda_runtime.h>
#include <cuda_bf16.h>
#include <math.h>
#include <stdint.h>

#define Bv 4
#define Tv 4096
#define Cv 512
#define Rv (Bv*Tv)            // 16384 rows
#define Fv (4*Cv)             // 2048
#define GUARDE (2048*Cv)      // guard rows (zero-init) for shifted scan operand
#define Sm ((long)Cv*Cv)

typedef __nv_bfloat16 bf16;

// ---------------- static device scratch (zero-initialized) ----------------
__device__ bf16 g_qH[GUARDE + Rv*Cv];
__device__ bf16 g_qL[GUARDE + Rv*Cv];
__device__ bf16 g_vH[Rv*Cv], g_vL[Rv*Cv];
__device__ float g_z[Rv*Cv];
__device__ bf16 g_hH[Rv*Cv], g_hL[Rv*Cv];
__device__ bf16 g_fcH[Rv*Fv], g_fcL[Rv*Fv];
// weight splits
__device__ bf16 g_WqH[Cv*Cv], g_WqL[Cv*Cv];
__device__ bf16 g_WvH[Cv*Cv], g_WvL[Cv*Cv];
__device__ bf16 g_WoH[Cv*Cv], g_WoL[Cv*Cv];
__device__ bf16 g_WfcH[Fv*Cv], g_WfcL[Fv*Cv];
__device__ bf16 g_WprH[Cv*Fv], g_WprL[Cv*Fv];
// polar scratch (x2 matrices, batched)
__device__ bf16 g_XaH[2*Cv*Cv], g_XaL[2*Cv*Cv];
__device__ bf16 g_XbH[2*Cv*Cv], g_XbL[2*Cv*Cv];
__device__ bf16 g_XtH[2*Cv*Cv], g_XtL[2*Cv*Cv];
__device__ bf16 g_YH [2*Cv*Cv], g_YL [2*Cv*Cv];
__device__ bf16 g_MH [2*Cv*Cv], g_ML [2*Cv*Cv];
__device__ float g_YF[2*Cv*Cv];
__device__ bf16 g_PcH[Cv*2*Cv], g_PcL[Cv*2*Cv];   // [P1||P2] along K (512 x 1024)
__device__ float g_part[2*Cv];
__device__ float g_rn[2];

// ================= helpers =================
__device__ __forceinline__ uint32_t smem_to_u32(const void* p) {
    uint32_t a;
    asm("{ .reg .u64 t; cvta.to.shared.u64 t, %1; cvt.u32.u64 %0, t; }" : "=r"(a) : "l"(p));
    return a;
}
__device__ __forceinline__ void split2(float x, bf16& h, bf16& l) {
    h = __float2bfloat16(x);
    l = __float2bfloat16(x - __bfloat162float(h));
}
__device__ __forceinline__ uint32_t pk2(bf16 a, bf16 b) {
    __nv_bfloat162 t; t.x = a; t.y = b;
    return *(uint32_t*)&t;
}
__device__ __forceinline__ void up2(uint32_t u, float& a, float& b) {
    __nv_bfloat162 t = *(__nv_bfloat162*)&u;
    a = __bfloat162float(t.x); b = __bfloat162float(t.y);
}
__device__ __forceinline__ void ldsm4(uint32_t (&r)[4], uint32_t addr) {
    asm volatile("ldmatrix.sync.aligned.m8n8.x4.shared.b16 {%0,%1,%2,%3}, [%4];"
        : "=r"(r[0]), "=r"(r[1]), "=r"(r[2]), "=r"(r[3]) : "r"(addr));
}
__device__ __forceinline__ void mma16816(float (&d)[4], const uint32_t (&a)[4],
                                         uint32_t b0, uint32_t b1) {
    asm volatile("mma.sync.aligned.m16n8k16.row.col.f32.bf16.bf16.f32 "
        "{%0,%1,%2,%3}, {%4,%5,%6,%7}, {%8,%9}, {%0,%1,%2,%3};"
        : "+f"(d[0]), "+f"(d[1]), "+f"(d[2]), "+f"(d[3])
        : "r"(a[0]), "r"(a[1]), "r"(a[2]), "r"(a[3]), "r"(b0), "r"(b1));
}
__device__ __forceinline__ void cp_async16(uint32_t so, const void* gp) {
    asm volatile("cp.async.cg.shared.global [%0], [%1], 16;" :: "r"(so), "l"(gp) : "memory");
}
#define CP_COMMIT() asm volatile("cp.async.commit_group;" ::: "memory")
#define CP_WAIT(n)  asm volatile("cp.async.wait_group %0;" :: "n"(n) : "memory")

// ================= mma.sync split-bf16 GEMM: C = alpha*A@B^T (+beta*add +diag*I) =====
// A: [M,K] bf16 hi/lo (K ranges split across Ah(k<K1)/Ah2(k>=K1), pitch lda).
// B: [N,K] bf16 hi/lo, pitch ldb. 3 passes hh+lh+hl interleaved with ldsm to
// keep live fragments <= 40 regs (under the 128-reg cap at 2 CTAs/SM).
// CTA tile BMxBM, 8 warps (2x4). K-chunk 32, 3-stage cp.async pipeline,
// paired-row smem layout (two 64B k-rows per 128B line, XOR-16 swizzle).
// grid.z batches: A/B/out/add advance by zA/zB/zOut/zAdd; rows offset by mskip.
// Optional transposed output (outTH/outTL) staged through smem (for polar Xt).
struct GA {
    const bf16 *Ah, *Al, *Ah2, *Al2, *Bh, *Bl;
    int M, N, K, K1, lda, ldb, mskip;
    long zA, zB;
};
struct TEpi {
    float alpha, beta, diag;
    const float* add; long zAdd;
    int gelu;
    float* outF; bf16 *outH, *outL; long zOut;
    bf16 *outTH, *outTL;     // transposed bf16 split output (square, pitch N)
};

template<int BM, int BN>
__global__ __launch_bounds__(256, 2)
void mma_gemm(GA g, TEpi e)
{
    static_assert(BM == BN, "square tiles only");
    constexpr int MF = BM/32, NF = BN/32, NB = NF/2;
    constexpr int ASZ = BM*64;         // one operand tile (BM rows x 32 k x 2B)
    constexpr int BUF = 4*ASZ;         // hi/lo A + hi/lo B per stage
    extern __shared__ char smem[];
    const uint32_t sb = smem_to_u32(smem);
    const int tid  = threadIdx.x;
    const int lane = tid & 31;
    const int wm   = (tid >> 5) & 1;
    const int wn   = (tid >> 5) >> 1;
    const int m0 = g.mskip + blockIdx.y * BM;
    const int n0 = blockIdx.x * BN;
    const int bz = blockIdx.z;
    const int NC = g.K / 32;

    const bf16 *Ah = g.Ah + bz*g.zA,  *Al = g.Al + bz*g.zA;
    const bf16 *Ah2 = g.Ah2 + bz*g.zA, *Al2 = g.Al2 + bz*g.zA;
    const bf16 *Bh = g.Bh + bz*g.zB,  *Bl = g.Bl + bz*g.zB;

    // precomputed per-(ks,frag) smem offsets within a stage buffer
    int aOff[2][MF], bOff[2][NB];
    {
        const int aKb = (lane >> 4) * 16;
#pragma unroll
        for (int mf = 0; mf < MF; mf++) {
            int r = wm * (BM/2) + mf * 16 + (lane & 15);
            int base = (r >> 1) * 128, po = (r & 1) * 64, xm = ((r >> 1) & 7) << 4;
#pragma unroll
            for (int ks = 0; ks < 2; ks++)
                aOff[ks][mf] = base + ((po + ks * 32 + aKb) ^ xm);
        }
        const int bKb = ((lane >> 3) & 1) * 16;
#pragma unroll
        for (int nb = 0; nb < NB; nb++) {
            int r = wn * (BN/4) + nb * 16 + ((lane >> 4) << 3) + (lane & 7);
            int base = (r >> 1) * 128, po = (r & 1) * 64, xm = ((r >> 1) & 7) << 4;
#pragma unroll
            for (int ks = 0; ks < 2; ks++)
                bOff[ks][nb] = base + ((po + ks * 32 + bKb) ^ xm);
        }
    }

    float acc[MF][NF][4];
#pragma unroll
    for (int i = 0; i < MF; i++)
#pragma unroll
        for (int j = 0; j < NF; j++)
#pragma unroll
            for (int t = 0; t < 4; t++) acc[i][j][t] = 0.f;

    auto loadChunk = [&](int c) {
        const long cofs = (long)c * 32;
        const int st = c % 3;
        const bf16* AHc = Ah; const bf16* ALc = Al;
        long acol = cofs;
        if (cofs >= g.K1) { AHc = Ah2; ALc = Al2; acol = cofs - g.K1; }
        constexpr int TV = BM * 4;      // 16B vectors per tile
#pragma unroll
        for (int t = 0; t < (4*TV)/256; t++) {
            int u = tid + t * 256;
            int tile = u / TV;
            int w = u % TV;
            int row = w >> 2;
            int seg = w & 3;
            const bf16* gp;
            if      (tile == 0) gp = AHc + (long)(m0 + row) * g.lda + acol;
            else if (tile == 1) gp = ALc + (long)(m0 + row) * g.lda + acol;
            else if (tile == 2) gp = Bh + (long)(n0 + row) * g.ldb + cofs;
            else                gp = Bl + (long)(n0 + row) * g.ldb + cofs;
            gp += seg * 8;
            int j = row >> 1, p = row & 1;
            uint32_t so = sb + st * BUF + tile * ASZ + j * 128
                        + ((p * 64 + seg * 16) ^ ((j & 7) << 4));
            cp_async16(so, gp);
        }
        CP_COMMIT();
    };

    loadChunk(0);
    if (NC > 1) loadChunk(1);

    for (int c = 0; c < NC; c++) {
        if (c + 2 < NC) { loadChunk(c + 2); CP_WAIT(2); }
        else if (c + 1 < NC) CP_WAIT(1);
        else CP_WAIT(0);
        __syncthreads();

        const uint32_t bufB = sb + (c % 3) * BUF;
#pragma unroll
        for (int ks = 0; ks < 2; ks++) {
            uint32_t afH[MF][4], bfH[NB][4];
#pragma unroll
            for (int mf = 0; mf < MF; mf++)
                ldsm4(afH[mf], bufB + aOff[ks][mf]);
#pragma unroll
            for (int nb = 0; nb < NB; nb++)
                ldsm4(bfH[nb], bufB + 2*ASZ + bOff[ks][nb]);
            // pass hh
#pragma unroll
            for (int mf = 0; mf < MF; mf++)
#pragma unroll
                for (int nf = 0; nf < NF; nf++)
                    mma16816(acc[mf][nf], afH[mf], bfH[nf>>1][(nf&1)*2], bfH[nf>>1][(nf&1)*2+1]);
            // pass lh (afL loaded now; bfH still live)
            {
                uint32_t afL[MF][4];
#pragma unroll
                for (int mf = 0; mf < MF; mf++)
                    ldsm4(afL[mf], bufB + ASZ + aOff[ks][mf]);
#pragma unroll
                for (int mf = 0; mf < MF; mf++)
#pragma unroll
                    for (int nf = 0; nf < NF; nf++)
                        mma16816(acc[mf][nf], afL[mf], bfH[nf>>1][(nf&1)*2], bfH[nf>>1][(nf&1)*2+1]);
            }
            // pass hl (bfL loaded now; afH still live, afL/bfH dead)
            {
                uint32_t bfL[NB][4];
#pragma unroll
                for (int nb = 0; nb < NB; nb++)
                    ldsm4(bfL[nb], bufB + 3*ASZ + bOff[ks][nb]);
#pragma unroll
                for (int mf = 0; mf < MF; mf++)
#pragma unroll
                    for (int nf = 0; nf < NF; nf++)
                        mma16816(acc[mf][nf], afH[mf], bfL[nf>>1][(nf&1)*2], bfL[nf>>1][(nf&1)*2+1]);
            }
        }
        __syncthreads();
    }

    // ---- epilogue ----
    float* outF = e.outF ? e.outF + bz*e.zOut : (float*)0;
    bf16*  outH = e.outH ? e.outH + bz*e.zOut : (bf16*)0;
    bf16*  outL = e.outL ? e.outL + bz*e.zOut : (bf16*)0;
    const float* add = e.add ? e.add + bz*e.zAdd : (const float*)0;
    bf16* sH = (bf16*)smem;                    // transposed staging [BM][BN+1]
    bf16* sL = sH + BM*(BN+1);
    const int rl = lane >> 2;
    const int cl = (lane & 3) * 2;
#pragma unroll
    for (int mf = 0; mf < MF; mf++) {
#pragma unroll
        for (int nf = 0; nf < NF; nf++) {
            int lc = wn * (BN/4) + nf * 8 + cl;
            int c0 = n0 + lc;
#pragma unroll
            for (int half = 0; half < 2; half++) {
                int lr = wm * (BM/2) + mf * 16 + rl + half * 8;
                int row = m0 + lr;
                long ofs = (long)row * g.N + c0;
                float f0 = e.alpha * acc[mf][nf][half*2];
                float f1 = e.alpha * acc[mf][nf][half*2 + 1];
                if (add) {
                    float2 ra = *(const float2*)(add + ofs);
                    f0 += e.beta * ra.x; f1 += e.beta * ra.y;
                }
                if (e.diag != 0.f) {
                    if (row == c0)     f0 += e.diag;
                    if (row == c0 + 1) f1 += e.diag;
                }
                if (e.gelu) {
                    f0 = 0.5f * f0 * (1.f + erff(f0 * 0.70710678118654752f));
                    f1 = 0.5f * f1 * (1.f + erff(f1 * 0.70710678118654752f));
                }
                if (outF)
                    *(float2*)(outF + ofs) = make_float2(f0, f1);
                if (outH || e.outTH) {
                    bf16 h0, h1, l0, l1;
                    split2(f0, h0, l0);
                    split2(f1, h1, l1);
                    if (outH) {
                        *(uint32_t*)(outH + ofs) = pk2(h0, h1);
                        *(uint32_t*)(outL + ofs) = pk2(l0, l1);
                    }
                    if (e.outTH) {
                        sH[lr*(BN+1) + lc] = h0; sH[lr*(BN+1) + lc + 1] = h1;
                        sL[lr*(BN+1) + lc] = l0; sL[lr*(BN+1) + lc + 1] = l1;
                    }
                }
            }
        }
    }
    if (e.outTH) {
        __syncthreads();
        bf16* outTH = e.outTH + bz*e.zOut;
        bf16* outTL = e.outTL + bz*e.zOut;
#pragma unroll
        for (int it = 0; it < (BM*BN)/256; it++) {
            int idx = tid + it * 256;
            int j = idx / BM;        // col of X = row of Xt
            int i = idx % BM;        // row of X
            long o = (long)(n0 + j) * g.N + m0 + i;
            outTH[o] = sH[i*(BN+1) + j];
            outTL[o] = sL[i*(BN+1) + j];
        }
    }
}

// ---------------- elementwise / reduction kernels ----------------
__global__ void ln_kernel(const float* __restrict__ x, const float* __restrict__ w,
                          bf16* __restrict__ oh, bf16* __restrict__ ol)
{
    const int r = blockIdx.x, tid = threadIdx.x;
    float4 f = ((const float4*)(x + (long)r*Cv))[tid];
    float s = f.x+f.y+f.z+f.w;
    float q = f.x*f.x+f.y*f.y+f.z*f.z+f.w*f.w;
    __shared__ float shs[4], shq[4];
#pragma unroll
    for (int off=16; off>0; off>>=1) {
        s += __shfl_down_sync(0xffffffffu, s, off);
        q += __shfl_down_sync(0xffffffffu, q, off);
    }
    if ((tid&31)==0) { shs[tid>>5]=s; shq[tid>>5]=q; }
    __syncthreads();
    float S = shs[0]+shs[1]+shs[2]+shs[3];
    float Q = shq[0]+shq[1]+shq[2]+shq[3];
    float mean = S*(1.f/Cv);
    float var  = Q*(1.f/Cv) - mean*mean;
    float inv  = rsqrtf(var + 1e-5f);
    float4 wf = ((const float4*)w)[tid];
    float o0=(f.x-mean)*inv*wf.x, o1=(f.y-mean)*inv*wf.y;
    float o2=(f.z-mean)*inv*wf.z, o3=(f.w-mean)*inv*wf.w;
    bf16 h0,h1,h2,h3,l0,l1,l2,l3;
    split2(o0,h0,l0); split2(o1,h1,l1); split2(o2,h2,l2); split2(o3,h3,l3);
    long ofs = (long)r*Cv + tid*4;
    uint2 uh; uh.x=pk2(h0,h1); uh.y=pk2(h2,h3);
    uint2 ul; ul.x=pk2(l0,l1); ul.y=pk2(l2,l3);
    *(uint2*)(oh+ofs)=uh; *(uint2*)(ol+ofs)=ul;
}

// in-place scan combine: q[t] <- rms(z[t]) for t >= d. grid (Tv - mskip, Bv).
__global__ void pscan_combine(const float* __restrict__ z,
                              bf16* __restrict__ qH, bf16* __restrict__ qL,
                              int d, int mskip)
{
    const int t = mskip + blockIdx.x;
    if (t < d) return;
    const int r = blockIdx.y * Tv + t;
    const int tid = threadIdx.x;
    long ofs = (long)r*Cv + tid*4;
    float4 f = *(const float4*)(z+ofs);
    float q = f.x*f.x+f.y*f.y+f.z*f.z+f.w*f.w;
    __shared__ float shq[4];
#pragma unroll
    for (int off=16; off>0; off>>=1) q += __shfl_down_sync(0xffffffffu, q, off);
    if ((tid&31)==0) shq[tid>>5]=q;
    __syncthreads();
    float Q = shq[0]+shq[1]+shq[2]+shq[3];
    float sc = rsqrtf(Q*(1.f/Cv) + 1e-6f);
    float o0=f.x*sc, o1=f.y*sc, o2=f.z*sc, o3=f.w*sc;
    bf16 h0,h1,h2,h3,l0,l1,l2,l3;
    split2(o0,h0,l0); split2(o1,h1,l1); split2(o2,h2,l2); split2(o3,h3,l3);
    uint2 uh; uh.x=pk2(h0,h1); uh.y=pk2(h2,h3);
    uint2 ul; ul.x=pk2(l0,l1); ul.y=pk2(l2,l3);
    *(uint2*)(qH+ofs)=uh; *(uint2*)(qL+ofs)=ul;
}

// h = split(q * v) with q,v reconstructed from bf16 pairs
__global__ void mul_split(const bf16* __restrict__ qH, const bf16* __restrict__ qL,
                          const bf16* __restrict__ vH, const bf16* __restrict__ vL,
                          bf16* __restrict__ H, bf16* __restrict__ L)
{
    long i = ((long)blockIdx.x*256 + threadIdx.x)*4;
    uint2 a = *(const uint2*)(qH+i), b = *(const uint2*)(qL+i);
    uint2 c = *(const uint2*)(vH+i), d = *(const uint2*)(vL+i);
    float q0,q1,q2,q3,ql0,ql1,ql2,ql3,v0,v1,v2,v3,vl0,vl1,vl2,vl3;
    up2(a.x,q0,q1); up2(a.y,q2,q3); up2(b.x,ql0,ql1); up2(b.y,ql2,ql3);
    up2(c.x,v0,v1); up2(c.y,v2,v3); up2(d.x,vl0,vl1); up2(d.y,vl2,vl3);
    float o0=(q0+ql0)*(v0+vl0), o1=(q1+ql1)*(v1+vl1);
    float o2=(q2+ql2)*(v2+vl2), o3=(q3+ql3)*(v3+vl3);
    bf16 h0,h1,h2,h3,l0,l1,l2,l3;
    split2(o0,h0,l0); split2(o1,h1,l1); split2(o2,h2,l2); split2(o3,h3,l3);
    uint2 uh; uh.x=pk2(h0,h1); uh.y=pk2(h2,h3);
    uint2 ul; ul.x=pk2(l0,l1); ul.y=pk2(l2,l3);
    *(uint2*)(H+i)=uh; *(uint2*)(L+i)=ul;
}

// all five weight splits in one launch
__global__ void wsplit5(const float* __restrict__ Wq, const float* __restrict__ Wv,
                        const float* __restrict__ Wo, const float* __restrict__ Wfc,
                        const float* __restrict__ Wpr,
                        bf16* WqH, bf16* WqL, bf16* WvH, bf16* WvL,
                        bf16* WoH, bf16* WoL, bf16* WfcH, bf16* WfcL,
                        bf16* WprH, bf16* WprL)
{
    const int S = Cv*Cv;
    long i = (long)blockIdx.x*256 + threadIdx.x;   // over 11*S
    const float* W; bf16 *H, *L; long j;
    if      (i < S)       { W=Wq;  H=WqH;  L=WqL;  j=i; }
    else if (i < 2L*S)    { W=Wv;  H=WvH;  L=WvL;  j=i-S; }
    else if (i < 3L*S)    { W=Wo;  H=WoH;  L=WoL;  j=i-2L*S; }
    else if (i < 7L*S)    { W=Wfc; H=WfcH; L=WfcL; j=i-3L*S; }
    else                  { W=Wpr; H=WprH; L=WprL; j=i-7L*S; }
    float x = W[j];
    bf16 h, l; split2(x, h, l);
    H[j] = h; L[j] = l;
}

__global__ void frob1(const float* __restrict__ W1, const float* __restrict__ W2,
                      float* __restrict__ part)
{
    const int row = blockIdx.x, mat = blockIdx.y, tid = threadIdx.x;
    const float* W = mat ? W2 : W1;
    float4 f = ((const float4*)(W + (long)row*Cv))[tid];
    float q = f.x*f.x+f.y*f.y+f.z*f.z+f.w*f.w;
    __shared__ float shq[4];
#pragma unroll
    for (int off=16; off>0; off>>=1) q += __shfl_down_sync(0xffffffffu, q, off);
    if ((tid&31)==0) shq[tid>>5]=q;
    __syncthreads();
    if (tid==0) part[mat*Cv + row] = shq[0]+shq[1]+shq[2]+shq[3];
}

__global__ void frob2(const float* __restrict__ part, float* __restrict__ rn)
{
    const int mat = blockIdx.x, tid = threadIdx.x;
    __shared__ float sh[256];
    sh[tid] = part[mat*Cv + tid] + part[mat*Cv + tid + 256];
    __syncthreads();
    for (int off=128; off>0; off>>=1) {
        if (tid<off) sh[tid] += sh[tid+off];
        __syncthreads();
    }
    if (tid==0) rn[mat] = rsqrtf(sh[0]);
}

// X = W * rn, split to H/L, plus transposed copies. grid (16,16,2), block (32,8).
__global__ void split_tr_init(const float* __restrict__ W1, const float* __restrict__ W2,
                              const float* __restrict__ rn,
                              bf16* XH, bf16* XL, bf16* XtH, bf16* XtL)
{
    __shared__ float t[32][33];
    const int mat = blockIdx.z;
    const float* W = mat ? W2 : W1;
    const float s = rn[mat];
    const int r0 = blockIdx.y*32, c0 = blockIdx.x*32;
    const int tx = threadIdx.x, ty = threadIdx.y;
    const long mo = (long)mat*Sm;
#pragma unroll
    for (int i = 0; i < 4; i++) {
        int rr = ty + i*8;
        t[rr][tx] = W[(long)(r0+rr)*Cv + c0+tx] * s;
    }
    __syncthreads();
#pragma unroll
    for (int i = 0; i < 4; i++) {
        int rr = ty + i*8;
        bf16 h, l;
        split2(t[rr][tx], h, l);
        XH[mo + (long)(r0+rr)*Cv + c0+tx] = h;
        XL[mo + (long)(r0+rr)*Cv + c0+tx] = l;
        split2(t[tx][rr], h, l);
        XtH[mo + (long)(c0+rr)*Cv + r0+tx] = h;
        XtL[mo + (long)(c0+rr)*Cv + r0+tx] = l;
    }
}

// Pc[n, 0:512] = P1[n,:], Pc[n, 512:1024] = P2[n,:]
__global__ void packP(const bf16* __restrict__ XH, const bf16* __restrict__ XL,
                      bf16* __restrict__ PcH, bf16* __restrict__ PcL)
{
    int idx = blockIdx.x*256 + threadIdx.x;     // over 512*1024
    int n = idx >> 10, k = idx & 1023;
    long src = (k < 512) ? ((long)n*Cv + k) : (Sm + (long)n*Cv + (k-512));
    PcH[idx] = XH[src];
    PcL[idx] = XL[src];
}

// ---------------- host ----------------
static inline GA mkga(const bf16* Ah, const bf16* Al, const bf16* Bh, const bf16* Bl,
                      int M, int N, int K, int lda, int ldb, long zA = 0, long zB = 0)
{
    GA g; g.Ah=Ah; g.Al=Al; g.Ah2=Ah; g.Al2=Al; g.Bh=Bh; g.Bl=Bl;
    g.M=M; g.N=N; g.K=K; g.K1=K; g.lda=lda; g.ldb=ldb; g.mskip=0; g.zA=zA; g.zB=zB;
    return g;
}
static inline TEpi te()
{
    TEpi e; e.alpha=1.f; e.beta=1.f; e.diag=0.f; e.add=0; e.zAdd=0;
    e.gelu=0; e.outF=0; e.outH=0; e.outL=0; e.zOut=0; e.outTH=0; e.outTL=0;
    return e;
}

#define SM128 (3*4*128*64)
#define SM64  (3*4*64*64)

extern "C" void kernel_launch(void* const* d_in, const int* in_sizes, int n_in,
                              void* d_out, int out_size)
{
    const float* x   = (const float*)d_in[0];
    const float* ln1 = (const float*)d_in[1];
    const float* Wq  = (const float*)d_in[2];
    const float* Wv  = (const float*)d_in[3];
    const float* Wo  = (const float*)d_in[4];
    // d_in[5] = identity : mathematically unused (rows computed from it are discarded)
    const float* Wp1 = (const float*)d_in[6];
    const float* Wp2 = (const float*)d_in[7];
    const float* ln2 = (const float*)d_in[8];
    const float* Wfc = (const float*)d_in[9];
    const float* Wpr = (const float*)d_in[10];
    float* out = (float*)d_out;

    cudaFuncSetAttribute(mma_gemm<128,128>, cudaFuncAttributeMaxDynamicSharedMemorySize, SM128);
    cudaFuncSetAttribute(mma_gemm<64,64>,   cudaFuncAttributeMaxDynamicSharedMemorySize, SM64);

    bf16 *qH,*qL,*vH,*vL,*hH,*hL,*fcH,*fcL;
    bf16 *WqH,*WqL,*WvH,*WvL,*WoH,*WoL,*WfcH,*WfcL,*WprH,*WprL;
    bf16 *XaH,*XaL,*XbH,*XbL,*XtH,*XtL,*YH,*YL,*MH,*ML,*PcH,*PcL;
    float *z,*YF,*part,*rn;
    cudaGetSymbolAddress((void**)&qH, g_qH);   cudaGetSymbolAddress((void**)&qL, g_qL);
    cudaGetSymbolAddress((void**)&vH, g_vH);   cudaGetSymbolAddress((void**)&vL, g_vL);
    cudaGetSymbolAddress((void**)&hH, g_hH);   cudaGetSymbolAddress((void**)&hL, g_hL);
    cudaGetSymbolAddress((void**)&fcH, g_fcH); cudaGetSymbolAddress((void**)&fcL, g_fcL);
    cudaGetSymbolAddress((void**)&WqH, g_WqH); cudaGetSymbolAddress((void**)&WqL, g_WqL);
    cudaGetSymbolAddress((void**)&WvH, g_WvH); cudaGetSymbolAddress((void**)&WvL, g_WvL);
    cudaGetSymbolAddress((void**)&WoH, g_WoH); cudaGetSymbolAddress((void**)&WoL, g_WoL);
    cudaGetSymbolAddress((void**)&WfcH,g_WfcH); cudaGetSymbolAddress((void**)&WfcL,g_WfcL);
    cudaGetSymbolAddress((void**)&WprH,g_WprH); cudaGetSymbolAddress((void**)&WprL,g_WprL);
    cudaGetSymbolAddress((void**)&XaH, g_XaH); cudaGetSymbolAddress((void**)&XaL, g_XaL);
    cudaGetSymbolAddress((void**)&XbH, g_XbH); cudaGetSymbolAddress((void**)&XbL, g_XbL);
    cudaGetSymbolAddress((void**)&XtH, g_XtH); cudaGetSymbolAddress((void**)&XtL, g_XtL);
    cudaGetSymbolAddress((void**)&YH,  g_YH);  cudaGetSymbolAddress((void**)&YL,  g_YL);
    cudaGetSymbolAddress((void**)&MH,  g_MH);  cudaGetSymbolAddress((void**)&ML,  g_ML);
    cudaGetSymbolAddress((void**)&PcH, g_PcH); cudaGetSymbolAddress((void**)&PcL, g_PcL);
    cudaGetSymbolAddress((void**)&z,   g_z);
    cudaGetSymbolAddress((void**)&YF,  g_YF);
    cudaGetSymbolAddress((void**)&part,g_part);
    cudaGetSymbolAddress((void**)&rn,  g_rn);

    // ---- weight splits (single launch) ----
    wsplit5<<<(11*Cv*Cv)/256,256>>>(Wq, Wv, Wo, Wfc, Wpr,
        WqH, WqL, WvH, WvL, WoH, WoL, WfcH, WfcL, WprH, WprL);

    // ---- polar factors via Muon-quintic + Newton-Schulz on tensor cores ----
    frob1<<<dim3(Cv,2),128>>>(Wp1, Wp2, part);
    frob2<<<2,256>>>(part, rn);
    split_tr_init<<<dim3(16,16,2),dim3(32,8)>>>(Wp1, Wp2, rn, XaH, XaL, XtH, XtL);

    const dim3 gp(8, 8, 2);
    for (int it = 0; it < 9; ++it) {
        // Y = Xt @ Xt^T  (= X^T X, symmetric)
        GA g1 = mkga(XtH, XtL, XtH, XtL, Cv, Cv, Cv, Cv, Cv, Sm, Sm);
        TEpi e1 = te(); e1.outF = YF; e1.outH = YH; e1.outL = YL; e1.zOut = Sm;
        mma_gemm<64,64><<<gp,256,SM64>>>(g1, e1);
        // M = 2.0315*Y@Y^T - 4.7750*Y + 3.4445*I  (symmetric)
        GA g2 = mkga(YH, YL, YH, YL, Cv, Cv, Cv, Cv, Cv, Sm, Sm);
        TEpi e2 = te(); e2.alpha = 2.0315f; e2.add = YF; e2.zAdd = Sm;
        e2.beta = -4.7750f; e2.diag = 3.4445f; e2.outH = MH; e2.outL = ML; e2.zOut = Sm;
        mma_gemm<64,64><<<gp,256,SM64>>>(g2, e2);
        // X' = X @ M^T (= X M, M symmetric); epilogue also emits Xt'
        GA g3 = mkga(XaH, XaL, MH, ML, Cv, Cv, Cv, Cv, Cv, Sm, Sm);
        TEpi e3 = te(); e3.outH = XbH; e3.outL = XbL; e3.zOut = Sm;
        e3.outTH = XtH; e3.outTL = XtL;
        mma_gemm<64,64><<<gp,256,SM64>>>(g3, e3);
        bf16* t;
        t = XaH; XaH = XbH; XbH = t;
        t = XaL; XaL = XbL; XbL = t;
    }
    for (int it = 0; it < 5; ++it) {
        // G = -0.5*Xt@Xt^T + 1.5I  (symmetric)
        GA g1 = mkga(XtH, XtL, XtH, XtL, Cv, Cv, Cv, Cv, Cv, Sm, Sm);
        TEpi e1 = te(); e1.alpha = -0.5f; e1.diag = 1.5f;
        e1.outH = MH; e1.outL = ML; e1.zOut = Sm;
        mma_gemm<64,64><<<gp,256,SM64>>>(g1, e1);
        // X' = X @ G^T; epilogue also emits Xt'
        GA g2 = mkga(XaH, XaL, MH, ML, Cv, Cv, Cv, Cv, Cv, Sm, Sm);
        TEpi e2 = te(); e2.outH = XbH; e2.outL = XbL; e2.zOut = Sm;
        e2.outTH = XtH; e2.outTL = XtL;
        mma_gemm<64,64><<<gp,256,SM64>>>(g2, e2);
        bf16* t;
        t = XaH; XaH = XbH; XbH = t;
        t = XaL; XaL = XbL; XbL = t;
    }
    packP<<<(Cv*2*Cv)/256,256>>>(XaH, XaL, PcH, PcL);

    // ---- SSM branch ----
    ln_kernel<<<Rv,128>>>(x, ln1, hH, hL);
    {
        GA gq = mkga(hH, hL, WqH, WqL, Rv, Cv, Cv, Cv, Cv);
        TEpi eq = te(); eq.outH = qH + GUARDE; eq.outL = qL + GUARDE;
        mma_gemm<128,128><<<dim3(Cv/128, Rv/128), 256, SM128>>>(gq, eq);
        GA gv = mkga(hH, hL, WvH, WvL, Rv, Cv, Cv, Cv, Cv);
        TEpi ev = te(); ev.outH = vH; ev.outL = vL;
        mma_gemm<128,128><<<dim3(Cv/128, Rv/128), 256, SM128>>>(gv, ev);
    }

    for (int d = 1; d < Tv; d <<= 1) {
        const int mskip = d & ~127;          // whole 128-row tiles with t<d skipped
        // z = qshift @ P1^T + q @ P2^T : single GEMM, K=1024
        // chunks k<512 read q[t-d] (guard zeros / stale rows, discarded), k>=512 read q[t]
        GA gs = mkga(qH + GUARDE, qL + GUARDE, PcH, PcL, Rv, Cv, 2*Cv, Cv, 2*Cv);
        gs.Ah = qH + GUARDE - (long)d*Cv;
        gs.Al = qL + GUARDE - (long)d*Cv;
        gs.K1 = Cv;
        gs.mskip = mskip;
        gs.zA = (long)Tv*Cv;                  // batch stride (rows)
        TEpi es = te(); es.outF = z; es.zOut = (long)Tv*Cv;
        mma_gemm<128,128><<<dim3(Cv/128, (Tv-mskip)/128, Bv), 256, SM128>>>(gs, es);
        pscan_combine<<<dim3(Tv-mskip, Bv),128>>>(z, qH + GUARDE, qL + GUARDE, d, mskip);
    }

    // x1 = x + (q*v) @ Wo^T   (into d_out)
    mul_split<<<(Rv*Cv/4)/256,256>>>(qH + GUARDE, qL + GUARDE, vH, vL, hH, hL);
    {
        GA go = mkga(hH, hL, WoH, WoL, Rv, Cv, Cv, Cv, Cv);
        TEpi er = te(); er.add = x; er.outF = out;
        mma_gemm<128,128><<<dim3(Cv/128, Rv/128), 256, SM128>>>(go, er);
    }

    // ---- MLP branch ----
    ln_kernel<<<Rv,128>>>(out, ln2, hH, hL);
    {
        GA gf = mkga(hH, hL, WfcH, WfcL, Rv, Fv, Cv, Cv, Cv);
        TEpi eg = te(); eg.gelu = 1; eg.outH = fcH; eg.outL = fcL;
        mma_gemm<128,128><<<dim3(Fv/128, Rv/128), 256, SM128>>>(gf, eg);
        GA gr = mkga(fcH, fcL, WprH, WprL, Rv, Cv, Fv, Fv, Fv);
        TEpi er2 = te(); er2.add = out; er2.outF = out;
        mma_gemm<128,128><<<dim3(Cv/128, Rv/128), 256, SM128>>>(gr, er2);
    }
}

// round 9
// speedup vs baseline: 3.2072x; 1.0036x over previous
#include <cuda_runtime.h>
#include <cuda_bf16.h>
#include <math.h>
#include <stdint.h>

#define Bv 4
#define Tv 4096
#define Cv 512
#define Rv (Bv*Tv)            // 16384 rows
#define Fv (4*Cv)             // 2048
#define GUARDE (2048*Cv)      // guard rows (zero-init) for shifted scan operand
#define Sm ((long)Cv*Cv)

typedef __nv_bfloat16 bf16;

// ---------------- static device scratch (zero-initialized) ----------------
__device__ bf16 g_qH[GUARDE + Rv*Cv];
__device__ bf16 g_qL[GUARDE + Rv*Cv];
__device__ bf16 g_vH[Rv*Cv], g_vL[Rv*Cv];
__device__ float g_z[Rv*Cv];
__device__ bf16 g_hH[Rv*Cv], g_hL[Rv*Cv];
__device__ bf16 g_fcH[Rv*Fv], g_fcL[Rv*Fv];
// weight splits
__device__ bf16 g_WqH[Cv*Cv], g_WqL[Cv*Cv];
__device__ bf16 g_WvH[Cv*Cv], g_WvL[Cv*Cv];
__device__ bf16 g_WoH[Cv*Cv], g_WoL[Cv*Cv];
__device__ bf16 g_WfcH[Fv*Cv], g_WfcL[Fv*Cv];
__device__ bf16 g_WprH[Cv*Fv], g_WprL[Cv*Fv];
// polar scratch (x2 matrices, batched)
__device__ bf16 g_XaH[2*Cv*Cv], g_XaL[2*Cv*Cv];
__device__ bf16 g_XbH[2*Cv*Cv], g_XbL[2*Cv*Cv];
__device__ bf16 g_XtH[2*Cv*Cv], g_XtL[2*Cv*Cv];
__device__ bf16 g_YH [2*Cv*Cv], g_YL [2*Cv*Cv];
__device__ bf16 g_MH [2*Cv*Cv], g_ML [2*Cv*Cv];
__device__ float g_YF[2*Cv*Cv];
__device__ bf16 g_PcH[Cv*2*Cv], g_PcL[Cv*2*Cv];   // [P1||P2] along K (512 x 1024)
__device__ float g_part[2*Cv];
__device__ float g_rn[2];

// ================= helpers =================
__device__ __forceinline__ uint32_t smem_to_u32(const void* p) {
    uint32_t a;
    asm("{ .reg .u64 t; cvta.to.shared.u64 t, %1; cvt.u32.u64 %0, t; }" : "=r"(a) : "l"(p));
    return a;
}
__device__ __forceinline__ void split2(float x, bf16& h, bf16& l) {
    h = __float2bfloat16(x);
    l = __float2bfloat16(x - __bfloat162float(h));
}
__device__ __forceinline__ uint32_t pk2(bf16 a, bf16 b) {
    __nv_bfloat162 t; t.x = a; t.y = b;
    return *(uint32_t*)&t;
}
__device__ __forceinline__ void up2(uint32_t u, float& a, float& b) {
    __nv_bfloat162 t = *(__nv_bfloat162*)&u;
    a = __bfloat162float(t.x); b = __bfloat162float(t.y);
}
__device__ __forceinline__ void ldsm4(uint32_t (&r)[4], uint32_t addr) {
    asm volatile("ldmatrix.sync.aligned.m8n8.x4.shared.b16 {%0,%1,%2,%3}, [%4];"
        : "=r"(r[0]), "=r"(r[1]), "=r"(r[2]), "=r"(r[3]) : "r"(addr));
}
__device__ __forceinline__ void mma16816(float (&d)[4], const uint32_t (&a)[4],
                                         uint32_t b0, uint32_t b1) {
    asm volatile("mma.sync.aligned.m16n8k16.row.col.f32.bf16.bf16.f32 "
        "{%0,%1,%2,%3}, {%4,%5,%6,%7}, {%8,%9}, {%0,%1,%2,%3};"
        : "+f"(d[0]), "+f"(d[1]), "+f"(d[2]), "+f"(d[3])
        : "r"(a[0]), "r"(a[1]), "r"(a[2]), "r"(a[3]), "r"(b0), "r"(b1));
}
__device__ __forceinline__ void cp_async16(uint32_t so, const void* gp) {
    asm volatile("cp.async.cg.shared.global [%0], [%1], 16;" :: "r"(so), "l"(gp) : "memory");
}
#define CP_COMMIT() asm volatile("cp.async.commit_group;" ::: "memory")
#define CP_WAIT(n)  asm volatile("cp.async.wait_group %0;" :: "n"(n) : "memory")

// ================= mma.sync split-bf16 GEMM: C = alpha*A@B^T (+beta*add +diag*I) =====
// A: [M,K] bf16 hi/lo (K ranges split across Ah(k<K1)/Ah2(k>=K1), pitch lda).
// B: [N,K] bf16 hi/lo, pitch ldb. 3 passes hh+lh+hl interleaved with ldsm.
// CTA tile BMxBM, 8 warps (2x4). K-chunk 32, 3-stage cp.async pipeline with
// ONE __syncthreads per iteration (WAIT -> sync -> issue c+2 -> compute c):
// loads into buffer (c+2)%3 are safe because the sync guarantees every warp
// finished compute(c-1), which was the last reader of that buffer.
// grid.z batches: A/B/out/add advance by zA/zB/zOut/zAdd; rows offset by mskip.
// Optional transposed output (outTH/outTL) staged through smem (for polar Xt).
struct GA {
    const bf16 *Ah, *Al, *Ah2, *Al2, *Bh, *Bl;
    int M, N, K, K1, lda, ldb, mskip;
    long zA, zB;
};
struct TEpi {
    float alpha, beta, diag;
    const float* add; long zAdd;
    int gelu;
    float* outF; bf16 *outH, *outL; long zOut;
    bf16 *outTH, *outTL;     // transposed bf16 split output (square, pitch N)
};

template<int BM, int BN>
__global__ __launch_bounds__(256, 2)
void mma_gemm(GA g, TEpi e)
{
    static_assert(BM == BN, "square tiles only");
    constexpr int MF = BM/32, NF = BN/32, NB = NF/2;
    constexpr int ASZ = BM*64;         // one operand tile (BM rows x 32 k x 2B)
    constexpr int BUF = 4*ASZ;         // hi/lo A + hi/lo B per stage
    extern __shared__ char smem[];
    const uint32_t sb = smem_to_u32(smem);
    const int tid  = threadIdx.x;
    const int lane = tid & 31;
    const int wm   = (tid >> 5) & 1;
    const int wn   = (tid >> 5) >> 1;
    const int m0 = g.mskip + blockIdx.y * BM;
    const int n0 = blockIdx.x * BN;
    const int bz = blockIdx.z;
    const int NC = g.K / 32;

    const bf16 *Ah = g.Ah + bz*g.zA,  *Al = g.Al + bz*g.zA;
    const bf16 *Ah2 = g.Ah2 + bz*g.zA, *Al2 = g.Al2 + bz*g.zA;
    const bf16 *Bh = g.Bh + bz*g.zB,  *Bl = g.Bl + bz*g.zB;

    // precomputed per-(ks,frag) smem offsets within a stage buffer
    int aOff[2][MF], bOff[2][NB];
    {
        const int aKb = (lane >> 4) * 16;
#pragma unroll
        for (int mf = 0; mf < MF; mf++) {
            int r = wm * (BM/2) + mf * 16 + (lane & 15);
            int base = (r >> 1) * 128, po = (r & 1) * 64, xm = ((r >> 1) & 7) << 4;
#pragma unroll
            for (int ks = 0; ks < 2; ks++)
                aOff[ks][mf] = base + ((po + ks * 32 + aKb) ^ xm);
        }
        const int bKb = ((lane >> 3) & 1) * 16;
#pragma unroll
        for (int nb = 0; nb < NB; nb++) {
            int r = wn * (BN/4) + nb * 16 + ((lane >> 4) << 3) + (lane & 7);
            int base = (r >> 1) * 128, po = (r & 1) * 64, xm = ((r >> 1) & 7) << 4;
#pragma unroll
            for (int ks = 0; ks < 2; ks++)
                bOff[ks][nb] = base + ((po + ks * 32 + bKb) ^ xm);
        }
    }

    float acc[MF][NF][4];
#pragma unroll
    for (int i = 0; i < MF; i++)
#pragma unroll
        for (int j = 0; j < NF; j++)
#pragma unroll
            for (int t = 0; t < 4; t++) acc[i][j][t] = 0.f;

    auto loadChunk = [&](int c) {
        const long cofs = (long)c * 32;
        const int st = c % 3;
        const bf16* AHc = Ah; const bf16* ALc = Al;
        long acol = cofs;
        if (cofs >= g.K1) { AHc = Ah2; ALc = Al2; acol = cofs - g.K1; }
        constexpr int TV = BM * 4;      // 16B vectors per tile
#pragma unroll
        for (int t = 0; t < (4*TV)/256; t++) {
            int u = tid + t * 256;
            int tile = u / TV;
            int w = u % TV;
            int row = w >> 2;
            int seg = w & 3;
            const bf16* gp;
            if      (tile == 0) gp = AHc + (long)(m0 + row) * g.lda + acol;
            else if (tile == 1) gp = ALc + (long)(m0 + row) * g.lda + acol;
            else if (tile == 2) gp = Bh + (long)(n0 + row) * g.ldb + cofs;
            else                gp = Bl + (long)(n0 + row) * g.ldb + cofs;
            gp += seg * 8;
            int j = row >> 1, p = row & 1;
            uint32_t so = sb + st * BUF + tile * ASZ + j * 128
                        + ((p * 64 + seg * 16) ^ ((j & 7) << 4));
            cp_async16(so, gp);
        }
        CP_COMMIT();
    };

    loadChunk(0);
    if (NC > 1) loadChunk(1);

    for (int c = 0; c < NC; c++) {
        if (c + 1 < NC) CP_WAIT(1);
        else            CP_WAIT(0);
        __syncthreads();
        if (c + 2 < NC) loadChunk(c + 2);

        const uint32_t bufB = sb + (c % 3) * BUF;
#pragma unroll
        for (int ks = 0; ks < 2; ks++) {
            uint32_t afH[MF][4], bfH[NB][4];
#pragma unroll
            for (int mf = 0; mf < MF; mf++)
                ldsm4(afH[mf], bufB + aOff[ks][mf]);
#pragma unroll
            for (int nb = 0; nb < NB; nb++)
                ldsm4(bfH[nb], bufB + 2*ASZ + bOff[ks][nb]);
            // pass hh
#pragma unroll
            for (int mf = 0; mf < MF; mf++)
#pragma unroll
                for (int nf = 0; nf < NF; nf++)
                    mma16816(acc[mf][nf], afH[mf], bfH[nf>>1][(nf&1)*2], bfH[nf>>1][(nf&1)*2+1]);
            // pass lh (afL loaded now; bfH still live)
            {
                uint32_t afL[MF][4];
#pragma unroll
                for (int mf = 0; mf < MF; mf++)
                    ldsm4(afL[mf], bufB + ASZ + aOff[ks][mf]);
#pragma unroll
                for (int mf = 0; mf < MF; mf++)
#pragma unroll
                    for (int nf = 0; nf < NF; nf++)
                        mma16816(acc[mf][nf], afL[mf], bfH[nf>>1][(nf&1)*2], bfH[nf>>1][(nf&1)*2+1]);
            }
            // pass hl (bfL loaded now; afH still live, afL/bfH dead)
            {
                uint32_t bfL[NB][4];
#pragma unroll
                for (int nb = 0; nb < NB; nb++)
                    ldsm4(bfL[nb], bufB + 3*ASZ + bOff[ks][nb]);
#pragma unroll
                for (int mf = 0; mf < MF; mf++)
#pragma unroll
                    for (int nf = 0; nf < NF; nf++)
                        mma16816(acc[mf][nf], afH[mf], bfL[nf>>1][(nf&1)*2], bfL[nf>>1][(nf&1)*2+1]);
            }
        }
    }
    __syncthreads();    // all warps done with smem before epilogue staging reuses it

    // ---- epilogue ----
    float* outF = e.outF ? e.outF + bz*e.zOut : (float*)0;
    bf16*  outH = e.outH ? e.outH + bz*e.zOut : (bf16*)0;
    bf16*  outL = e.outL ? e.outL + bz*e.zOut : (bf16*)0;
    const float* add = e.add ? e.add + bz*e.zAdd : (const float*)0;
    bf16* sH = (bf16*)smem;                    // transposed staging [BM][BN+1]
    bf16* sL = sH + BM*(BN+1);
    const int rl = lane >> 2;
    const int cl = (lane & 3) * 2;
#pragma unroll
    for (int mf = 0; mf < MF; mf++) {
#pragma unroll
        for (int nf = 0; nf < NF; nf++) {
            int lc = wn * (BN/4) + nf * 8 + cl;
            int c0 = n0 + lc;
#pragma unroll
            for (int half = 0; half < 2; half++) {
                int lr = wm * (BM/2) + mf * 16 + rl + half * 8;
                int row = m0 + lr;
                long ofs = (long)row * g.N + c0;
                float f0 = e.alpha * acc[mf][nf][half*2];
                float f1 = e.alpha * acc[mf][nf][half*2 + 1];
                if (add) {
                    float2 ra = *(const float2*)(add + ofs);
                    f0 += e.beta * ra.x; f1 += e.beta * ra.y;
                }
                if (e.diag != 0.f) {
                    if (row == c0)     f0 += e.diag;
                    if (row == c0 + 1) f1 += e.diag;
                }
                if (e.gelu) {
                    f0 = 0.5f * f0 * (1.f + erff(f0 * 0.70710678118654752f));
                    f1 = 0.5f * f1 * (1.f + erff(f1 * 0.70710678118654752f));
                }
                if (outF)
                    *(float2*)(outF + ofs) = make_float2(f0, f1);
                if (outH || e.outTH) {
                    bf16 h0, h1, l0, l1;
                    split2(f0, h0, l0);
                    split2(f1, h1, l1);
                    if (outH) {
                        *(uint32_t*)(outH + ofs) = pk2(h0, h1);
                        *(uint32_t*)(outL + ofs) = pk2(l0, l1);
                    }
                    if (e.outTH) {
                        sH[lr*(BN+1) + lc] = h0; sH[lr*(BN+1) + lc + 1] = h1;
                        sL[lr*(BN+1) + lc] = l0; sL[lr*(BN+1) + lc + 1] = l1;
                    }
                }
            }
        }
    }
    if (e.outTH) {
        __syncthreads();
        bf16* outTH = e.outTH + bz*e.zOut;
        bf16* outTL = e.outTL + bz*e.zOut;
#pragma unroll
        for (int it = 0; it < (BM*BN)/256; it++) {
            int idx = tid + it * 256;
            int j = idx / BM;        // col of X = row of Xt
            int i = idx % BM;        // row of X
            long o = (long)(n0 + j) * g.N + m0 + i;
            outTH[o] = sH[i*(BN+1) + j];
            outTL[o] = sL[i*(BN+1) + j];
        }
    }
}

// ---------------- elementwise / reduction kernels ----------------
__global__ void ln_kernel(const float* __restrict__ x, const float* __restrict__ w,
                          bf16* __restrict__ oh, bf16* __restrict__ ol)
{
    const int r = blockIdx.x, tid = threadIdx.x;
    float4 f = ((const float4*)(x + (long)r*Cv))[tid];
    float s = f.x+f.y+f.z+f.w;
    float q = f.x*f.x+f.y*f.y+f.z*f.z+f.w*f.w;
    __shared__ float shs[4], shq[4];
#pragma unroll
    for (int off=16; off>0; off>>=1) {
        s += __shfl_down_sync(0xffffffffu, s, off);
        q += __shfl_down_sync(0xffffffffu, q, off);
    }
    if ((tid&31)==0) { shs[tid>>5]=s; shq[tid>>5]=q; }
    __syncthreads();
    float S = shs[0]+shs[1]+shs[2]+shs[3];
    float Q = shq[0]+shq[1]+shq[2]+shq[3];
    float mean = S*(1.f/Cv);
    float var  = Q*(1.f/Cv) - mean*mean;
    float inv  = rsqrtf(var + 1e-5f);
    float4 wf = ((const float4*)w)[tid];
    float o0=(f.x-mean)*inv*wf.x, o1=(f.y-mean)*inv*wf.y;
    float o2=(f.z-mean)*inv*wf.z, o3=(f.w-mean)*inv*wf.w;
    bf16 h0,h1,h2,h3,l0,l1,l2,l3;
    split2(o0,h0,l0); split2(o1,h1,l1); split2(o2,h2,l2); split2(o3,h3,l3);
    long ofs = (long)r*Cv + tid*4;
    uint2 uh; uh.x=pk2(h0,h1); uh.y=pk2(h2,h3);
    uint2 ul; ul.x=pk2(l0,l1); ul.y=pk2(l2,l3);
    *(uint2*)(oh+ofs)=uh; *(uint2*)(ol+ofs)=ul;
}

// in-place scan combine: q[t] <- rms(z[t]) for t >= d. grid (Tv - mskip, Bv).
__global__ void pscan_combine(const float* __restrict__ z,
                              bf16* __restrict__ qH, bf16* __restrict__ qL,
                              int d, int mskip)
{
    const int t = mskip + blockIdx.x;
    if (t < d) return;
    const int r = blockIdx.y * Tv + t;
    const int tid = threadIdx.x;
    long ofs = (long)r*Cv + tid*4;
    float4 f = *(const float4*)(z+ofs);
    float q = f.x*f.x+f.y*f.y+f.z*f.z+f.w*f.w;
    __shared__ float shq[4];
#pragma unroll
    for (int off=16; off>0; off>>=1) q += __shfl_down_sync(0xffffffffu, q, off);
    if ((tid&31)==0) shq[tid>>5]=q;
    __syncthreads();
    float Q = shq[0]+shq[1]+shq[2]+shq[3];
    float sc = rsqrtf(Q*(1.f/Cv) + 1e-6f);
    float o0=f.x*sc, o1=f.y*sc, o2=f.z*sc, o3=f.w*sc;
    bf16 h0,h1,h2,h3,l0,l1,l2,l3;
    split2(o0,h0,l0); split2(o1,h1,l1); split2(o2,h2,l2); split2(o3,h3,l3);
    uint2 uh; uh.x=pk2(h0,h1); uh.y=pk2(h2,h3);
    uint2 ul; ul.x=pk2(l0,l1); ul.y=pk2(l2,l3);
    *(uint2*)(qH+ofs)=uh; *(uint2*)(qL+ofs)=ul;
}

// h = split(q * v) with q,v reconstructed from bf16 pairs
__global__ void mul_split(const bf16* __restrict__ qH, const bf16* __restrict__ qL,
                          const bf16* __restrict__ vH, const bf16* __restrict__ vL,
                          bf16* __restrict__ H, bf16* __restrict__ L)
{
    long i = ((long)blockIdx.x*256 + threadIdx.x)*4;
    uint2 a = *(const uint2*)(qH+i), b = *(const uint2*)(qL+i);
    uint2 c = *(const uint2*)(vH+i), d = *(const uint2*)(vL+i);
    float q0,q1,q2,q3,ql0,ql1,ql2,ql3,v0,v1,v2,v3,vl0,vl1,vl2,vl3;
    up2(a.x,q0,q1); up2(a.y,q2,q3); up2(b.x,ql0,ql1); up2(b.y,ql2,ql3);
    up2(c.x,v0,v1); up2(c.y,v2,v3); up2(d.x,vl0,vl1); up2(d.y,vl2,vl3);
    float o0=(q0+ql0)*(v0+vl0), o1=(q1+ql1)*(v1+vl1);
    float o2=(q2+ql2)*(v2+vl2), o3=(q3+ql3)*(v3+vl3);
    bf16 h0,h1,h2,h3,l0,l1,l2,l3;
    split2(o0,h0,l0); split2(o1,h1,l1); split2(o2,h2,l2); split2(o3,h3,l3);
    uint2 uh; uh.x=pk2(h0,h1); uh.y=pk2(h2,h3);
    uint2 ul; ul.x=pk2(l0,l1); ul.y=pk2(l2,l3);
    *(uint2*)(H+i)=uh; *(uint2*)(L+i)=ul;
}

// all five weight splits in one launch
__global__ void wsplit5(const float* __restrict__ Wq, const float* __restrict__ Wv,
                        const float* __restrict__ Wo, const float* __restrict__ Wfc,
                        const float* __restrict__ Wpr,
                        bf16* WqH, bf16* WqL, bf16* WvH, bf16* WvL,
                        bf16* WoH, bf16* WoL, bf16* WfcH, bf16* WfcL,
                        bf16* WprH, bf16* WprL)
{
    const int S = Cv*Cv;
    long i = (long)blockIdx.x*256 + threadIdx.x;   // over 11*S
    const float* W; bf16 *H, *L; long j;
    if      (i < S)       { W=Wq;  H=WqH;  L=WqL;  j=i; }
    else if (i < 2L*S)    { W=Wv;  H=WvH;  L=WvL;  j=i-S; }
    else if (i < 3L*S)    { W=Wo;  H=WoH;  L=WoL;  j=i-2L*S; }
    else if (i < 7L*S)    { W=Wfc; H=WfcH; L=WfcL; j=i-3L*S; }
    else                  { W=Wpr; H=WprH; L=WprL; j=i-7L*S; }
    float x = W[j];
    bf16 h, l; split2(x, h, l);
    H[j] = h; L[j] = l;
}

__global__ void frob1(const float* __restrict__ W1, const float* __restrict__ W2,
                      float* __restrict__ part)
{
    const int row = blockIdx.x, mat = blockIdx.y, tid = threadIdx.x;
    const float* W = mat ? W2 : W1;
    float4 f = ((const float4*)(W + (long)row*Cv))[tid];
    float q = f.x*f.x+f.y*f.y+f.z*f.z+f.w*f.w;
    __shared__ float shq[4];
#pragma unroll
    for (int off=16; off>0; off>>=1) q += __shfl_down_sync(0xffffffffu, q, off);
    if ((tid&31)==0) shq[tid>>5]=q;
    __syncthreads();
    if (tid==0) part[mat*Cv + row] = shq[0]+shq[1]+shq[2]+shq[3];
}

__global__ void frob2(const float* __restrict__ part, float* __restrict__ rn)
{
    const int mat = blockIdx.x, tid = threadIdx.x;
    __shared__ float sh[256];
    sh[tid] = part[mat*Cv + tid] + part[mat*Cv + tid + 256];
    __syncthreads();
    for (int off=128; off>0; off>>=1) {
        if (tid<off) sh[tid] += sh[tid+off];
        __syncthreads();
    }
    if (tid==0) rn[mat] = rsqrtf(sh[0]);
}

// X = W * rn, split to H/L, plus transposed copies. grid (16,16,2), block (32,8).
__global__ void split_tr_init(const float* __restrict__ W1, const float* __restrict__ W2,
                              const float* __restrict__ rn,
                              bf16* XH, bf16* XL, bf16* XtH, bf16* XtL)
{
    __shared__ float t[32][33];
    const int mat = blockIdx.z;
    const float* W = mat ? W2 : W1;
    const float s = rn[mat];
    const int r0 = blockIdx.y*32, c0 = blockIdx.x*32;
    const int tx = threadIdx.x, ty = threadIdx.y;
    const long mo = (long)mat*Sm;
#pragma unroll
    for (int i = 0; i < 4; i++) {
        int rr = ty + i*8;
        t[rr][tx] = W[(long)(r0+rr)*Cv + c0+tx] * s;
    }
    __syncthreads();
#pragma unroll
    for (int i = 0; i < 4; i++) {
        int rr = ty + i*8;
        bf16 h, l;
        split2(t[rr][tx], h, l);
        XH[mo + (long)(r0+rr)*Cv + c0+tx] = h;
        XL[mo + (long)(r0+rr)*Cv + c0+tx] = l;
        split2(t[tx][rr], h, l);
        XtH[mo + (long)(c0+rr)*Cv + r0+tx] = h;
        XtL[mo + (long)(c0+rr)*Cv + r0+tx] = l;
    }
}

// Pc[n, 0:512] = P1[n,:], Pc[n, 512:1024] = P2[n,:]
__global__ void packP(const bf16* __restrict__ XH, const bf16* __restrict__ XL,
                      bf16* __restrict__ PcH, bf16* __restrict__ PcL)
{
    int idx = blockIdx.x*256 + threadIdx.x;     // over 512*1024
    int n = idx >> 10, k = idx & 1023;
    long src = (k < 512) ? ((long)n*Cv + k) : (Sm + (long)n*Cv + (k-512));
    PcH[idx] = XH[src];
    PcL[idx] = XL[src];
}

// ---------------- host ----------------
static inline GA mkga(const bf16* Ah, const bf16* Al, const bf16* Bh, const bf16* Bl,
                      int M, int N, int K, int lda, int ldb, long zA = 0, long zB = 0)
{
    GA g; g.Ah=Ah; g.Al=Al; g.Ah2=Ah; g.Al2=Al; g.Bh=Bh; g.Bl=Bl;
    g.M=M; g.N=N; g.K=K; g.K1=K; g.lda=lda; g.ldb=ldb; g.mskip=0; g.zA=zA; g.zB=zB;
    return g;
}
static inline TEpi te()
{
    TEpi e; e.alpha=1.f; e.beta=1.f; e.diag=0.f; e.add=0; e.zAdd=0;
    e.gelu=0; e.outF=0; e.outH=0; e.outL=0; e.zOut=0; e.outTH=0; e.outTL=0;
    return e;
}

#define SM128 (3*4*128*64)
#define SM64  (3*4*64*64)

extern "C" void kernel_launch(void* const* d_in, const int* in_sizes, int n_in,
                              void* d_out, int out_size)
{
    const float* x   = (const float*)d_in[0];
    const float* ln1 = (const float*)d_in[1];
    const float* Wq  = (const float*)d_in[2];
    const float* Wv  = (const float*)d_in[3];
    const float* Wo  = (const float*)d_in[4];
    // d_in[5] = identity : mathematically unused (rows computed from it are discarded)
    const float* Wp1 = (const float*)d_in[6];
    const float* Wp2 = (const float*)d_in[7];
    const float* ln2 = (const float*)d_in[8];
    const float* Wfc = (const float*)d_in[9];
    const float* Wpr = (const float*)d_in[10];
    float* out = (float*)d_out;

    cudaFuncSetAttribute(mma_gemm<128,128>, cudaFuncAttributeMaxDynamicSharedMemorySize, SM128);
    cudaFuncSetAttribute(mma_gemm<64,64>,   cudaFuncAttributeMaxDynamicSharedMemorySize, SM64);

    // second stream for the (serial, low-occupancy) polar chain, overlapped
    // with weight splits + ln + q/v GEMMs via capture-safe fork/join events.
    static cudaStream_t sP = 0;
    static cudaEvent_t evF = 0, evJ = 0;
    if (!sP) {
        cudaStreamCreateWithFlags(&sP, cudaStreamNonBlocking);
        cudaEventCreateWithFlags(&evF, cudaEventDisableTiming);
        cudaEventCreateWithFlags(&evJ, cudaEventDisableTiming);
    }

    bf16 *qH,*qL,*vH,*vL,*hH,*hL,*fcH,*fcL;
    bf16 *WqH,*WqL,*WvH,*WvL,*WoH,*WoL,*WfcH,*WfcL,*WprH,*WprL;
    bf16 *XaH,*XaL,*XbH,*XbL,*XtH,*XtL,*YH,*YL,*MH,*ML,*PcH,*PcL;
    float *z,*YF,*part,*rn;
    cudaGetSymbolAddress((void**)&qH, g_qH);   cudaGetSymbolAddress((void**)&qL, g_qL);
    cudaGetSymbolAddress((void**)&vH, g_vH);   cudaGetSymbolAddress((void**)&vL, g_vL);
    cudaGetSymbolAddress((void**)&hH, g_hH);   cudaGetSymbolAddress((void**)&hL, g_hL);
    cudaGetSymbolAddress((void**)&fcH, g_fcH); cudaGetSymbolAddress((void**)&fcL, g_fcL);
    cudaGetSymbolAddress((void**)&WqH, g_WqH); cudaGetSymbolAddress((void**)&WqL, g_WqL);
    cudaGetSymbolAddress((void**)&WvH, g_WvH); cudaGetSymbolAddress((void**)&WvL, g_WvL);
    cudaGetSymbolAddress((void**)&WoH, g_WoH); cudaGetSymbolAddress((void**)&WoL, g_WoL);
    cudaGetSymbolAddress((void**)&WfcH,g_WfcH); cudaGetSymbolAddress((void**)&WfcL,g_WfcL);
    cudaGetSymbolAddress((void**)&WprH,g_WprH); cudaGetSymbolAddress((void**)&WprL,g_WprL);
    cudaGetSymbolAddress((void**)&XaH, g_XaH); cudaGetSymbolAddress((void**)&XaL, g_XaL);
    cudaGetSymbolAddress((void**)&XbH, g_XbH); cudaGetSymbolAddress((void**)&XbL, g_XbL);
    cudaGetSymbolAddress((void**)&XtH, g_XtH); cudaGetSymbolAddress((void**)&XtL, g_XtL);
    cudaGetSymbolAddress((void**)&YH,  g_YH);  cudaGetSymbolAddress((void**)&YL,  g_YL);
    cudaGetSymbolAddress((void**)&MH,  g_MH);  cudaGetSymbolAddress((void**)&ML,  g_ML);
    cudaGetSymbolAddress((void**)&PcH, g_PcH); cudaGetSymbolAddress((void**)&PcL, g_PcL);
    cudaGetSymbolAddress((void**)&z,   g_z);
    cudaGetSymbolAddress((void**)&YF,  g_YF);
    cudaGetSymbolAddress((void**)&part,g_part);
    cudaGetSymbolAddress((void**)&rn,  g_rn);

    // ---- fork: polar chain on sP, prep on main stream ----
    cudaEventRecord(evF, 0);
    cudaStreamWaitEvent(sP, evF, 0);

    {   // polar factors via Muon-quintic + Newton-Schulz on tensor cores (stream sP)
        frob1<<<dim3(Cv,2),128,0,sP>>>(Wp1, Wp2, part);
        frob2<<<2,256,0,sP>>>(part, rn);
        split_tr_init<<<dim3(16,16,2),dim3(32,8),0,sP>>>(Wp1, Wp2, rn, XaH, XaL, XtH, XtL);

        const dim3 gp(8, 8, 2);
        for (int it = 0; it < 9; ++it) {
            // Y = Xt @ Xt^T  (= X^T X, symmetric)
            GA g1 = mkga(XtH, XtL, XtH, XtL, Cv, Cv, Cv, Cv, Cv, Sm, Sm);
            TEpi e1 = te(); e1.outF = YF; e1.outH = YH; e1.outL = YL; e1.zOut = Sm;
            mma_gemm<64,64><<<gp,256,SM64,sP>>>(g1, e1);
            // M = 2.0315*Y@Y^T - 4.7750*Y + 3.4445*I  (symmetric)
            GA g2 = mkga(YH, YL, YH, YL, Cv, Cv, Cv, Cv, Cv, Sm, Sm);
            TEpi e2 = te(); e2.alpha = 2.0315f; e2.add = YF; e2.zAdd = Sm;
            e2.beta = -4.7750f; e2.diag = 3.4445f; e2.outH = MH; e2.outL = ML; e2.zOut = Sm;
            mma_gemm<64,64><<<gp,256,SM64,sP>>>(g2, e2);
            // X' = X @ M^T (= X M, M symmetric); epilogue also emits Xt'
            GA g3 = mkga(XaH, XaL, MH, ML, Cv, Cv, Cv, Cv, Cv, Sm, Sm);
            TEpi e3 = te(); e3.outH = XbH; e3.outL = XbL; e3.zOut = Sm;
            e3.outTH = XtH; e3.outTL = XtL;
            mma_gemm<64,64><<<gp,256,SM64,sP>>>(g3, e3);
            bf16* t;
            t = XaH; XaH = XbH; XbH = t;
            t = XaL; XaL = XbL; XbL = t;
        }
        for (int it = 0; it < 5; ++it) {
            // G = -0.5*Xt@Xt^T + 1.5I  (symmetric)
            GA g1 = mkga(XtH, XtL, XtH, XtL, Cv, Cv, Cv, Cv, Cv, Sm, Sm);
            TEpi e1 = te(); e1.alpha = -0.5f; e1.diag = 1.5f;
            e1.outH = MH; e1.outL = ML; e1.zOut = Sm;
            mma_gemm<64,64><<<gp,256,SM64,sP>>>(g1, e1);
            // X' = X @ G^T; epilogue also emits Xt'
            GA g2 = mkga(XaH, XaL, MH, ML, Cv, Cv, Cv, Cv, Cv, Sm, Sm);
            TEpi e2 = te(); e2.outH = XbH; e2.outL = XbL; e2.zOut = Sm;
            e2.outTH = XtH; e2.outTL = XtL;
            mma_gemm<64,64><<<gp,256,SM64,sP>>>(g2, e2);
            bf16* t;
            t = XaH; XaH = XbH; XbH = t;
            t = XaL; XaL = XbL; XbL = t;
        }
        packP<<<(Cv*2*Cv)/256,256,0,sP>>>(XaH, XaL, PcH, PcL);
        cudaEventRecord(evJ, sP);
    }

    // ---- main stream: weight splits + SSM prep (concurrent with polar) ----
    wsplit5<<<(11*Cv*Cv)/256,256>>>(Wq, Wv, Wo, Wfc, Wpr,
        WqH, WqL, WvH, WvL, WoH, WoL, WfcH, WfcL, WprH, WprL);
    ln_kernel<<<Rv,128>>>(x, ln1, hH, hL);
    {
        GA gq = mkga(hH, hL, WqH, WqL, Rv, Cv, Cv, Cv, Cv);
        TEpi eq = te(); eq.outH = qH + GUARDE; eq.outL = qL + GUARDE;
        mma_gemm<128,128><<<dim3(Cv/128, Rv/128), 256, SM128>>>(gq, eq);
        GA gv = mkga(hH, hL, WvH, WvL, Rv, Cv, Cv, Cv, Cv);
        TEpi ev = te(); ev.outH = vH; ev.outL = vL;
        mma_gemm<128,128><<<dim3(Cv/128, Rv/128), 256, SM128>>>(gv, ev);
    }

    // ---- join: scan needs Pc from the polar stream ----
    cudaStreamWaitEvent(0, evJ, 0);

    for (int d = 1; d < Tv; d <<= 1) {
        const int mskip = d & ~127;          // whole 128-row tiles with t<d skipped
        // z = qshift @ P1^T + q @ P2^T : single GEMM, K=1024
        // chunks k<512 read q[t-d] (guard zeros / stale rows, discarded), k>=512 read q[t]
        GA gs = mkga(qH + GUARDE, qL + GUARDE, PcH, PcL, Rv, Cv, 2*Cv, Cv, 2*Cv);
        gs.Ah = qH + GUARDE - (long)d*Cv;
        gs.Al = qL + GUARDE - (long)d*Cv;
        gs.K1 = Cv;
        gs.mskip = mskip;
        gs.zA = (long)Tv*Cv;                  // batch stride (rows)
        TEpi es = te(); es.outF = z; es.zOut = (long)Tv*Cv;
        mma_gemm<128,128><<<dim3(Cv/128, (Tv-mskip)/128, Bv), 256, SM128>>>(gs, es);
        pscan_combine<<<dim3(Tv-mskip, Bv),128>>>(z, qH + GUARDE, qL + GUARDE, d, mskip);
    }

    // x1 = x + (q*v) @ Wo^T   (into d_out)
    mul_split<<<(Rv*Cv/4)/256,256>>>(qH + GUARDE, qL + GUARDE, vH, vL, hH, hL);
    {
        GA go = mkga(hH, hL, WoH, WoL, Rv, Cv, Cv, Cv, Cv);
        TEpi er = te(); er.add = x; er.outF = out;
        mma_gemm<128,128><<<dim3(Cv/128, Rv/128), 256, SM128>>>(go, er);
    }

    // ---- MLP branch ----
    ln_kernel<<<Rv,128>>>(out, ln2, hH, hL);
    {
        GA gf = mkga(hH, hL, WfcH, WfcL, Rv, Fv, Cv, Cv, Cv);
        TEpi eg = te(); eg.gelu = 1; eg.outH = fcH; eg.outL = fcL;
        mma_gemm<128,128><<<dim3(Fv/128, Rv/128), 256, SM128>>>(gf, eg);
        GA gr = mkga(fcH, fcL, WprH, WprL, Rv, Cv, Fv, Fv, Fv);
        TEpi er2 = te(); er2.add = out; er2.outF = out;
        mma_gemm<128,128><<<dim3(Cv/128, Rv/128), 256, SM128>>>(gr, er2);
    }
}

// round 10
// speedup vs baseline: 3.2358x; 1.0089x over previous
#include <cuda_runtime.h>
#include <cuda_bf16.h>
#include <math.h>
#include <stdint.h>

#define Bv 4
#define Tv 4096
#define Cv 512
#define Rv (Bv*Tv)            // 16384 rows
#define Fv (4*Cv)             // 2048
#define GUARDE (2048*Cv)      // guard rows (zero-init) for shifted scan operand
#define Sm ((long)Cv*Cv)

typedef __nv_bfloat16 bf16;

// ---------------- static device scratch (zero-initialized) ----------------
__device__ bf16 g_qH[GUARDE + Rv*Cv];
__device__ bf16 g_qL[GUARDE + Rv*Cv];
__device__ bf16 g_vH[Rv*Cv], g_vL[Rv*Cv];
__device__ float g_z[Rv*Cv];
__device__ bf16 g_hH[Rv*Cv], g_hL[Rv*Cv];
__device__ bf16 g_fcH[Rv*Fv], g_fcL[Rv*Fv];
// weight splits
__device__ bf16 g_WqH[Cv*Cv], g_WqL[Cv*Cv];
__device__ bf16 g_WvH[Cv*Cv], g_WvL[Cv*Cv];
__device__ bf16 g_WoH[Cv*Cv], g_WoL[Cv*Cv];
__device__ bf16 g_WfcH[Fv*Cv], g_WfcL[Fv*Cv];
__device__ bf16 g_WprH[Cv*Fv], g_WprL[Cv*Fv];
// polar scratch (x2 matrices, batched)
__device__ bf16 g_XaH[2*Cv*Cv], g_XaL[2*Cv*Cv];
__device__ bf16 g_XbH[2*Cv*Cv], g_XbL[2*Cv*Cv];
__device__ bf16 g_XtH[2*Cv*Cv], g_XtL[2*Cv*Cv];
__device__ bf16 g_YH [2*Cv*Cv], g_YL [2*Cv*Cv];
__device__ bf16 g_MH [2*Cv*Cv], g_ML [2*Cv*Cv];
__device__ float g_YF[2*Cv*Cv];
__device__ bf16 g_PcH[Cv*2*Cv], g_PcL[Cv*2*Cv];   // [P1||P2] along K (512 x 1024)
__device__ float g_part[2*Cv];
__device__ float g_rn[2];

// ================= helpers =================
__device__ __forceinline__ uint32_t smem_to_u32(const void* p) {
    uint32_t a;
    asm("{ .reg .u64 t; cvta.to.shared.u64 t, %1; cvt.u32.u64 %0, t; }" : "=r"(a) : "l"(p));
    return a;
}
__device__ __forceinline__ void split2(float x, bf16& h, bf16& l) {
    h = __float2bfloat16(x);
    l = __float2bfloat16(x - __bfloat162float(h));
}
__device__ __forceinline__ uint32_t pk2(bf16 a, bf16 b) {
    __nv_bfloat162 t; t.x = a; t.y = b;
    return *(uint32_t*)&t;
}
__device__ __forceinline__ void up2(uint32_t u, float& a, float& b) {
    __nv_bfloat162 t = *(__nv_bfloat162*)&u;
    a = __bfloat162float(t.x); b = __bfloat162float(t.y);
}
__device__ __forceinline__ void ldsm4(uint32_t (&r)[4], uint32_t addr) {
    asm volatile("ldmatrix.sync.aligned.m8n8.x4.shared.b16 {%0,%1,%2,%3}, [%4];"
        : "=r"(r[0]), "=r"(r[1]), "=r"(r[2]), "=r"(r[3]) : "r"(addr));
}
__device__ __forceinline__ void mma16816(float (&d)[4], const uint32_t (&a)[4],
                                         uint32_t b0, uint32_t b1) {
    asm volatile("mma.sync.aligned.m16n8k16.row.col.f32.bf16.bf16.f32 "
        "{%0,%1,%2,%3}, {%4,%5,%6,%7}, {%8,%9}, {%0,%1,%2,%3};"
        : "+f"(d[0]), "+f"(d[1]), "+f"(d[2]), "+f"(d[3])
        : "r"(a[0]), "r"(a[1]), "r"(a[2]), "r"(a[3]), "r"(b0), "r"(b1));
}
__device__ __forceinline__ void cp_async16(uint32_t so, const void* gp) {
    asm volatile("cp.async.cg.shared.global [%0], [%1], 16;" :: "r"(so), "l"(gp) : "memory");
}
#define CP_COMMIT() asm volatile("cp.async.commit_group;" ::: "memory")
#define CP_WAIT(n)  asm volatile("cp.async.wait_group %0;" :: "n"(n) : "memory")

// ================= mma.sync split-bf16 GEMM: C = alpha*A@B^T (+beta*add +diag*I) =====
// A: [M,K] bf16 hi/lo (K ranges split across Ah(k<K1)/Ah2(k>=K1), pitch lda).
// B: [N,K] bf16 hi/lo, pitch ldb. 3 passes hh+lh+hl interleaved with ldsm.
// CTA tile BMxBN, 8 warps (2 row x 4 col). K-chunk 32, 3-stage cp.async pipeline,
// ONE __syncthreads per iteration (WAIT -> sync -> issue c+2 -> compute c).
// grid.z batches: A/B/out/add advance by zA/zB/zOut/zAdd; rows offset by mskip.
// Optional transposed output (outTH/outTL) staged through smem (for polar Xt).
struct GA {
    const bf16 *Ah, *Al, *Ah2, *Al2, *Bh, *Bl;
    int M, N, K, K1, lda, ldb, mskip;
    long zA, zB;
};
struct TEpi {
    float alpha, beta, diag;
    const float* add; long zAdd;
    int gelu;
    float* outF; bf16 *outH, *outL; long zOut;
    bf16 *outTH, *outTL;     // transposed bf16 split output (square, pitch N)
};

template<int BM, int BN, int OCC>
__global__ __launch_bounds__(256, OCC)
void mma_gemm(GA g, TEpi e)
{
    constexpr int MF = BM/32, NF = BN/32, NB = NF/2;
    static_assert(MF >= 1 && NB >= 1, "tile too small");
    constexpr int ASZA = BM*64;        // A operand tile (BM rows x 32 k x 2B)
    constexpr int ASZB = BN*64;        // B operand tile
    constexpr int BUF = 2*ASZA + 2*ASZB;
    extern __shared__ char smem[];
    const uint32_t sb = smem_to_u32(smem);
    const int tid  = threadIdx.x;
    const int lane = tid & 31;
    const int wm   = (tid >> 5) & 1;
    const int wn   = (tid >> 5) >> 1;
    const int m0 = g.mskip + blockIdx.y * BM;
    const int n0 = blockIdx.x * BN;
    const int bz = blockIdx.z;
    const int NC = g.K / 32;

    const bf16 *Ah = g.Ah + bz*g.zA,  *Al = g.Al + bz*g.zA;
    const bf16 *Ah2 = g.Ah2 + bz*g.zA, *Al2 = g.Al2 + bz*g.zA;
    const bf16 *Bh = g.Bh + bz*g.zB,  *Bl = g.Bl + bz*g.zB;

    // precomputed per-(ks,frag) smem offsets within a stage buffer
    int aOff[2][MF], bOff[2][NB];
    {
        const int aKb = (lane >> 4) * 16;
#pragma unroll
        for (int mf = 0; mf < MF; mf++) {
            int r = wm * (BM/2) + mf * 16 + (lane & 15);
            int base = (r >> 1) * 128, po = (r & 1) * 64, xm = ((r >> 1) & 7) << 4;
#pragma unroll
            for (int ks = 0; ks < 2; ks++)
                aOff[ks][mf] = base + ((po + ks * 32 + aKb) ^ xm);
        }
        const int bKb = ((lane >> 3) & 1) * 16;
#pragma unroll
        for (int nb = 0; nb < NB; nb++) {
            int r = wn * (BN/4) + nb * 16 + ((lane >> 4) << 3) + (lane & 7);
            int base = (r >> 1) * 128, po = (r & 1) * 64, xm = ((r >> 1) & 7) << 4;
#pragma unroll
            for (int ks = 0; ks < 2; ks++)
                bOff[ks][nb] = base + ((po + ks * 32 + bKb) ^ xm);
        }
    }

    float acc[MF][NF][4];
#pragma unroll
    for (int i = 0; i < MF; i++)
#pragma unroll
        for (int j = 0; j < NF; j++)
#pragma unroll
            for (int t = 0; t < 4; t++) acc[i][j][t] = 0.f;

    auto loadChunk = [&](int c) {
        const long cofs = (long)c * 32;
        const int st = c % 3;
        const bf16* AHc = Ah; const bf16* ALc = Al;
        long acol = cofs;
        if (cofs >= g.K1) { AHc = Ah2; ALc = Al2; acol = cofs - g.K1; }
        constexpr int TVA = BM * 4;     // 16B vectors per A tile
        constexpr int TVB = BN * 4;
        constexpr int NVEC = 2*TVA + 2*TVB;
#pragma unroll
        for (int t = 0; t < NVEC/256; t++) {
            int u = tid + t * 256;
            const bf16* base;
            int row, seg, sofs;
            if (u < TVA)            { base = AHc; row = u >> 2;          seg = u & 3;        sofs = 0;           }
            else if (u < 2*TVA)     { base = ALc; row = (u-TVA) >> 2;    seg = (u-TVA) & 3;  sofs = ASZA;        }
            else if (u < 2*TVA+TVB) { base = Bh;  row = (u-2*TVA) >> 2;  seg = (u-2*TVA) & 3; sofs = 2*ASZA;     }
            else                    { base = Bl;  row = (u-2*TVA-TVB) >> 2; seg = (u-2*TVA-TVB) & 3; sofs = 2*ASZA+ASZB; }
            const bf16* gp;
            if (sofs < 2*ASZA) gp = base + (long)(m0 + row) * g.lda + acol;
            else               gp = base + (long)(n0 + row) * g.ldb + cofs;
            gp += seg * 8;
            int j = row >> 1, p = row & 1;
            uint32_t so = sb + st * BUF + sofs + j * 128
                        + ((p * 64 + seg * 16) ^ ((j & 7) << 4));
            cp_async16(so, gp);
        }
        CP_COMMIT();
    };

    loadChunk(0);
    if (NC > 1) loadChunk(1);

    for (int c = 0; c < NC; c++) {
        if (c + 1 < NC) CP_WAIT(1);
        else            CP_WAIT(0);
        __syncthreads();
        if (c + 2 < NC) loadChunk(c + 2);

        const uint32_t bufB = sb + (c % 3) * BUF;
#pragma unroll
        for (int ks = 0; ks < 2; ks++) {
            uint32_t afH[MF][4], bfH[NB][4];
#pragma unroll
            for (int mf = 0; mf < MF; mf++)
                ldsm4(afH[mf], bufB + aOff[ks][mf]);
#pragma unroll
            for (int nb = 0; nb < NB; nb++)
                ldsm4(bfH[nb], bufB + 2*ASZA + bOff[ks][nb]);
            // pass hh
#pragma unroll
            for (int mf = 0; mf < MF; mf++)
#pragma unroll
                for (int nf = 0; nf < NF; nf++)
                    mma16816(acc[mf][nf], afH[mf], bfH[nf>>1][(nf&1)*2], bfH[nf>>1][(nf&1)*2+1]);
            // pass lh (afL loaded now; bfH still live)
            {
                uint32_t afL[MF][4];
#pragma unroll
                for (int mf = 0; mf < MF; mf++)
                    ldsm4(afL[mf], bufB + ASZA + aOff[ks][mf]);
#pragma unroll
                for (int mf = 0; mf < MF; mf++)
#pragma unroll
                    for (int nf = 0; nf < NF; nf++)
                        mma16816(acc[mf][nf], afL[mf], bfH[nf>>1][(nf&1)*2], bfH[nf>>1][(nf&1)*2+1]);
            }
            // pass hl (bfL loaded now; afH still live, afL/bfH dead)
            {
                uint32_t bfL[NB][4];
#pragma unroll
                for (int nb = 0; nb < NB; nb++)
                    ldsm4(bfL[nb], bufB + 2*ASZA + ASZB + bOff[ks][nb]);
#pragma unroll
                for (int mf = 0; mf < MF; mf++)
#pragma unroll
                    for (int nf = 0; nf < NF; nf++)
                        mma16816(acc[mf][nf], afH[mf], bfL[nf>>1][(nf&1)*2], bfL[nf>>1][(nf&1)*2+1]);
            }
        }
    }
    __syncthreads();    // all warps done with smem before epilogue staging reuses it

    // ---- epilogue ----
    float* outF = e.outF ? e.outF + bz*e.zOut : (float*)0;
    bf16*  outH = e.outH ? e.outH + bz*e.zOut : (bf16*)0;
    bf16*  outL = e.outL ? e.outL + bz*e.zOut : (bf16*)0;
    const float* add = e.add ? e.add + bz*e.zAdd : (const float*)0;
    bf16* sH = (bf16*)smem;                    // transposed staging [BM][BN+1]
    bf16* sL = sH + BM*(BN+1);
    const int rl = lane >> 2;
    const int cl = (lane & 3) * 2;
#pragma unroll
    for (int mf = 0; mf < MF; mf++) {
#pragma unroll
        for (int nf = 0; nf < NF; nf++) {
            int lc = wn * (BN/4) + nf * 8 + cl;
            int c0 = n0 + lc;
#pragma unroll
            for (int half = 0; half < 2; half++) {
                int lr = wm * (BM/2) + mf * 16 + rl + half * 8;
                int row = m0 + lr;
                long ofs = (long)row * g.N + c0;
                float f0 = e.alpha * acc[mf][nf][half*2];
                float f1 = e.alpha * acc[mf][nf][half*2 + 1];
                if (add) {
                    float2 ra = *(const float2*)(add + ofs);
                    f0 += e.beta * ra.x; f1 += e.beta * ra.y;
                }
                if (e.diag != 0.f) {
                    if (row == c0)     f0 += e.diag;
                    if (row == c0 + 1) f1 += e.diag;
                }
                if (e.gelu) {
                    f0 = 0.5f * f0 * (1.f + erff(f0 * 0.70710678118654752f));
                    f1 = 0.5f * f1 * (1.f + erff(f1 * 0.70710678118654752f));
                }
                if (outF)
                    *(float2*)(outF + ofs) = make_float2(f0, f1);
                if (outH || e.outTH) {
                    bf16 h0, h1, l0, l1;
                    split2(f0, h0, l0);
                    split2(f1, h1, l1);
                    if (outH) {
                        *(uint32_t*)(outH + ofs) = pk2(h0, h1);
                        *(uint32_t*)(outL + ofs) = pk2(l0, l1);
                    }
                    if (e.outTH) {
                        sH[lr*(BN+1) + lc] = h0; sH[lr*(BN+1) + lc + 1] = h1;
                        sL[lr*(BN+1) + lc] = l0; sL[lr*(BN+1) + lc + 1] = l1;
                    }
                }
            }
        }
    }
    if (e.outTH) {
        __syncthreads();
        bf16* outTH = e.outTH + bz*e.zOut;
        bf16* outTL = e.outTL + bz*e.zOut;
#pragma unroll
        for (int it = 0; it < (BM*BN)/256; it++) {
            int idx = tid + it * 256;
            int j = idx / BM;        // col of X = row of Xt
            int i = idx % BM;        // row of X
            long o = (long)(n0 + j) * g.N + m0 + i;
            outTH[o] = sH[i*(BN+1) + j];
            outTL[o] = sL[i*(BN+1) + j];
        }
    }
}

// ---------------- elementwise / reduction kernels ----------------
__global__ void ln_kernel(const float* __restrict__ x, const float* __restrict__ w,
                          bf16* __restrict__ oh, bf16* __restrict__ ol)
{
    const int r = blockIdx.x, tid = threadIdx.x;
    float4 f = ((const float4*)(x + (long)r*Cv))[tid];
    float s = f.x+f.y+f.z+f.w;
    float q = f.x*f.x+f.y*f.y+f.z*f.z+f.w*f.w;
    __shared__ float shs[4], shq[4];
#pragma unroll
    for (int off=16; off>0; off>>=1) {
        s += __shfl_down_sync(0xffffffffu, s, off);
        q += __shfl_down_sync(0xffffffffu, q, off);
    }
    if ((tid&31)==0) { shs[tid>>5]=s; shq[tid>>5]=q; }
    __syncthreads();
    float S = shs[0]+shs[1]+shs[2]+shs[3];
    float Q = shq[0]+shq[1]+shq[2]+shq[3];
    float mean = S*(1.f/Cv);
    float var  = Q*(1.f/Cv) - mean*mean;
    float inv  = rsqrtf(var + 1e-5f);
    float4 wf = ((const float4*)w)[tid];
    float o0=(f.x-mean)*inv*wf.x, o1=(f.y-mean)*inv*wf.y;
    float o2=(f.z-mean)*inv*wf.z, o3=(f.w-mean)*inv*wf.w;
    bf16 h0,h1,h2,h3,l0,l1,l2,l3;
    split2(o0,h0,l0); split2(o1,h1,l1); split2(o2,h2,l2); split2(o3,h3,l3);
    long ofs = (long)r*Cv + tid*4;
    uint2 uh; uh.x=pk2(h0,h1); uh.y=pk2(h2,h3);
    uint2 ul; ul.x=pk2(l0,l1); ul.y=pk2(l2,l3);
    *(uint2*)(oh+ofs)=uh; *(uint2*)(ol+ofs)=ul;
}

// in-place scan combine: q[t] <- rms(z[t]) for t >= d. grid (Tv - mskip, Bv).
__global__ void pscan_combine(const float* __restrict__ z,
                              bf16* __restrict__ qH, bf16* __restrict__ qL,
                              int d, int mskip)
{
    const int t = mskip + blockIdx.x;
    if (t < d) return;
    const int r = blockIdx.y * Tv + t;
    const int tid = threadIdx.x;
    long ofs = (long)r*Cv + tid*4;
    float4 f = *(const float4*)(z+ofs);
    float q = f.x*f.x+f.y*f.y+f.z*f.z+f.w*f.w;
    __shared__ float shq[4];
#pragma unroll
    for (int off=16; off>0; off>>=1) q += __shfl_down_sync(0xffffffffu, q, off);
    if ((tid&31)==0) shq[tid>>5]=q;
    __syncthreads();
    float Q = shq[0]+shq[1]+shq[2]+shq[3];
    float sc = rsqrtf(Q*(1.f/Cv) + 1e-6f);
    float o0=f.x*sc, o1=f.y*sc, o2=f.z*sc, o3=f.w*sc;
    bf16 h0,h1,h2,h3,l0,l1,l2,l3;
    split2(o0,h0,l0); split2(o1,h1,l1); split2(o2,h2,l2); split2(o3,h3,l3);
    uint2 uh; uh.x=pk2(h0,h1); uh.y=pk2(h2,h3);
    uint2 ul; ul.x=pk2(l0,l1); ul.y=pk2(l2,l3);
    *(uint2*)(qH+ofs)=uh; *(uint2*)(qL+ofs)=ul;
}

// h = split(q * v) with q,v reconstructed from bf16 pairs
__global__ void mul_split(const bf16* __restrict__ qH, const bf16* __restrict__ qL,
                          const bf16* __restrict__ vH, const bf16* __restrict__ vL,
                          bf16* __restrict__ H, bf16* __restrict__ L)
{
    long i = ((long)blockIdx.x*256 + threadIdx.x)*4;
    uint2 a = *(const uint2*)(qH+i), b = *(const uint2*)(qL+i);
    uint2 c = *(const uint2*)(vH+i), d = *(const uint2*)(vL+i);
    float q0,q1,q2,q3,ql0,ql1,ql2,ql3,v0,v1,v2,v3,vl0,vl1,vl2,vl3;
    up2(a.x,q0,q1); up2(a.y,q2,q3); up2(b.x,ql0,ql1); up2(b.y,ql2,ql3);
    up2(c.x,v0,v1); up2(c.y,v2,v3); up2(d.x,vl0,vl1); up2(d.y,vl2,vl3);
    float o0=(q0+ql0)*(v0+vl0), o1=(q1+ql1)*(v1+vl1);
    float o2=(q2+ql2)*(v2+vl2), o3=(q3+ql3)*(v3+vl3);
    bf16 h0,h1,h2,h3,l0,l1,l2,l3;
    split2(o0,h0,l0); split2(o1,h1,l1); split2(o2,h2,l2); split2(o3,h3,l3);
    uint2 uh; uh.x=pk2(h0,h1); uh.y=pk2(h2,h3);
    uint2 ul; ul.x=pk2(l0,l1); ul.y=pk2(l2,l3);
    *(uint2*)(H+i)=uh; *(uint2*)(L+i)=ul;
}

// all five weight splits in one launch
__global__ void wsplit5(const float* __restrict__ Wq, const float* __restrict__ Wv,
                        const float* __restrict__ Wo, const float* __restrict__ Wfc,
                        const float* __restrict__ Wpr,
                        bf16* WqH, bf16* WqL, bf16* WvH, bf16* WvL,
                        bf16* WoH, bf16* WoL, bf16* WfcH, bf16* WfcL,
                        bf16* WprH, bf16* WprL)
{
    const int S = Cv*Cv;
    long i = (long)blockIdx.x*256 + threadIdx.x;   // over 11*S
    const float* W; bf16 *H, *L; long j;
    if      (i < S)       { W=Wq;  H=WqH;  L=WqL;  j=i; }
    else if (i < 2L*S)    { W=Wv;  H=WvH;  L=WvL;  j=i-S; }
    else if (i < 3L*S)    { W=Wo;  H=WoH;  L=WoL;  j=i-2L*S; }
    else if (i < 7L*S)    { W=Wfc; H=WfcH; L=WfcL; j=i-3L*S; }
    else                  { W=Wpr; H=WprH; L=WprL; j=i-7L*S; }
    float x = W[j];
    bf16 h, l; split2(x, h, l);
    H[j] = h; L[j] = l;
}

__global__ void frob1(const float* __restrict__ W1, const float* __restrict__ W2,
                      float* __restrict__ part)
{
    const int row = blockIdx.x, mat = blockIdx.y, tid = threadIdx.x;
    const float* W = mat ? W2 : W1;
    float4 f = ((const float4*)(W + (long)row*Cv))[tid];
    float q = f.x*f.x+f.y*f.y+f.z*f.z+f.w*f.w;
    __shared__ float shq[4];
#pragma unroll
    for (int off=16; off>0; off>>=1) q += __shfl_down_sync(0xffffffffu, q, off);
    if ((tid&31)==0) shq[tid>>5]=q;
    __syncthreads();
    if (tid==0) part[mat*Cv + row] = shq[0]+shq[1]+shq[2]+shq[3];
}

__global__ void frob2(const float* __restrict__ part, float* __restrict__ rn)
{
    const int mat = blockIdx.x, tid = threadIdx.x;
    __shared__ float sh[256];
    sh[tid] = part[mat*Cv + tid] + part[mat*Cv + tid + 256];
    __syncthreads();
    for (int off=128; off>0; off>>=1) {
        if (tid<off) sh[tid] += sh[tid+off];
        __syncthreads();
    }
    if (tid==0) rn[mat] = rsqrtf(sh[0]);
}

// X = W * rn, split to H/L, plus transposed copies. grid (16,16,2), block (32,8).
__global__ void split_tr_init(const float* __restrict__ W1, const float* __restrict__ W2,
                              const float* __restrict__ rn,
                              bf16* XH, bf16* XL, bf16* XtH, bf16* XtL)
{
    __shared__ float t[32][33];
    const int mat = blockIdx.z;
    const float* W = mat ? W2 : W1;
    const float s = rn[mat];
    const int r0 = blockIdx.y*32, c0 = blockIdx.x*32;
    const int tx = threadIdx.x, ty = threadIdx.y;
    const long mo = (long)mat*Sm;
#pragma unroll
    for (int i = 0; i < 4; i++) {
        int rr = ty + i*8;
        t[rr][tx] = W[(long)(r0+rr)*Cv + c0+tx] * s;
    }
    __syncthreads();
#pragma unroll
    for (int i = 0; i < 4; i++) {
        int rr = ty + i*8;
        bf16 h, l;
        split2(t[rr][tx], h, l);
        XH[mo + (long)(r0+rr)*Cv + c0+tx] = h;
        XL[mo + (long)(r0+rr)*Cv + c0+tx] = l;
        split2(t[tx][rr], h, l);
        XtH[mo + (long)(c0+rr)*Cv + r0+tx] = h;
        XtL[mo + (long)(c0+rr)*Cv + r0+tx] = l;
    }
}

// Pc[n, 0:512] = P1[n,:], Pc[n, 512:1024] = P2[n,:]
__global__ void packP(const bf16* __restrict__ XH, const bf16* __restrict__ XL,
                      bf16* __restrict__ PcH, bf16* __restrict__ PcL)
{
    int idx = blockIdx.x*256 + threadIdx.x;     // over 512*1024
    int n = idx >> 10, k = idx & 1023;
    long src = (k < 512) ? ((long)n*Cv + k) : (Sm + (long)n*Cv + (k-512));
    PcH[idx] = XH[src];
    PcL[idx] = XL[src];
}

// ---------------- host ----------------
static inline GA mkga(const bf16* Ah, const bf16* Al, const bf16* Bh, const bf16* Bl,
                      int M, int N, int K, int lda, int ldb, long zA = 0, long zB = 0)
{
    GA g; g.Ah=Ah; g.Al=Al; g.Ah2=Ah; g.Al2=Al; g.Bh=Bh; g.Bl=Bl;
    g.M=M; g.N=N; g.K=K; g.K1=K; g.lda=lda; g.ldb=ldb; g.mskip=0; g.zA=zA; g.zB=zB;
    return g;
}
static inline TEpi te()
{
    TEpi e; e.alpha=1.f; e.beta=1.f; e.diag=0.f; e.add=0; e.zAdd=0;
    e.gelu=0; e.outF=0; e.outH=0; e.outL=0; e.zOut=0; e.outTH=0; e.outTL=0;
    return e;
}

#define SM128 (3*4*128*64)                   // 98304: 3 stages x (2+2) x 128-row tiles
#define SMP   (3*(2*32*64 + 2*64*64))        // 36864: polar 32x64 tiles

extern "C" void kernel_launch(void* const* d_in, const int* in_sizes, int n_in,
                              void* d_out, int out_size)
{
    const float* x   = (const float*)d_in[0];
    const float* ln1 = (const float*)d_in[1];
    const float* Wq  = (const float*)d_in[2];
    const float* Wv  = (const float*)d_in[3];
    const float* Wo  = (const float*)d_in[4];
    // d_in[5] = identity : mathematically unused (rows computed from it are discarded)
    const float* Wp1 = (const float*)d_in[6];
    const float* Wp2 = (const float*)d_in[7];
    const float* ln2 = (const float*)d_in[8];
    const float* Wfc = (const float*)d_in[9];
    const float* Wpr = (const float*)d_in[10];
    float* out = (float*)d_out;

    cudaFuncSetAttribute(mma_gemm<128,128,2>, cudaFuncAttributeMaxDynamicSharedMemorySize, SM128);
    cudaFuncSetAttribute(mma_gemm<32,64,3>,   cudaFuncAttributeMaxDynamicSharedMemorySize, SMP);

    // streams: sP = polar chain, sM = main prep; both forked off the capture
    // origin stream and joined before the scan.
    static cudaStream_t sP = 0, sM = 0;
    static cudaEvent_t evF = 0, evJ = 0, evM = 0;
    if (!sP) {
        cudaStreamCreateWithFlags(&sP, cudaStreamNonBlocking);
        cudaStreamCreateWithFlags(&sM, cudaStreamNonBlocking);
        cudaEventCreateWithFlags(&evF, cudaEventDisableTiming);
        cudaEventCreateWithFlags(&evJ, cudaEventDisableTiming);
        cudaEventCreateWithFlags(&evM, cudaEventDisableTiming);
    }

    bf16 *qH,*qL,*vH,*vL,*hH,*hL,*fcH,*fcL;
    bf16 *WqH,*WqL,*WvH,*WvL,*WoH,*WoL,*WfcH,*WfcL,*WprH,*WprL;
    bf16 *XaH,*XaL,*XbH,*XbL,*XtH,*XtL,*YH,*YL,*MH,*ML,*PcH,*PcL;
    float *z,*YF,*part,*rn;
    cudaGetSymbolAddress((void**)&qH, g_qH);   cudaGetSymbolAddress((void**)&qL, g_qL);
    cudaGetSymbolAddress((void**)&vH, g_vH);   cudaGetSymbolAddress((void**)&vL, g_vL);
    cudaGetSymbolAddress((void**)&hH, g_hH);   cudaGetSymbolAddress((void**)&hL, g_hL);
    cudaGetSymbolAddress((void**)&fcH, g_fcH); cudaGetSymbolAddress((void**)&fcL, g_fcL);
    cudaGetSymbolAddress((void**)&WqH, g_WqH); cudaGetSymbolAddress((void**)&WqL, g_WqL);
    cudaGetSymbolAddress((void**)&WvH, g_WvH); cudaGetSymbolAddress((void**)&WvL, g_WvL);
    cudaGetSymbolAddress((void**)&WoH, g_WoH); cudaGetSymbolAddress((void**)&WoL, g_WoL);
    cudaGetSymbolAddress((void**)&WfcH,g_WfcH); cudaGetSymbolAddress((void**)&WfcL,g_WfcL);
    cudaGetSymbolAddress((void**)&WprH,g_WprH); cudaGetSymbolAddress((void**)&WprL,g_WprL);
    cudaGetSymbolAddress((void**)&XaH, g_XaH); cudaGetSymbolAddress((void**)&XaL, g_XaL);
    cudaGetSymbolAddress((void**)&XbH, g_XbH); cudaGetSymbolAddress((void**)&XbL, g_XbL);
    cudaGetSymbolAddress((void**)&XtH, g_XtH); cudaGetSymbolAddress((void**)&XtL, g_XtL);
    cudaGetSymbolAddress((void**)&YH,  g_YH);  cudaGetSymbolAddress((void**)&YL,  g_YL);
    cudaGetSymbolAddress((void**)&MH,  g_MH);  cudaGetSymbolAddress((void**)&ML,  g_ML);
    cudaGetSymbolAddress((void**)&PcH, g_PcH); cudaGetSymbolAddress((void**)&PcL, g_PcL);
    cudaGetSymbolAddress((void**)&z,   g_z);
    cudaGetSymbolAddress((void**)&YF,  g_YF);
    cudaGetSymbolAddress((void**)&part,g_part);
    cudaGetSymbolAddress((void**)&rn,  g_rn);

    // ---- fork ----
    cudaEventRecord(evF, 0);
    cudaStreamWaitEvent(sP, evF, 0);
    cudaStreamWaitEvent(sM, evF, 0);

    {   // polar factors via Muon-quintic + Newton-Schulz on tensor cores (stream sP)
        frob1<<<dim3(Cv,2),128,0,sP>>>(Wp1, Wp2, part);
        frob2<<<2,256,0,sP>>>(part, rn);
        split_tr_init<<<dim3(16,16,2),dim3(32,8),0,sP>>>(Wp1, Wp2, rn, XaH, XaL, XtH, XtL);

        const dim3 gp(Cv/64, Cv/32, 2);     // (8,16,2) = 256 CTAs, 32x64 tiles
        for (int it = 0; it < 9; ++it) {
            // Y = Xt @ Xt^T  (= X^T X, symmetric)
            GA g1 = mkga(XtH, XtL, XtH, XtL, Cv, Cv, Cv, Cv, Cv, Sm, Sm);
            TEpi e1 = te(); e1.outF = YF; e1.outH = YH; e1.outL = YL; e1.zOut = Sm;
            mma_gemm<32,64,3><<<gp,256,SMP,sP>>>(g1, e1);
            // M = 2.0315*Y@Y^T - 4.7750*Y + 3.4445*I  (symmetric)
            GA g2 = mkga(YH, YL, YH, YL, Cv, Cv, Cv, Cv, Cv, Sm, Sm);
            TEpi e2 = te(); e2.alpha = 2.0315f; e2.add = YF; e2.zAdd = Sm;
            e2.beta = -4.7750f; e2.diag = 3.4445f; e2.outH = MH; e2.outL = ML; e2.zOut = Sm;
            mma_gemm<32,64,3><<<gp,256,SMP,sP>>>(g2, e2);
            // X' = X @ M^T (= X M, M symmetric); epilogue also emits Xt'
            GA g3 = mkga(XaH, XaL, MH, ML, Cv, Cv, Cv, Cv, Cv, Sm, Sm);
            TEpi e3 = te(); e3.outH = XbH; e3.outL = XbL; e3.zOut = Sm;
            e3.outTH = XtH; e3.outTL = XtL;
            mma_gemm<32,64,3><<<gp,256,SMP,sP>>>(g3, e3);
            bf16* t;
            t = XaH; XaH = XbH; XbH = t;
            t = XaL; XaL = XbL; XbL = t;
        }
        for (int it = 0; it < 5; ++it) {
            // G = -0.5*Xt@Xt^T + 1.5I  (symmetric)
            GA g1 = mkga(XtH, XtL, XtH, XtL, Cv, Cv, Cv, Cv, Cv, Sm, Sm);
            TEpi e1 = te(); e1.alpha = -0.5f; e1.diag = 1.5f;
            e1.outH = MH; e1.outL = ML; e1.zOut = Sm;
            mma_gemm<32,64,3><<<gp,256,SMP,sP>>>(g1, e1);
            // X' = X @ G^T; epilogue also emits Xt'
            GA g2 = mkga(XaH, XaL, MH, ML, Cv, Cv, Cv, Cv, Cv, Sm, Sm);
            TEpi e2 = te(); e2.outH = XbH; e2.outL = XbL; e2.zOut = Sm;
            e2.outTH = XtH; e2.outTL = XtL;
            mma_gemm<32,64,3><<<gp,256,SMP,sP>>>(g2, e2);
            bf16* t;
            t = XaH; XaH = XbH; XbH = t;
            t = XaL; XaL = XbL; XbL = t;
        }
        packP<<<(Cv*2*Cv)/256,256,0,sP>>>(XaH, XaL, PcH, PcL);
        cudaEventRecord(evJ, sP);
    }

    {   // main prep: weight splits + ln + q/v GEMMs (stream sM, concurrent w/ polar)
        wsplit5<<<(11*Cv*Cv)/256,256,0,sM>>>(Wq, Wv, Wo, Wfc, Wpr,
            WqH, WqL, WvH, WvL, WoH, WoL, WfcH, WfcL, WprH, WprL);
        ln_kernel<<<Rv,128,0,sM>>>(x, ln1, hH, hL);
        GA gq = mkga(hH, hL, WqH, WqL, Rv, Cv, Cv, Cv, Cv);
        TEpi eq = te(); eq.outH = qH + GUARDE; eq.outL = qL + GUARDE;
        mma_gemm<128,128,2><<<dim3(Cv/128, Rv/128), 256, SM128, sM>>>(gq, eq);
        GA gv = mkga(hH, hL, WvH, WvL, Rv, Cv, Cv, Cv, Cv);
        TEpi ev = te(); ev.outH = vH; ev.outL = vL;
        mma_gemm<128,128,2><<<dim3(Cv/128, Rv/128), 256, SM128, sM>>>(gv, ev);
        cudaEventRecord(evM, sM);
    }

    // ---- join: scan needs Pc (sP) and q (sM) ----
    cudaStreamWaitEvent(0, evJ, 0);
    cudaStreamWaitEvent(0, evM, 0);

    for (int d = 1; d < Tv; d <<= 1) {
        const int mskip = d & ~127;          // whole 128-row tiles with t<d skipped
        // z = qshift @ P1^T + q @ P2^T : single GEMM, K=1024
        // chunks k<512 read q[t-d] (guard zeros / stale rows, discarded), k>=512 read q[t]
        GA gs = mkga(qH + GUARDE, qL + GUARDE, PcH, PcL, Rv, Cv, 2*Cv, Cv, 2*Cv);
        gs.Ah = qH + GUARDE - (long)d*Cv;
        gs.Al = qL + GUARDE - (long)d*Cv;
        gs.K1 = Cv;
        gs.mskip = mskip;
        gs.zA = (long)Tv*Cv;                  // batch stride (rows)
        TEpi es = te(); es.outF = z; es.zOut = (long)Tv*Cv;
        mma_gemm<128,128,2><<<dim3(Cv/128, (Tv-mskip)/128, Bv), 256, SM128>>>(gs, es);
        pscan_combine<<<dim3(Tv-mskip, Bv),128>>>(z, qH + GUARDE, qL + GUARDE, d, mskip);
    }

    // x1 = x + (q*v) @ Wo^T   (into d_out)
    mul_split<<<(Rv*Cv/4)/256,256>>>(qH + GUARDE, qL + GUARDE, vH, vL, hH, hL);
    {
        GA go = mkga(hH, hL, WoH, WoL, Rv, Cv, Cv, Cv, Cv);
        TEpi er = te(); er.add = x; er.outF = out;
        mma_gemm<128,128,2><<<dim3(Cv/128, Rv/128), 256, SM128>>>(go, er);
    }

    // ---- MLP branch ----
    ln_kernel<<<Rv,128>>>(out, ln2, hH, hL);
    {
        GA gf = mkga(hH, hL, WfcH, WfcL, Rv, Fv, Cv, Cv, Cv);
        TEpi eg = te(); eg.gelu = 1; eg.outH = fcH; eg.outL = fcL;
        mma_gemm<128,128,2><<<dim3(Fv/128, Rv/128), 256, SM128>>>(gf, eg);
        GA gr = mkga(fcH, fcL, WprH, WprL, Rv, Cv, Fv, Fv, Fv);
        TEpi er2 = te(); er2.add = out; er2.outF = out;
        mma_gemm<128,128,2><<<dim3(Cv/128, Rv/128), 256, SM128>>>(gr, er2);
    }
}